// round 1
// baseline (speedup 1.0000x reference)
#include <cuda_runtime.h>
#include <math.h>

#define TOK   4096          // B*N
#define BSZ   4
#define NSEQ  1024
#define CDIM  1024
#define HEADS 16
#define HDIM  64
#define FFD   4096
#define LAYERS 4
#define ATT_SCALE 0.125f    // 64^-0.5

// Scratch (device globals; no allocation allowed)
__device__ float g_xn  [(size_t)TOK * CDIM];
__device__ float g_qkv [(size_t)TOK * 3 * CDIM];
__device__ float g_attn[(size_t)TOK * CDIM];
__device__ float g_ff  [(size_t)TOK * FFD];

// ---------------------------------------------------------------------------
// out = x + pos (pos broadcast over batch)
// ---------------------------------------------------------------------------
__global__ void add_pos_kernel(const float* __restrict__ x,
                               const float* __restrict__ pos,
                               float* __restrict__ out) {
    int i = blockIdx.x * blockDim.x + threadIdx.x;      // float4 index
    const float4 a = ((const float4*)x)[i];
    const float4 p = ((const float4*)pos)[i & ((NSEQ * CDIM / 4) - 1)];
    float4 o;
    o.x = a.x + p.x; o.y = a.y + p.y; o.z = a.z + p.z; o.w = a.w + p.w;
    ((float4*)out)[i] = o;
}

// ---------------------------------------------------------------------------
// LayerNorm: one block (256 thr) per row of 1024
// ---------------------------------------------------------------------------
__global__ void ln_kernel(const float* __restrict__ in,
                          const float* __restrict__ g,
                          const float* __restrict__ b,
                          float* __restrict__ out) {
    const int row = blockIdx.x;
    const int tid = threadIdx.x;
    const float4 x = ((const float4*)(in + (size_t)row * CDIM))[tid];
    float s  = x.x + x.y + x.z + x.w;
    float sq = x.x * x.x + x.y * x.y + x.z * x.z + x.w * x.w;

    __shared__ float ssum[8], ssq[8];
    __shared__ float smean, srstd;
    const int lane = tid & 31, wid = tid >> 5;
    #pragma unroll
    for (int o = 16; o > 0; o >>= 1) {
        s  += __shfl_down_sync(0xffffffffu, s, o);
        sq += __shfl_down_sync(0xffffffffu, sq, o);
    }
    if (lane == 0) { ssum[wid] = s; ssq[wid] = sq; }
    __syncthreads();
    if (tid == 0) {
        float S = 0.f, Q = 0.f;
        #pragma unroll
        for (int w = 0; w < 8; w++) { S += ssum[w]; Q += ssq[w]; }
        const float mean = S * (1.0f / CDIM);
        const float var  = Q * (1.0f / CDIM) - mean * mean;
        smean = mean;
        srstd = rsqrtf(var + 1e-5f);
    }
    __syncthreads();
    const float mean = smean, rstd = srstd;
    const int c = tid * 4;
    float4 gg = ((const float4*)g)[tid];
    float4 bb = ((const float4*)b)[tid];
    float4 y;
    y.x = (x.x - mean) * rstd * gg.x + bb.x;
    y.y = (x.y - mean) * rstd * gg.y + bb.y;
    y.z = (x.z - mean) * rstd * gg.z + bb.z;
    y.w = (x.w - mean) * rstd * gg.w + bb.w;
    ((float4*)(out + (size_t)row * CDIM))[tid] = y;
    (void)c;
}

// ---------------------------------------------------------------------------
// SGEMM: C[M,Nc] = A[M,K] @ W[K,Nc] + bias  (ACT 0: none, 1: gelu, 2: +res)
// 128x128x16 tile, 256 threads, 8x8 microtile
// ---------------------------------------------------------------------------
template <int ACT>
__global__ void sgemm_kernel(const float* __restrict__ A,
                             const float* __restrict__ W,
                             const float* __restrict__ bias,
                             const float* __restrict__ res,
                             float* __restrict__ C,
                             int M, int Nc, int K) {
    __shared__ float As[16][128];   // [k][m]
    __shared__ float Bs[16][128];   // [k][n]

    const int tid = threadIdx.x;            // 256
    const int tx = tid & 15, ty = tid >> 4; // 16x16
    const int bm = blockIdx.y * 128;
    const int bn = blockIdx.x * 128;

    float acc[8][8];
    #pragma unroll
    for (int i = 0; i < 8; i++)
        #pragma unroll
        for (int j = 0; j < 8; j++) acc[i][j] = 0.f;

    for (int k0 = 0; k0 < K; k0 += 16) {
        #pragma unroll
        for (int i = 0; i < 2; i++) {
            int idx = tid + i * 256;                  // 0..511
            int row = idx >> 2;                       // 0..127
            int k4  = (idx & 3) * 4;                  // 0,4,8,12
            float4 a = *(const float4*)(A + (size_t)(bm + row) * K + k0 + k4);
            As[k4 + 0][row] = a.x; As[k4 + 1][row] = a.y;
            As[k4 + 2][row] = a.z; As[k4 + 3][row] = a.w;
            int kr = idx >> 5;                        // 0..15
            int n4 = (idx & 31) * 4;                  // 0..124
            float4 bv = *(const float4*)(W + (size_t)(k0 + kr) * Nc + bn + n4);
            *(float4*)&Bs[kr][n4] = bv;
        }
        __syncthreads();
        #pragma unroll
        for (int kk = 0; kk < 16; kk++) {
            float4 a0 = *(const float4*)&As[kk][ty * 8];
            float4 a1 = *(const float4*)&As[kk][ty * 8 + 4];
            float4 b0 = *(const float4*)&Bs[kk][tx * 8];
            float4 b1 = *(const float4*)&Bs[kk][tx * 8 + 4];
            float af[8] = {a0.x, a0.y, a0.z, a0.w, a1.x, a1.y, a1.z, a1.w};
            float bf[8] = {b0.x, b0.y, b0.z, b0.w, b1.x, b1.y, b1.z, b1.w};
            #pragma unroll
            for (int i = 0; i < 8; i++)
                #pragma unroll
                for (int j = 0; j < 8; j++)
                    acc[i][j] += af[i] * bf[j];
        }
        __syncthreads();
    }

    float bias_r[8];
    #pragma unroll
    for (int j = 0; j < 8; j++) bias_r[j] = bias[bn + tx * 8 + j];

    #pragma unroll
    for (int i = 0; i < 8; i++) {
        float* crow = C + (size_t)(bm + ty * 8 + i) * Nc + bn + tx * 8;
        const float* rrow = (ACT == 2)
            ? (res + (size_t)(bm + ty * 8 + i) * Nc + bn + tx * 8) : nullptr;
        #pragma unroll
        for (int j = 0; j < 8; j++) {
            float v = acc[i][j] + bias_r[j];
            if (ACT == 1) v = 0.5f * v * (1.0f + erff(v * 0.70710678118654752f));
            if (ACT == 2) v += rrow[j];
            crow[j] = v;
        }
    }
}

// ---------------------------------------------------------------------------
// Attention with hard threshold.  Since softmax rows sum to 1, at most one
// entry per row can exceed 0.5 and it must be the row max.  So:
//   out_row = (1/Z > 0.5) ? V[argmax]/Z : 0,   Z = sum exp(s - max)
// One block: (b,h) x 64 query rows; stream over all 1024 keys in 64-col tiles.
// qkv layout: [B,N,3,H,HD]; out layout: [B,N,C] with c = h*64+d.
// ---------------------------------------------------------------------------
__global__ void attn_kernel(const float* __restrict__ qkv,
                            float* __restrict__ out) {
    const int bh = blockIdx.y;
    const int b  = bh / HEADS;
    const int h  = bh % HEADS;
    const int r0 = blockIdx.x * 64;

    __shared__ float Qs[64][65];
    __shared__ float Ks[64][65];
    __shared__ float redm[64][16];
    __shared__ float redz[64][16];
    __shared__ int   redj[64][16];
    __shared__ float rscale[64];
    __shared__ int   rjmax[64];

    const int tid = threadIdx.x;            // 256
    const int tx = tid & 15, ty = tid >> 4;

    // load Q tile [64 rows x 64 dims]
    #pragma unroll
    for (int i = 0; i < 4; i++) {
        int idx = tid + i * 256;            // 0..1023
        int r = idx >> 4;
        int d4 = (idx & 15) * 4;
        float4 q = *(const float4*)(qkv + ((size_t)(b * NSEQ + r0 + r) * 3) * CDIM
                                    + h * HDIM + d4);
        Qs[r][d4] = q.x; Qs[r][d4 + 1] = q.y; Qs[r][d4 + 2] = q.z; Qs[r][d4 + 3] = q.w;
    }

    float vmax[4], Zp[4];
    int jmax[4];
    #pragma unroll
    for (int i = 0; i < 4; i++) { vmax[i] = -1e30f; Zp[i] = 0.f; jmax[i] = 0; }

    for (int c0 = 0; c0 < NSEQ; c0 += 64) {
        __syncthreads();
        #pragma unroll
        for (int i = 0; i < 4; i++) {
            int idx = tid + i * 256;
            int r = idx >> 4;
            int d4 = (idx & 15) * 4;
            float4 k = *(const float4*)(qkv + ((size_t)(b * NSEQ + c0 + r) * 3 + 1) * CDIM
                                        + h * HDIM + d4);
            Ks[r][d4] = k.x; Ks[r][d4 + 1] = k.y; Ks[r][d4 + 2] = k.z; Ks[r][d4 + 3] = k.w;
        }
        __syncthreads();

        float s[4][4];
        #pragma unroll
        for (int i = 0; i < 4; i++)
            #pragma unroll
            for (int j = 0; j < 4; j++) s[i][j] = 0.f;

        #pragma unroll
        for (int d = 0; d < 64; d++) {
            float qa[4], ka[4];
            #pragma unroll
            for (int i = 0; i < 4; i++) qa[i] = Qs[ty * 4 + i][d];
            #pragma unroll
            for (int j = 0; j < 4; j++) ka[j] = Ks[tx * 4 + j][d];
            #pragma unroll
            for (int i = 0; i < 4; i++)
                #pragma unroll
                for (int j = 0; j < 4; j++)
                    s[i][j] += qa[i] * ka[j];
        }

        #pragma unroll
        for (int i = 0; i < 4; i++) {
            float tmax = -1e30f; int tj = 0;
            #pragma unroll
            for (int j = 0; j < 4; j++) {
                float sv = s[i][j] * ATT_SCALE;
                s[i][j] = sv;
                if (sv > tmax) { tmax = sv; tj = c0 + tx * 4 + j; }
            }
            if (tmax > vmax[i]) {
                Zp[i] *= expf(vmax[i] - tmax);
                vmax[i] = tmax;
                jmax[i] = tj;
            }
            float e = 0.f;
            #pragma unroll
            for (int j = 0; j < 4; j++) e += expf(s[i][j] - vmax[i]);
            Zp[i] += e;
        }
    }

    #pragma unroll
    for (int i = 0; i < 4; i++) {
        redm[ty * 4 + i][tx] = vmax[i];
        redz[ty * 4 + i][tx] = Zp[i];
        redj[ty * 4 + i][tx] = jmax[i];
    }
    __syncthreads();

    if (tid < 64) {
        const int r = tid;
        float gm = -1e30f; int gj = 0;
        #pragma unroll
        for (int t = 0; t < 16; t++)
            if (redm[r][t] > gm) { gm = redm[r][t]; gj = redj[r][t]; }
        float Z = 0.f;
        #pragma unroll
        for (int t = 0; t < 16; t++) Z += redz[r][t] * expf(redm[r][t] - gm);
        const float amax = 1.0f / Z;
        rscale[r] = (amax > 0.5f) ? amax : 0.0f;
        rjmax[r]  = gj;
    }
    __syncthreads();

    // write: 64 rows x 64 dims; thread -> 16 elems
    const int r  = tid >> 2;
    const int d0 = (tid & 3) * 16;
    const float sc = rscale[r];
    const int jj = rjmax[r];
    const float* vrow = qkv + ((size_t)(b * NSEQ + jj) * 3 + 2) * CDIM + h * HDIM;
    float* orow = out + (size_t)(b * NSEQ + r0 + r) * CDIM + h * HDIM;
    #pragma unroll
    for (int d = d0; d < d0 + 16; d += 4) {
        float4 o;
        if (sc != 0.0f) {
            float4 v = *(const float4*)(vrow + d);
            o.x = v.x * sc; o.y = v.y * sc; o.z = v.z * sc; o.w = v.w * sc;
        } else {
            o.x = 0.f; o.y = 0.f; o.z = 0.f; o.w = 0.f;
        }
        *(float4*)(orow + d) = o;
    }
}

// ---------------------------------------------------------------------------
extern "C" void kernel_launch(void* const* d_in, const int* in_sizes, int n_in,
                              void* d_out, int out_size) {
    (void)in_sizes; (void)n_in; (void)out_size;
    const float* x      = (const float*)d_in[0];
    const float* pos    = (const float*)d_in[1];
    const float* qkv_w  = (const float*)d_in[2];
    const float* qkv_b  = (const float*)d_in[3];
    const float* proj_w = (const float*)d_in[4];
    const float* proj_b = (const float*)d_in[5];
    const float* ln1_g  = (const float*)d_in[6];
    const float* ln1_b  = (const float*)d_in[7];
    const float* ln2_g  = (const float*)d_in[8];
    const float* ln2_b  = (const float*)d_in[9];
    const float* fc1_w  = (const float*)d_in[10];
    const float* fc1_b  = (const float*)d_in[11];
    const float* fc2_w  = (const float*)d_in[12];
    const float* fc2_b  = (const float*)d_in[13];
    float* out = (float*)d_out;

    float *xn, *qkv, *attn, *ff;
    cudaGetSymbolAddress((void**)&xn,   g_xn);
    cudaGetSymbolAddress((void**)&qkv,  g_qkv);
    cudaGetSymbolAddress((void**)&attn, g_attn);
    cudaGetSymbolAddress((void**)&ff,   g_ff);

    add_pos_kernel<<<(size_t)TOK * CDIM / 4 / 256, 256>>>(x, pos, out);

    for (int l = 0; l < LAYERS; l++) {
        // --- attention block ---
        ln_kernel<<<TOK, 256>>>(out, ln1_g + (size_t)l * CDIM, ln1_b + (size_t)l * CDIM, xn);
        sgemm_kernel<0><<<dim3(3 * CDIM / 128, TOK / 128), 256>>>(
            xn, qkv_w + (size_t)l * CDIM * 3 * CDIM, qkv_b + (size_t)l * 3 * CDIM,
            nullptr, qkv, TOK, 3 * CDIM, CDIM);
        attn_kernel<<<dim3(NSEQ / 64, BSZ * HEADS), 256>>>(qkv, attn);
        sgemm_kernel<2><<<dim3(CDIM / 128, TOK / 128), 256>>>(
            attn, proj_w + (size_t)l * CDIM * CDIM, proj_b + (size_t)l * CDIM,
            out, out, TOK, CDIM, CDIM);
        // --- MLP block ---
        ln_kernel<<<TOK, 256>>>(out, ln2_g + (size_t)l * CDIM, ln2_b + (size_t)l * CDIM, xn);
        sgemm_kernel<1><<<dim3(FFD / 128, TOK / 128), 256>>>(
            xn, fc1_w + (size_t)l * CDIM * FFD, fc1_b + (size_t)l * FFD,
            nullptr, ff, TOK, FFD, CDIM);
        sgemm_kernel<2><<<dim3(CDIM / 128, TOK / 128), 256>>>(
            ff, fc2_w + (size_t)l * FFD * CDIM, fc2_b + (size_t)l * CDIM,
            out, out, TOK, CDIM, FFD);
    }
}

// round 3
// speedup vs baseline: 2.7680x; 2.7680x over previous
#include <cuda_runtime.h>
#include <math.h>
#include <stdint.h>

#define TOK   4096          // B*N
#define BSZ   4
#define NSEQ  1024
#define CDIM  1024
#define HEADS 16
#define HDIM  64
#define FFD   4096
#define LAYERS 4
#define ATT_SCALE 0.125f    // 64^-0.5

#define LDA 36              // smem stride (floats) for A tiles (128x32)
#define LDB 136             // smem stride (floats) for B tiles (32x128): 128 + 8 pad
#define SMEM_A_FLOATS (2 * 128 * LDA)
#define SMEM_B_FLOATS (2 * 32 * LDB)
#define SMEM_BYTES ((SMEM_A_FLOATS + SMEM_B_FLOATS) * 4)

// Scratch (device globals; no allocation allowed)
__device__ float g_xn  [(size_t)TOK * CDIM];
__device__ float g_qkv [(size_t)TOK * 3 * CDIM];
__device__ float g_attn[(size_t)TOK * CDIM];
__device__ float g_ff  [(size_t)TOK * FFD];

// ---------------------------------------------------------------------------
__device__ __forceinline__ float tf32r(float x) {
    float y;
    asm("cvt.rna.tf32.f32 %0, %1;" : "=f"(y) : "f"(x));
    return y;
}
__device__ __forceinline__ uint32_t tf32r_u(float x) {
    uint32_t y;
    asm("cvt.rna.tf32.f32 %0, %1;" : "=r"(y) : "f"(x));
    return y;
}
__device__ __forceinline__ void cp_async16(uint32_t s, const void* g) {
    asm volatile("cp.async.cg.shared.global [%0], [%1], 16;" :: "r"(s), "l"(g));
}
__device__ __forceinline__ void cp_commit() {
    asm volatile("cp.async.commit_group;");
}
__device__ __forceinline__ void cp_wait0() {
    asm volatile("cp.async.wait_group 0;");
}
__device__ __forceinline__ void ldsm_x4(uint32_t& r0, uint32_t& r1, uint32_t& r2,
                                        uint32_t& r3, uint32_t addr) {
    asm volatile("ldmatrix.sync.aligned.m8n8.x4.shared.b16 {%0,%1,%2,%3}, [%4];"
                 : "=r"(r0), "=r"(r1), "=r"(r2), "=r"(r3) : "r"(addr));
}
__device__ __forceinline__ void mma_tf32(float* c, const uint32_t* a, const uint32_t* b) {
    asm volatile(
        "mma.sync.aligned.m16n8k8.row.col.f32.tf32.tf32.f32 "
        "{%0,%1,%2,%3}, {%4,%5,%6,%7}, {%8,%9}, {%0,%1,%2,%3};"
        : "+f"(c[0]), "+f"(c[1]), "+f"(c[2]), "+f"(c[3])
        : "r"(a[0]), "r"(a[1]), "r"(a[2]), "r"(a[3]), "r"(b[0]), "r"(b[1]));
}

// ---------------------------------------------------------------------------
// out = x + pos (pos broadcast over batch)
// ---------------------------------------------------------------------------
__global__ void add_pos_kernel(const float* __restrict__ x,
                               const float* __restrict__ pos,
                               float* __restrict__ out) {
    int i = blockIdx.x * blockDim.x + threadIdx.x;      // float4 index
    const float4 a = ((const float4*)x)[i];
    const float4 p = ((const float4*)pos)[i & ((NSEQ * CDIM / 4) - 1)];
    float4 o;
    o.x = a.x + p.x; o.y = a.y + p.y; o.z = a.z + p.z; o.w = a.w + p.w;
    ((float4*)out)[i] = o;
}

// ---------------------------------------------------------------------------
// LayerNorm: one block (256 thr) per row of 1024. Output tf32-rounded
// (it feeds tensor-core GEMMs only).
// ---------------------------------------------------------------------------
__global__ void ln_kernel(const float* __restrict__ in,
                          const float* __restrict__ g,
                          const float* __restrict__ b,
                          float* __restrict__ out) {
    const int row = blockIdx.x;
    const int tid = threadIdx.x;
    const float4 x = ((const float4*)(in + (size_t)row * CDIM))[tid];
    float s  = x.x + x.y + x.z + x.w;
    float sq = x.x * x.x + x.y * x.y + x.z * x.z + x.w * x.w;

    __shared__ float ssum[8], ssq[8];
    __shared__ float smean, srstd;
    const int lane = tid & 31, wid = tid >> 5;
    #pragma unroll
    for (int o = 16; o > 0; o >>= 1) {
        s  += __shfl_down_sync(0xffffffffu, s, o);
        sq += __shfl_down_sync(0xffffffffu, sq, o);
    }
    if (lane == 0) { ssum[wid] = s; ssq[wid] = sq; }
    __syncthreads();
    if (tid == 0) {
        float S = 0.f, Q = 0.f;
        #pragma unroll
        for (int w = 0; w < 8; w++) { S += ssum[w]; Q += ssq[w]; }
        const float mean = S * (1.0f / CDIM);
        const float var  = Q * (1.0f / CDIM) - mean * mean;
        smean = mean;
        srstd = rsqrtf(var + 1e-5f);
    }
    __syncthreads();
    const float mean = smean, rstd = srstd;
    float4 gg = ((const float4*)g)[tid];
    float4 bb = ((const float4*)b)[tid];
    float4 y;
    y.x = tf32r((x.x - mean) * rstd * gg.x + bb.x);
    y.y = tf32r((x.y - mean) * rstd * gg.y + bb.y);
    y.z = tf32r((x.z - mean) * rstd * gg.z + bb.z);
    y.w = tf32r((x.w - mean) * rstd * gg.w + bb.w);
    ((float4*)(out + (size_t)row * CDIM))[tid] = y;
}

// ---------------------------------------------------------------------------
// TF32 tensor-core GEMM: C[M,N] = A[M,K] @ W[K,N] + bias
// ACT 0: none, 1: gelu (+tf32 round, feeds next GEMM), 2: +residual
// 128x128 CTA tile, BK=32, 256 threads (2x4 warps, 64x32 warp tile),
// cp.async double-buffered, dynamic smem (71,680 B).
// ---------------------------------------------------------------------------
template <int ACT>
__global__ __launch_bounds__(256)
void mma_gemm_kernel(const float* __restrict__ A,
                     const float* __restrict__ W,
                     const float* __restrict__ bias,
                     const float* __restrict__ res,
                     float* __restrict__ C,
                     int M, int N, int K) {
    extern __shared__ float smem[];
    float* Asm = smem;                              // [2][128*LDA]
    float* Bsm = smem + SMEM_A_FLOATS;              // [2][32*LDB]

    const int tid  = threadIdx.x;
    const int lane = tid & 31;
    const int warp = tid >> 5;
    const int wm = warp >> 2;            // 0..1
    const int wn = warp & 3;             // 0..3
    const int bm = blockIdx.y * 128;
    const int bn = blockIdx.x * 128;

    float acc[4][4][4];
    #pragma unroll
    for (int i = 0; i < 4; i++)
        #pragma unroll
        for (int j = 0; j < 4; j++)
            #pragma unroll
            for (int t = 0; t < 4; t++) acc[i][j][t] = 0.f;

    // per-thread load offsets
    const int ar  = tid >> 3;            // A row base 0..31 (x4 -> 128 rows)
    const int ac4 = (tid & 7) * 4;       // A col (0..28)
    const int br  = tid >> 5;            // B k-row base 0..7 (x4 -> 32 rows)
    const int bc4 = (tid & 31) * 4;      // B n col (0..124)

    auto load_tile = [&](int kt, int st) {
        const float* Ag = A + (size_t)bm * K + kt * 32;
        float* as = Asm + st * (128 * LDA);
        #pragma unroll
        for (int i = 0; i < 4; i++) {
            int r = ar + i * 32;
            uint32_t sa = (uint32_t)__cvta_generic_to_shared(&as[r * LDA + ac4]);
            cp_async16(sa, Ag + (size_t)r * K + ac4);
        }
        const float* Wg = W + (size_t)(kt * 32) * N + bn;
        float* bs = Bsm + st * (32 * LDB);
        #pragma unroll
        for (int i = 0; i < 4; i++) {
            int r = br + i * 8;
            uint32_t sa = (uint32_t)__cvta_generic_to_shared(&bs[r * LDB + bc4]);
            cp_async16(sa, Wg + (size_t)r * N + bc4);
        }
    };

    const int KT = K / 32;
    load_tile(0, 0);
    cp_commit();

    // A-fragment ldmatrix address components (per thread)
    const int a_row = wm * 64 + (lane & 15);
    const int a_col = (lane >> 4) * 4;
    // B scalar-load components
    const int b_k = lane & 3;
    const int b_n = wn * 32 + (lane >> 2);

    for (int kt = 0; kt < KT; kt++) {
        const int st = kt & 1;
        cp_wait0();
        __syncthreads();
        if (kt + 1 < KT) { load_tile(kt + 1, st ^ 1); cp_commit(); }

        const float* as = Asm + st * (128 * LDA);
        const float* bs = Bsm + st * (32 * LDB);
        #pragma unroll
        for (int ks = 0; ks < 4; ks++) {
            uint32_t a[4][4];
            #pragma unroll
            for (int mt = 0; mt < 4; mt++) {
                uint32_t addr = (uint32_t)__cvta_generic_to_shared(
                    &as[(a_row + mt * 16) * LDA + ks * 8 + a_col]);
                ldsm_x4(a[mt][0], a[mt][1], a[mt][2], a[mt][3], addr);
            }
            uint32_t b[4][2];
            #pragma unroll
            for (int nt = 0; nt < 4; nt++) {
                float b0 = bs[(ks * 8 + b_k) * LDB + b_n + nt * 8];
                float b1 = bs[(ks * 8 + b_k + 4) * LDB + b_n + nt * 8];
                b[nt][0] = tf32r_u(b0);
                b[nt][1] = tf32r_u(b1);
            }
            #pragma unroll
            for (int mt = 0; mt < 4; mt++)
                #pragma unroll
                for (int nt = 0; nt < 4; nt++)
                    mma_tf32(acc[mt][nt], a[mt], b[nt]);
        }
        __syncthreads();
    }

    // Epilogue: c0,c1 at (row, col..col+1), c2,c3 at (row+8, ...)
    const int e_row = bm + wm * 64 + (lane >> 2);
    const int e_col = bn + wn * 32 + (lane & 3) * 2;
    #pragma unroll
    for (int mt = 0; mt < 4; mt++) {
        #pragma unroll
        for (int nt = 0; nt < 4; nt++) {
            const int col = e_col + nt * 8;
            const float bz0 = bias[col], bz1 = bias[col + 1];
            #pragma unroll
            for (int half = 0; half < 2; half++) {
                const int row = e_row + mt * 16 + half * 8;
                float v0 = acc[mt][nt][half * 2 + 0] + bz0;
                float v1 = acc[mt][nt][half * 2 + 1] + bz1;
                if (ACT == 1) {
                    v0 = tf32r(0.5f * v0 * (1.0f + erff(v0 * 0.70710678118654752f)));
                    v1 = tf32r(0.5f * v1 * (1.0f + erff(v1 * 0.70710678118654752f)));
                }
                if (ACT == 2) {
                    const float2 r2 = *(const float2*)(res + (size_t)row * N + col);
                    v0 += r2.x; v1 += r2.y;
                }
                float2 o; o.x = v0; o.y = v1;
                *(float2*)(C + (size_t)row * N + col) = o;
            }
        }
    }
}

// ---------------------------------------------------------------------------
// Attention with hard threshold.  Softmax rows sum to 1, so at most one entry
// can exceed 0.5 and it must be the row max:
//   out_row = (1/Z > 0.5) ? V[argmax]/Z : 0,   Z = sum exp(s - max)
// Output tf32-rounded (feeds the proj GEMM).
// ---------------------------------------------------------------------------
__global__ void attn_kernel(const float* __restrict__ qkv,
                            float* __restrict__ out) {
    const int bh = blockIdx.y;
    const int b  = bh / HEADS;
    const int h  = bh % HEADS;
    const int r0 = blockIdx.x * 64;

    __shared__ float Qs[64][65];
    __shared__ float Ks[64][65];
    __shared__ float redm[64][16];
    __shared__ float redz[64][16];
    __shared__ int   redj[64][16];
    __shared__ float rscale[64];
    __shared__ int   rjmax[64];

    const int tid = threadIdx.x;            // 256
    const int tx = tid & 15, ty = tid >> 4;

    #pragma unroll
    for (int i = 0; i < 4; i++) {
        int idx = tid + i * 256;
        int r = idx >> 4;
        int d4 = (idx & 15) * 4;
        float4 q = *(const float4*)(qkv + ((size_t)(b * NSEQ + r0 + r) * 3) * CDIM
                                    + h * HDIM + d4);
        Qs[r][d4] = q.x; Qs[r][d4 + 1] = q.y; Qs[r][d4 + 2] = q.z; Qs[r][d4 + 3] = q.w;
    }

    float vmax[4], Zp[4];
    int jmax[4];
    #pragma unroll
    for (int i = 0; i < 4; i++) { vmax[i] = -1e30f; Zp[i] = 0.f; jmax[i] = 0; }

    for (int c0 = 0; c0 < NSEQ; c0 += 64) {
        __syncthreads();
        #pragma unroll
        for (int i = 0; i < 4; i++) {
            int idx = tid + i * 256;
            int r = idx >> 4;
            int d4 = (idx & 15) * 4;
            float4 k = *(const float4*)(qkv + ((size_t)(b * NSEQ + c0 + r) * 3 + 1) * CDIM
                                        + h * HDIM + d4);
            Ks[r][d4] = k.x; Ks[r][d4 + 1] = k.y; Ks[r][d4 + 2] = k.z; Ks[r][d4 + 3] = k.w;
        }
        __syncthreads();

        float s[4][4];
        #pragma unroll
        for (int i = 0; i < 4; i++)
            #pragma unroll
            for (int j = 0; j < 4; j++) s[i][j] = 0.f;

        #pragma unroll
        for (int d = 0; d < 64; d++) {
            float qa[4], ka[4];
            #pragma unroll
            for (int i = 0; i < 4; i++) qa[i] = Qs[ty * 4 + i][d];
            #pragma unroll
            for (int j = 0; j < 4; j++) ka[j] = Ks[tx * 4 + j][d];
            #pragma unroll
            for (int i = 0; i < 4; i++)
                #pragma unroll
                for (int j = 0; j < 4; j++)
                    s[i][j] += qa[i] * ka[j];
        }

        #pragma unroll
        for (int i = 0; i < 4; i++) {
            float tmax = -1e30f; int tj = 0;
            #pragma unroll
            for (int j = 0; j < 4; j++) {
                float sv = s[i][j] * ATT_SCALE;
                s[i][j] = sv;
                if (sv > tmax) { tmax = sv; tj = c0 + tx * 4 + j; }
            }
            if (tmax > vmax[i]) {
                Zp[i] *= expf(vmax[i] - tmax);
                vmax[i] = tmax;
                jmax[i] = tj;
            }
            float e = 0.f;
            #pragma unroll
            for (int j = 0; j < 4; j++) e += expf(s[i][j] - vmax[i]);
            Zp[i] += e;
        }
    }

    #pragma unroll
    for (int i = 0; i < 4; i++) {
        redm[ty * 4 + i][tx] = vmax[i];
        redz[ty * 4 + i][tx] = Zp[i];
        redj[ty * 4 + i][tx] = jmax[i];
    }
    __syncthreads();

    if (tid < 64) {
        const int r = tid;
        float gm = -1e30f; int gj = 0;
        #pragma unroll
        for (int t = 0; t < 16; t++)
            if (redm[r][t] > gm) { gm = redm[r][t]; gj = redj[r][t]; }
        float Z = 0.f;
        #pragma unroll
        for (int t = 0; t < 16; t++) Z += redz[r][t] * expf(redm[r][t] - gm);
        const float amax = 1.0f / Z;
        rscale[r] = (amax > 0.5f) ? amax : 0.0f;
        rjmax[r]  = gj;
    }
    __syncthreads();

    const int r  = tid >> 2;
    const int d0 = (tid & 3) * 16;
    const float sc = rscale[r];
    const int jj = rjmax[r];
    const float* vrow = qkv + ((size_t)(b * NSEQ + jj) * 3 + 2) * CDIM + h * HDIM;
    float* orow = out + (size_t)(b * NSEQ + r0 + r) * CDIM + h * HDIM;
    #pragma unroll
    for (int d = d0; d < d0 + 16; d += 4) {
        float4 o;
        if (sc != 0.0f) {
            float4 v = *(const float4*)(vrow + d);
            o.x = tf32r(v.x * sc); o.y = tf32r(v.y * sc);
            o.z = tf32r(v.z * sc); o.w = tf32r(v.w * sc);
        } else {
            o.x = 0.f; o.y = 0.f; o.z = 0.f; o.w = 0.f;
        }
        *(float4*)(orow + d) = o;
    }
}

// ---------------------------------------------------------------------------
extern "C" void kernel_launch(void* const* d_in, const int* in_sizes, int n_in,
                              void* d_out, int out_size) {
    (void)in_sizes; (void)n_in; (void)out_size;
    const float* x      = (const float*)d_in[0];
    const float* pos    = (const float*)d_in[1];
    const float* qkv_w  = (const float*)d_in[2];
    const float* qkv_b  = (const float*)d_in[3];
    const float* proj_w = (const float*)d_in[4];
    const float* proj_b = (const float*)d_in[5];
    const float* ln1_g  = (const float*)d_in[6];
    const float* ln1_b  = (const float*)d_in[7];
    const float* ln2_g  = (const float*)d_in[8];
    const float* ln2_b  = (const float*)d_in[9];
    const float* fc1_w  = (const float*)d_in[10];
    const float* fc1_b  = (const float*)d_in[11];
    const float* fc2_w  = (const float*)d_in[12];
    const float* fc2_b  = (const float*)d_in[13];
    float* out = (float*)d_out;

    float *xn, *qkv, *attn, *ff;
    cudaGetSymbolAddress((void**)&xn,   g_xn);
    cudaGetSymbolAddress((void**)&qkv,  g_qkv);
    cudaGetSymbolAddress((void**)&attn, g_attn);
    cudaGetSymbolAddress((void**)&ff,   g_ff);

    // Opt-in to >48KB dynamic smem (immediate context op; capture-legal)
    cudaFuncSetAttribute(mma_gemm_kernel<0>,
                         cudaFuncAttributeMaxDynamicSharedMemorySize, SMEM_BYTES);
    cudaFuncSetAttribute(mma_gemm_kernel<1>,
                         cudaFuncAttributeMaxDynamicSharedMemorySize, SMEM_BYTES);
    cudaFuncSetAttribute(mma_gemm_kernel<2>,
                         cudaFuncAttributeMaxDynamicSharedMemorySize, SMEM_BYTES);

    add_pos_kernel<<<(size_t)TOK * CDIM / 4 / 256, 256>>>(x, pos, out);

    for (int l = 0; l < LAYERS; l++) {
        // --- attention block ---
        ln_kernel<<<TOK, 256>>>(out, ln1_g + (size_t)l * CDIM, ln1_b + (size_t)l * CDIM, xn);
        mma_gemm_kernel<0><<<dim3(3 * CDIM / 128, TOK / 128), 256, SMEM_BYTES>>>(
            xn, qkv_w + (size_t)l * CDIM * 3 * CDIM, qkv_b + (size_t)l * 3 * CDIM,
            nullptr, qkv, TOK, 3 * CDIM, CDIM);
        attn_kernel<<<dim3(NSEQ / 64, BSZ * HEADS), 256>>>(qkv, attn);
        mma_gemm_kernel<2><<<dim3(CDIM / 128, TOK / 128), 256, SMEM_BYTES>>>(
            attn, proj_w + (size_t)l * CDIM * CDIM, proj_b + (size_t)l * CDIM,
            out, out, TOK, CDIM, CDIM);
        // --- MLP block ---
        ln_kernel<<<TOK, 256>>>(out, ln2_g + (size_t)l * CDIM, ln2_b + (size_t)l * CDIM, xn);
        mma_gemm_kernel<1><<<dim3(FFD / 128, TOK / 128), 256, SMEM_BYTES>>>(
            xn, fc1_w + (size_t)l * CDIM * FFD, fc1_b + (size_t)l * FFD,
            nullptr, ff, TOK, FFD, CDIM);
        mma_gemm_kernel<2><<<dim3(CDIM / 128, TOK / 128), 256, SMEM_BYTES>>>(
            ff, fc2_w + (size_t)l * FFD * CDIM, fc2_b + (size_t)l * CDIM,
            out, out, TOK, CDIM, FFD);
    }
}

// round 4
// speedup vs baseline: 3.5468x; 1.2814x over previous
#include <cuda_runtime.h>
#include <math.h>
#include <stdint.h>

#define TOK   4096          // B*N
#define BSZ   4
#define NSEQ  1024
#define CDIM  1024
#define HEADS 16
#define HDIM  64
#define FFD   4096
#define LAYERS 4
#define ATT_SCALE 0.125f    // 64^-0.5

#define LDA 36              // smem stride (floats) for A tiles (128x32)
#define LDB 136             // smem stride (floats) for B tiles (32x128)
#define SMEM_A_FLOATS (2 * 128 * LDA)
#define SMEM_B_FLOATS (2 * 32 * LDB)
#define SMEM_BYTES ((SMEM_A_FLOATS + SMEM_B_FLOATS) * 4)

// attn smem: Q [2 chunks][64*36] + K [2 buf][2 chunks][128*36]
#define ATTN_Q_FLOATS (2 * 64 * 36)
#define ATTN_K_FLOATS (4 * 128 * 36)
#define ATTN_SMEM_BYTES ((ATTN_Q_FLOATS + ATTN_K_FLOATS) * 4)

// Scratch (device globals; no allocation allowed)
__device__ float g_xn  [(size_t)TOK * CDIM];
__device__ float g_qkv [(size_t)TOK * 3 * CDIM];
__device__ float g_attn[(size_t)TOK * CDIM];
__device__ float g_ff  [(size_t)TOK * FFD];
// tf32-pre-rounded weights
__device__ float g_wq[(size_t)LAYERS * CDIM * 3 * CDIM];
__device__ float g_wp[(size_t)LAYERS * CDIM * CDIM];
__device__ float g_w1[(size_t)LAYERS * CDIM * FFD];
__device__ float g_w2[(size_t)LAYERS * FFD * CDIM];

// ---------------------------------------------------------------------------
__device__ __forceinline__ float tf32r(float x) {
    float y;
    asm("cvt.rna.tf32.f32 %0, %1;" : "=f"(y) : "f"(x));
    return y;
}
__device__ __forceinline__ void cp_async16(uint32_t s, const void* g) {
    asm volatile("cp.async.cg.shared.global [%0], [%1], 16;" :: "r"(s), "l"(g));
}
__device__ __forceinline__ void cp_commit() {
    asm volatile("cp.async.commit_group;");
}
__device__ __forceinline__ void cp_wait0() {
    asm volatile("cp.async.wait_group 0;");
}
__device__ __forceinline__ void ldsm_x4(uint32_t& r0, uint32_t& r1, uint32_t& r2,
                                        uint32_t& r3, uint32_t addr) {
    asm volatile("ldmatrix.sync.aligned.m8n8.x4.shared.b16 {%0,%1,%2,%3}, [%4];"
                 : "=r"(r0), "=r"(r1), "=r"(r2), "=r"(r3) : "r"(addr));
}
__device__ __forceinline__ void mma_tf32(float* c, const uint32_t* a, const uint32_t* b) {
    asm volatile(
        "mma.sync.aligned.m16n8k8.row.col.f32.tf32.tf32.f32 "
        "{%0,%1,%2,%3}, {%4,%5,%6,%7}, {%8,%9}, {%0,%1,%2,%3};"
        : "+f"(c[0]), "+f"(c[1]), "+f"(c[2]), "+f"(c[3])
        : "r"(a[0]), "r"(a[1]), "r"(a[2]), "r"(a[3]), "r"(b[0]), "r"(b[1]));
}

// ---------------------------------------------------------------------------
// weight pre-round: dst = tf32(src), float4-vectorized
// ---------------------------------------------------------------------------
__global__ void round_w_kernel(const float* __restrict__ src,
                               float* __restrict__ dst, int n4) {
    int i = blockIdx.x * blockDim.x + threadIdx.x;
    if (i >= n4) return;
    float4 v = ((const float4*)src)[i];
    v.x = tf32r(v.x); v.y = tf32r(v.y); v.z = tf32r(v.z); v.w = tf32r(v.w);
    ((float4*)dst)[i] = v;
}

// ---------------------------------------------------------------------------
// out = x + pos (pos broadcast over batch)
// ---------------------------------------------------------------------------
__global__ void add_pos_kernel(const float* __restrict__ x,
                               const float* __restrict__ pos,
                               float* __restrict__ out) {
    int i = blockIdx.x * blockDim.x + threadIdx.x;
    const float4 a = ((const float4*)x)[i];
    const float4 p = ((const float4*)pos)[i & ((NSEQ * CDIM / 4) - 1)];
    float4 o;
    o.x = a.x + p.x; o.y = a.y + p.y; o.z = a.z + p.z; o.w = a.w + p.w;
    ((float4*)out)[i] = o;
}

// ---------------------------------------------------------------------------
// LayerNorm: one block (256 thr) per row of 1024. Output tf32-rounded.
// ---------------------------------------------------------------------------
__global__ void ln_kernel(const float* __restrict__ in,
                          const float* __restrict__ g,
                          const float* __restrict__ b,
                          float* __restrict__ out) {
    const int row = blockIdx.x;
    const int tid = threadIdx.x;
    const float4 x = ((const float4*)(in + (size_t)row * CDIM))[tid];
    float s  = x.x + x.y + x.z + x.w;
    float sq = x.x * x.x + x.y * x.y + x.z * x.z + x.w * x.w;

    __shared__ float ssum[8], ssq[8];
    __shared__ float smean, srstd;
    const int lane = tid & 31, wid = tid >> 5;
    #pragma unroll
    for (int o = 16; o > 0; o >>= 1) {
        s  += __shfl_down_sync(0xffffffffu, s, o);
        sq += __shfl_down_sync(0xffffffffu, sq, o);
    }
    if (lane == 0) { ssum[wid] = s; ssq[wid] = sq; }
    __syncthreads();
    if (tid == 0) {
        float S = 0.f, Q = 0.f;
        #pragma unroll
        for (int w = 0; w < 8; w++) { S += ssum[w]; Q += ssq[w]; }
        const float mean = S * (1.0f / CDIM);
        const float var  = Q * (1.0f / CDIM) - mean * mean;
        smean = mean;
        srstd = rsqrtf(var + 1e-5f);
    }
    __syncthreads();
    const float mean = smean, rstd = srstd;
    float4 gg = ((const float4*)g)[tid];
    float4 bb = ((const float4*)b)[tid];
    float4 y;
    y.x = tf32r((x.x - mean) * rstd * gg.x + bb.x);
    y.y = tf32r((x.y - mean) * rstd * gg.y + bb.y);
    y.z = tf32r((x.z - mean) * rstd * gg.z + bb.z);
    y.w = tf32r((x.w - mean) * rstd * gg.w + bb.w);
    ((float4*)(out + (size_t)row * CDIM))[tid] = y;
}

// ---------------------------------------------------------------------------
// TF32 tensor-core GEMM: C[M,N] = A[M,K] @ W[K,N] + bias
// A and W must already be tf32-rounded.
// ACT 0: none, 1: gelu+round, 2: +residual, 3: round
// ---------------------------------------------------------------------------
template <int ACT>
__global__ __launch_bounds__(256)
void mma_gemm_kernel(const float* __restrict__ A,
                     const float* __restrict__ W,
                     const float* __restrict__ bias,
                     const float* __restrict__ res,
                     float* __restrict__ C,
                     int M, int N, int K) {
    extern __shared__ float smem[];
    float* Asm = smem;                              // [2][128*LDA]
    float* Bsm = smem + SMEM_A_FLOATS;              // [2][32*LDB]

    const int tid  = threadIdx.x;
    const int lane = tid & 31;
    const int warp = tid >> 5;
    const int wm = warp >> 2;
    const int wn = warp & 3;
    const int bm = blockIdx.y * 128;
    const int bn = blockIdx.x * 128;

    float acc[4][4][4];
    #pragma unroll
    for (int i = 0; i < 4; i++)
        #pragma unroll
        for (int j = 0; j < 4; j++)
            #pragma unroll
            for (int t = 0; t < 4; t++) acc[i][j][t] = 0.f;

    const int ar  = tid >> 3;
    const int ac4 = (tid & 7) * 4;
    const int br  = tid >> 5;
    const int bc4 = (tid & 31) * 4;

    auto load_tile = [&](int kt, int st) {
        const float* Ag = A + (size_t)bm * K + kt * 32;
        float* as = Asm + st * (128 * LDA);
        #pragma unroll
        for (int i = 0; i < 4; i++) {
            int r = ar + i * 32;
            uint32_t sa = (uint32_t)__cvta_generic_to_shared(&as[r * LDA + ac4]);
            cp_async16(sa, Ag + (size_t)r * K + ac4);
        }
        const float* Wg = W + (size_t)(kt * 32) * N + bn;
        float* bs = Bsm + st * (32 * LDB);
        #pragma unroll
        for (int i = 0; i < 4; i++) {
            int r = br + i * 8;
            uint32_t sa = (uint32_t)__cvta_generic_to_shared(&bs[r * LDB + bc4]);
            cp_async16(sa, Wg + (size_t)r * N + bc4);
        }
    };

    const int KT = K / 32;
    load_tile(0, 0);
    cp_commit();

    const int a_row = wm * 64 + (lane & 15);
    const int a_col = (lane >> 4) * 4;
    const int b_k = lane & 3;
    const int b_n = wn * 32 + (lane >> 2);

    for (int kt = 0; kt < KT; kt++) {
        const int st = kt & 1;
        cp_wait0();
        __syncthreads();
        if (kt + 1 < KT) { load_tile(kt + 1, st ^ 1); cp_commit(); }

        const float* as = Asm + st * (128 * LDA);
        const float* bs = Bsm + st * (32 * LDB);
        #pragma unroll
        for (int ks = 0; ks < 4; ks++) {
            uint32_t a[4][4];
            #pragma unroll
            for (int mt = 0; mt < 4; mt++) {
                uint32_t addr = (uint32_t)__cvta_generic_to_shared(
                    &as[(a_row + mt * 16) * LDA + ks * 8 + a_col]);
                ldsm_x4(a[mt][0], a[mt][1], a[mt][2], a[mt][3], addr);
            }
            uint32_t b[4][2];
            #pragma unroll
            for (int nt = 0; nt < 4; nt++) {
                b[nt][0] = __float_as_uint(bs[(ks * 8 + b_k) * LDB + b_n + nt * 8]);
                b[nt][1] = __float_as_uint(bs[(ks * 8 + b_k + 4) * LDB + b_n + nt * 8]);
            }
            #pragma unroll
            for (int mt = 0; mt < 4; mt++)
                #pragma unroll
                for (int nt = 0; nt < 4; nt++)
                    mma_tf32(acc[mt][nt], a[mt], b[nt]);
        }
        __syncthreads();
    }

    const int e_row = bm + wm * 64 + (lane >> 2);
    const int e_col = bn + wn * 32 + (lane & 3) * 2;
    #pragma unroll
    for (int mt = 0; mt < 4; mt++) {
        #pragma unroll
        for (int nt = 0; nt < 4; nt++) {
            const int col = e_col + nt * 8;
            const float bz0 = bias[col], bz1 = bias[col + 1];
            #pragma unroll
            for (int half = 0; half < 2; half++) {
                const int row = e_row + mt * 16 + half * 8;
                float v0 = acc[mt][nt][half * 2 + 0] + bz0;
                float v1 = acc[mt][nt][half * 2 + 1] + bz1;
                if (ACT == 1) {
                    v0 = tf32r(0.5f * v0 * (1.0f + erff(v0 * 0.70710678118654752f)));
                    v1 = tf32r(0.5f * v1 * (1.0f + erff(v1 * 0.70710678118654752f)));
                }
                if (ACT == 2) {
                    const float2 r2 = *(const float2*)(res + (size_t)row * N + col);
                    v0 += r2.x; v1 += r2.y;
                }
                if (ACT == 3) { v0 = tf32r(v0); v1 = tf32r(v1); }
                float2 o; o.x = v0; o.y = v1;
                *(float2*)(C + (size_t)row * N + col) = o;
            }
        }
    }
}

// ---------------------------------------------------------------------------
// Tensor-core attention with hard threshold.
//   out_row = (1/Z > 0.5) ? V[argmax]/Z : 0,   Z = sum exp(s - max)
// Scores S = Q K^T via tf32 MMA. 64 q-rows per block, 128-key chunks,
// cp.async double-buffered K, online (max, argmax, Z) on fragments.
// qkv buffer is tf32-rounded by the qkv GEMM (ACT=3).
// ---------------------------------------------------------------------------
__global__ __launch_bounds__(256, 2)
void attn_mma_kernel(const float* __restrict__ qkv,
                     float* __restrict__ out) {
    extern __shared__ float sm[];
    float* Qs = sm;                       // [2 chunk][64*36]
    float* Ks = sm + ATTN_Q_FLOATS;       // [2 buf][2 chunk][128*36]

    __shared__ float part_m[64][4];
    __shared__ float part_z[64][4];
    __shared__ int   part_j[64][4];
    __shared__ float rscale[64];
    __shared__ int   rjmax[64];

    const int bh = blockIdx.y;
    const int b  = bh >> 4;
    const int h  = bh & 15;
    const int r0 = blockIdx.x * 64;
    const int tid = threadIdx.x, lane = tid & 31, warp = tid >> 5;
    const int wm = warp >> 2, wn = warp & 3;

    // load Q tile [64][64] into 2 chunked [64][36] tiles
    #pragma unroll
    for (int i = 0; i < 4; i++) {
        int idx = tid + i * 256;            // 0..1023
        int r = idx >> 4, d4 = (idx & 15) * 4;
        const float4 q = *(const float4*)(qkv + ((size_t)(b * NSEQ + r0 + r) * 3) * CDIM
                                          + h * HDIM + d4);
        *(float4*)(Qs + (d4 >> 5) * (64 * 36) + r * 36 + (d4 & 31)) = q;
    }

    auto load_k = [&](int c0, int buf) {
        float* base = Ks + buf * (2 * 128 * 36);
        #pragma unroll
        for (int i = 0; i < 8; i++) {
            int idx = tid + i * 256;        // 0..2047
            int r = idx >> 4, d4 = (idx & 15) * 4;
            const float* src = qkv + ((size_t)(b * NSEQ + c0 + r) * 3 + 1) * CDIM
                               + h * HDIM + d4;
            uint32_t dst = (uint32_t)__cvta_generic_to_shared(
                base + (d4 >> 5) * (128 * 36) + r * 36 + (d4 & 31));
            cp_async16(dst, src);
        }
    };

    load_k(0, 0);
    cp_commit();

    float m_[4], Z_[4];
    int j_[4];
    #pragma unroll
    for (int i = 0; i < 4; i++) { m_[i] = -1e30f; Z_[i] = 0.f; j_[i] = 0; }

    for (int kc = 0; kc < 8; kc++) {
        const int buf = kc & 1;
        cp_wait0();
        __syncthreads();
        if (kc < 7) { load_k((kc + 1) * 128, buf ^ 1); cp_commit(); }

        float acc[2][4][4];
        #pragma unroll
        for (int i = 0; i < 2; i++)
            #pragma unroll
            for (int j = 0; j < 4; j++)
                #pragma unroll
                for (int t = 0; t < 4; t++) acc[i][j][t] = 0.f;

        const float* kb = Ks + buf * (2 * 128 * 36);
        #pragma unroll
        for (int ks = 0; ks < 8; ks++) {
            const float* qc = Qs + (ks >> 2) * (64 * 36);
            const float* kch = kb + (ks >> 2) * (128 * 36);
            uint32_t a[2][4];
            #pragma unroll
            for (int mt = 0; mt < 2; mt++) {
                uint32_t addr = (uint32_t)__cvta_generic_to_shared(
                    qc + (wm * 32 + mt * 16 + (lane & 15)) * 36
                       + (ks & 3) * 8 + (lane >> 4) * 4);
                ldsm_x4(a[mt][0], a[mt][1], a[mt][2], a[mt][3], addr);
            }
            uint32_t bfr[4][2];
            #pragma unroll
            for (int nt = 0; nt < 4; nt++) {
                const float* bp = kch + (wn * 32 + nt * 8 + (lane >> 2)) * 36
                                  + (ks & 3) * 8 + (lane & 3);
                bfr[nt][0] = __float_as_uint(bp[0]);
                bfr[nt][1] = __float_as_uint(bp[4]);
            }
            #pragma unroll
            for (int mt = 0; mt < 2; mt++)
                #pragma unroll
                for (int nt = 0; nt < 4; nt++)
                    mma_tf32(acc[mt][nt], a[mt], bfr[nt]);
        }

        // online (max, argmax, Z) update on fragments
        #pragma unroll
        for (int mt = 0; mt < 2; mt++) {
            #pragma unroll
            for (int half = 0; half < 2; half++) {
                const int si = mt * 2 + half;
                const int bcol = kc * 128 + wn * 32 + (lane & 3) * 2;
                float v[8];
                #pragma unroll
                for (int nt = 0; nt < 4; nt++) {
                    v[nt * 2 + 0] = acc[mt][nt][half * 2 + 0] * ATT_SCALE;
                    v[nt * 2 + 1] = acc[mt][nt][half * 2 + 1] * ATT_SCALE;
                }
                float cmax = v[0]; int cj = bcol;
                #pragma unroll
                for (int q = 1; q < 8; q++) {
                    int col = bcol + (q >> 1) * 8 + (q & 1);
                    if (v[q] > cmax) { cmax = v[q]; cj = col; }
                }
                if (cmax > m_[si]) {
                    Z_[si] *= expf(m_[si] - cmax);
                    m_[si] = cmax;
                    j_[si] = cj;
                }
                float e = 0.f;
                #pragma unroll
                for (int q = 0; q < 8; q++) e += expf(v[q] - m_[si]);
                Z_[si] += e;
            }
        }
    }

    // quad (lane&3) reduce, then cross-warp (wn) reduce via smem
    #pragma unroll
    for (int si = 0; si < 4; si++) {
        float mm = m_[si], zz = Z_[si];
        int jj = j_[si];
        #pragma unroll
        for (int o = 1; o <= 2; o <<= 1) {
            float om = __shfl_xor_sync(0xffffffffu, mm, o);
            float oz = __shfl_xor_sync(0xffffffffu, zz, o);
            int   oj = __shfl_xor_sync(0xffffffffu, jj, o);
            if (om > mm) { zz = zz * expf(mm - om) + oz; mm = om; jj = oj; }
            else         { zz = zz + oz * expf(om - mm); }
        }
        if ((lane & 3) == 0) {
            int row = wm * 32 + (si >> 1) * 16 + (si & 1) * 8 + (lane >> 2);
            part_m[row][wn] = mm;
            part_z[row][wn] = zz;
            part_j[row][wn] = jj;
        }
    }
    __syncthreads();

    if (tid < 64) {
        float mm = part_m[tid][0], zz = part_z[tid][0];
        int jj = part_j[tid][0];
        #pragma unroll
        for (int t = 1; t < 4; t++) {
            float om = part_m[tid][t], oz = part_z[tid][t];
            int   oj = part_j[tid][t];
            if (om > mm) { zz = zz * expf(mm - om) + oz; mm = om; jj = oj; }
            else         { zz = zz + oz * expf(om - mm); }
        }
        const float amax = 1.0f / zz;
        rscale[tid] = (amax > 0.5f) ? amax : 0.0f;
        rjmax[tid]  = jj;
    }
    __syncthreads();

    // gather: out_row = scale * V[jmax]; tf32-rounded (feeds proj GEMM)
    const int r  = tid >> 2;
    const int d0 = (tid & 3) * 16;
    const float sc = rscale[r];
    const int jj = rjmax[r];
    const float* vrow = qkv + ((size_t)(b * NSEQ + jj) * 3 + 2) * CDIM + h * HDIM;
    float* orow = out + (size_t)(b * NSEQ + r0 + r) * CDIM + h * HDIM;
    #pragma unroll
    for (int d = d0; d < d0 + 16; d += 4) {
        float4 o;
        if (sc != 0.0f) {
            float4 v = *(const float4*)(vrow + d);
            o.x = tf32r(v.x * sc); o.y = tf32r(v.y * sc);
            o.z = tf32r(v.z * sc); o.w = tf32r(v.w * sc);
        } else {
            o.x = 0.f; o.y = 0.f; o.z = 0.f; o.w = 0.f;
        }
        *(float4*)(orow + d) = o;
    }
}

// ---------------------------------------------------------------------------
extern "C" void kernel_launch(void* const* d_in, const int* in_sizes, int n_in,
                              void* d_out, int out_size) {
    (void)in_sizes; (void)n_in; (void)out_size;
    const float* x      = (const float*)d_in[0];
    const float* pos    = (const float*)d_in[1];
    const float* qkv_w  = (const float*)d_in[2];
    const float* qkv_b  = (const float*)d_in[3];
    const float* proj_w = (const float*)d_in[4];
    const float* proj_b = (const float*)d_in[5];
    const float* ln1_g  = (const float*)d_in[6];
    const float* ln1_b  = (const float*)d_in[7];
    const float* ln2_g  = (const float*)d_in[8];
    const float* ln2_b  = (const float*)d_in[9];
    const float* fc1_w  = (const float*)d_in[10];
    const float* fc1_b  = (const float*)d_in[11];
    const float* fc2_w  = (const float*)d_in[12];
    const float* fc2_b  = (const float*)d_in[13];
    float* out = (float*)d_out;

    float *xn, *qkv, *attn, *ff, *wq, *wp, *w1, *w2;
    cudaGetSymbolAddress((void**)&xn,   g_xn);
    cudaGetSymbolAddress((void**)&qkv,  g_qkv);
    cudaGetSymbolAddress((void**)&attn, g_attn);
    cudaGetSymbolAddress((void**)&ff,   g_ff);
    cudaGetSymbolAddress((void**)&wq,   g_wq);
    cudaGetSymbolAddress((void**)&wp,   g_wp);
    cudaGetSymbolAddress((void**)&w1,   g_w1);
    cudaGetSymbolAddress((void**)&w2,   g_w2);

    cudaFuncSetAttribute(mma_gemm_kernel<1>,
                         cudaFuncAttributeMaxDynamicSharedMemorySize, SMEM_BYTES);
    cudaFuncSetAttribute(mma_gemm_kernel<2>,
                         cudaFuncAttributeMaxDynamicSharedMemorySize, SMEM_BYTES);
    cudaFuncSetAttribute(mma_gemm_kernel<3>,
                         cudaFuncAttributeMaxDynamicSharedMemorySize, SMEM_BYTES);
    cudaFuncSetAttribute(attn_mma_kernel,
                         cudaFuncAttributeMaxDynamicSharedMemorySize, ATTN_SMEM_BYTES);

    // pre-round all weights to tf32 (once per launch; deterministic)
    {
        const int nq = LAYERS * CDIM * 3 * CDIM / 4;
        const int np = LAYERS * CDIM * CDIM / 4;
        const int nf = LAYERS * CDIM * FFD / 4;
        round_w_kernel<<<(nq + 255) / 256, 256>>>(qkv_w,  wq, nq);
        round_w_kernel<<<(np + 255) / 256, 256>>>(proj_w, wp, np);
        round_w_kernel<<<(nf + 255) / 256, 256>>>(fc1_w,  w1, nf);
        round_w_kernel<<<(nf + 255) / 256, 256>>>(fc2_w,  w2, nf);
    }

    add_pos_kernel<<<(size_t)TOK * CDIM / 4 / 256, 256>>>(x, pos, out);

    for (int l = 0; l < LAYERS; l++) {
        // --- attention block ---
        ln_kernel<<<TOK, 256>>>(out, ln1_g + (size_t)l * CDIM, ln1_b + (size_t)l * CDIM, xn);
        mma_gemm_kernel<3><<<dim3(3 * CDIM / 128, TOK / 128), 256, SMEM_BYTES>>>(
            xn, wq + (size_t)l * CDIM * 3 * CDIM, qkv_b + (size_t)l * 3 * CDIM,
            nullptr, qkv, TOK, 3 * CDIM, CDIM);
        attn_mma_kernel<<<dim3(NSEQ / 64, BSZ * HEADS), 256, ATTN_SMEM_BYTES>>>(qkv, attn);
        mma_gemm_kernel<2><<<dim3(CDIM / 128, TOK / 128), 256, SMEM_BYTES>>>(
            attn, wp + (size_t)l * CDIM * CDIM, proj_b + (size_t)l * CDIM,
            out, out, TOK, CDIM, CDIM);
        // --- MLP block ---
        ln_kernel<<<TOK, 256>>>(out, ln2_g + (size_t)l * CDIM, ln2_b + (size_t)l * CDIM, xn);
        mma_gemm_kernel<1><<<dim3(FFD / 128, TOK / 128), 256, SMEM_BYTES>>>(
            xn, w1 + (size_t)l * CDIM * FFD, fc1_b + (size_t)l * FFD,
            nullptr, ff, TOK, FFD, CDIM);
        mma_gemm_kernel<2><<<dim3(CDIM / 128, TOK / 128), 256, SMEM_BYTES>>>(
            ff, w2 + (size_t)l * FFD * CDIM, fc2_b + (size_t)l * CDIM,
            out, out, TOK, CDIM, FFD);
    }
}

// round 6
// speedup vs baseline: 6.1013x; 1.7202x over previous
#include <cuda_runtime.h>
#include <cuda_fp16.h>
#include <math.h>
#include <stdint.h>

#define TOK   4096          // B*N
#define BSZ   4
#define NSEQ  1024
#define CDIM  1024
#define HEADS 16
#define HDIM  64
#define FFD   4096
#define LAYERS 4
#define ATT_SCALE 0.125f    // 64^-0.5

// GEMM smem strides (halves)
#define LDH 72              // 64 halves + 8 pad -> 144 B row stride
#define GEMM_TILE_H (128 * LDH)                 // halves per tile
#define GEMM_SMEM_BYTES (4 * GEMM_TILE_H * 2)   // A0,A1,B0,B1 = 73728 B

// attn smem: Q [64][72] + K [2 buf][128][72] halves
#define ATTN_Q_H (64 * LDH)
#define ATTN_K_H (2 * 128 * LDH)
#define ATTN_SMEM_BYTES ((ATTN_Q_H + ATTN_K_H) * 2)

// Scratch (device globals; no allocation allowed)
__device__ __half g_xn  [(size_t)TOK * CDIM];
__device__ __half g_qkv [(size_t)TOK * 3 * CDIM];
__device__ __half g_attn[(size_t)TOK * CDIM];
__device__ __half g_ff  [(size_t)TOK * FFD];
// fp16, TRANSPOSED weights: Wt[N][K]
__device__ __half g_wq[(size_t)LAYERS * CDIM * 3 * CDIM];
__device__ __half g_wp[(size_t)LAYERS * CDIM * CDIM];
__device__ __half g_w1[(size_t)LAYERS * CDIM * FFD];
__device__ __half g_w2[(size_t)LAYERS * FFD * CDIM];

// ---------------------------------------------------------------------------
__device__ __forceinline__ void cp_async16(uint32_t s, const void* g) {
    asm volatile("cp.async.cg.shared.global [%0], [%1], 16;" :: "r"(s), "l"(g));
}
__device__ __forceinline__ void cp_commit() {
    asm volatile("cp.async.commit_group;");
}
__device__ __forceinline__ void cp_wait0() {
    asm volatile("cp.async.wait_group 0;");
}
__device__ __forceinline__ void ldsm_x4(uint32_t& r0, uint32_t& r1, uint32_t& r2,
                                        uint32_t& r3, uint32_t addr) {
    asm volatile("ldmatrix.sync.aligned.m8n8.x4.shared.b16 {%0,%1,%2,%3}, [%4];"
                 : "=r"(r0), "=r"(r1), "=r"(r2), "=r"(r3) : "r"(addr));
}
__device__ __forceinline__ void mma_f16(float* c, const uint32_t* a, const uint32_t* b) {
    asm volatile(
        "mma.sync.aligned.m16n8k16.row.col.f32.f16.f16.f32 "
        "{%0,%1,%2,%3}, {%4,%5,%6,%7}, {%8,%9}, {%0,%1,%2,%3};"
        : "+f"(c[0]), "+f"(c[1]), "+f"(c[2]), "+f"(c[3])
        : "r"(a[0]), "r"(a[1]), "r"(a[2]), "r"(a[3]), "r"(b[0]), "r"(b[1]));
}

// ---------------------------------------------------------------------------
// weight prep: fp32 [K,N] -> half [N,K] (transpose + convert), per-layer via z
// ---------------------------------------------------------------------------
__global__ void prep_w_kernel(const float* __restrict__ src,
                              __half* __restrict__ dst, int K, int N) {
    __shared__ __half t[32][33];
    const size_t lo = (size_t)blockIdx.z * K * N;
    const int n0 = blockIdx.x * 32, k0 = blockIdx.y * 32;
    const int tx = threadIdx.x & 31, ty = threadIdx.x >> 5;   // 32x8
    #pragma unroll
    for (int i = 0; i < 4; i++) {
        int k = k0 + ty + i * 8;
        t[ty + i * 8][tx] = __float2half(src[lo + (size_t)k * N + n0 + tx]);
    }
    __syncthreads();
    #pragma unroll
    for (int i = 0; i < 4; i++) {
        int n = n0 + ty + i * 8;
        dst[lo + (size_t)n * K + k0 + tx] = t[tx][ty + i * 8];
    }
}

// ---------------------------------------------------------------------------
// out = x + pos (pos broadcast over batch), fp32
// ---------------------------------------------------------------------------
__global__ void add_pos_kernel(const float* __restrict__ x,
                               const float* __restrict__ pos,
                               float* __restrict__ out) {
    int i = blockIdx.x * blockDim.x + threadIdx.x;
    const float4 a = ((const float4*)x)[i];
    const float4 p = ((const float4*)pos)[i & ((NSEQ * CDIM / 4) - 1)];
    float4 o;
    o.x = a.x + p.x; o.y = a.y + p.y; o.z = a.z + p.z; o.w = a.w + p.w;
    ((float4*)out)[i] = o;
}

// ---------------------------------------------------------------------------
// LayerNorm: one block (256 thr) per row of 1024. fp32 in -> fp16 out.
// ---------------------------------------------------------------------------
__global__ void ln_kernel(const float* __restrict__ in,
                          const float* __restrict__ g,
                          const float* __restrict__ b,
                          __half* __restrict__ out) {
    const int row = blockIdx.x;
    const int tid = threadIdx.x;
    const float4 x = ((const float4*)(in + (size_t)row * CDIM))[tid];
    float s  = x.x + x.y + x.z + x.w;
    float sq = x.x * x.x + x.y * x.y + x.z * x.z + x.w * x.w;

    __shared__ float ssum[8], ssq[8];
    __shared__ float smean, srstd;
    const int lane = tid & 31, wid = tid >> 5;
    #pragma unroll
    for (int o = 16; o > 0; o >>= 1) {
        s  += __shfl_down_sync(0xffffffffu, s, o);
        sq += __shfl_down_sync(0xffffffffu, sq, o);
    }
    if (lane == 0) { ssum[wid] = s; ssq[wid] = sq; }
    __syncthreads();
    if (tid == 0) {
        float S = 0.f, Q = 0.f;
        #pragma unroll
        for (int w = 0; w < 8; w++) { S += ssum[w]; Q += ssq[w]; }
        const float mean = S * (1.0f / CDIM);
        const float var  = Q * (1.0f / CDIM) - mean * mean;
        smean = mean;
        srstd = rsqrtf(var + 1e-5f);
    }
    __syncthreads();
    const float mean = smean, rstd = srstd;
    float4 gg = ((const float4*)g)[tid];
    float4 bb = ((const float4*)b)[tid];
    __half2 h0 = __floats2half2_rn((x.x - mean) * rstd * gg.x + bb.x,
                                   (x.y - mean) * rstd * gg.y + bb.y);
    __half2 h1 = __floats2half2_rn((x.z - mean) * rstd * gg.z + bb.z,
                                   (x.w - mean) * rstd * gg.w + bb.w);
    uint2 o;
    o.x = *(uint32_t*)&h0;
    o.y = *(uint32_t*)&h1;
    ((uint2*)(out + (size_t)row * CDIM))[tid] = o;
}

// ---------------------------------------------------------------------------
// FP16 tensor-core GEMM: C = A[M,K] @ Wt[N,K]^T + bias
// A, Wt fp16; accumulate fp32. 128x128 CTA tile, BK=64, 256 threads
// (2x4 warps, 64x32 warp tiles), cp.async double-buffered.
// ACT 1: gelu (half out), 2: +residual (fp32 out), 3: plain (half out)
// ---------------------------------------------------------------------------
template <int ACT, typename OUT_T>
__global__ __launch_bounds__(256)
void hgemm_kernel(const __half* __restrict__ A,
                  const __half* __restrict__ Wt,
                  const float* __restrict__ bias,
                  const float* __restrict__ res,
                  OUT_T* __restrict__ C,
                  int M, int N, int K) {
    extern __shared__ __half smh[];
    __half* Asm = smh;                      // [2][128*LDH]
    __half* Bsm = smh + 2 * GEMM_TILE_H;    // [2][128*LDH]

    const int tid  = threadIdx.x;
    const int lane = tid & 31;
    const int warp = tid >> 5;
    const int wm = warp >> 2;
    const int wn = warp & 3;
    const int bm = blockIdx.y * 128;
    const int bn = blockIdx.x * 128;

    float acc[4][4][4];
    #pragma unroll
    for (int i = 0; i < 4; i++)
        #pragma unroll
        for (int j = 0; j < 4; j++)
            #pragma unroll
            for (int t = 0; t < 4; t++) acc[i][j][t] = 0.f;

    // loaders: each tile is 128 rows x 64 halves = 8 chunks(16B) per row,
    // 1024 chunks, 256 threads -> 4 each.
    auto load_tile = [&](int kt, int st) {
        const __half* Ag = A  + (size_t)bm * K + kt * 64;
        const __half* Bg = Wt + (size_t)bn * K + kt * 64;
        __half* as = Asm + st * GEMM_TILE_H;
        __half* bs = Bsm + st * GEMM_TILE_H;
        #pragma unroll
        for (int i = 0; i < 4; i++) {
            int c = tid + i * 256;
            int r = c >> 3, seg = (c & 7) * 8;
            cp_async16((uint32_t)__cvta_generic_to_shared(as + r * LDH + seg),
                       Ag + (size_t)r * K + seg);
            cp_async16((uint32_t)__cvta_generic_to_shared(bs + r * LDH + seg),
                       Bg + (size_t)r * K + seg);
        }
    };

    const int KT = K / 64;
    load_tile(0, 0);
    cp_commit();

    const int a_row = wm * 64 + (lane & 15);
    const int a_koff = (lane >> 4) * 8;
    const int b_n = wn * 32 + (lane >> 2);
    const int b_k = (lane & 3) * 2;

    for (int kt = 0; kt < KT; kt++) {
        const int st = kt & 1;
        cp_wait0();
        __syncthreads();
        if (kt + 1 < KT) { load_tile(kt + 1, st ^ 1); cp_commit(); }

        const __half* as = Asm + st * GEMM_TILE_H;
        const __half* bs = Bsm + st * GEMM_TILE_H;
        #pragma unroll
        for (int ks = 0; ks < 4; ks++) {
            uint32_t a[4][4];
            #pragma unroll
            for (int mt = 0; mt < 4; mt++) {
                uint32_t addr = (uint32_t)__cvta_generic_to_shared(
                    as + (a_row + mt * 16) * LDH + ks * 16 + a_koff);
                ldsm_x4(a[mt][0], a[mt][1], a[mt][2], a[mt][3], addr);
            }
            uint32_t b[4][2];
            #pragma unroll
            for (int nt = 0; nt < 4; nt++) {
                const __half* bp = bs + (b_n + nt * 8) * LDH + ks * 16 + b_k;
                b[nt][0] = *(const uint32_t*)(bp);
                b[nt][1] = *(const uint32_t*)(bp + 8);
            }
            #pragma unroll
            for (int mt = 0; mt < 4; mt++)
                #pragma unroll
                for (int nt = 0; nt < 4; nt++)
                    mma_f16(acc[mt][nt], a[mt], b[nt]);
        }
        __syncthreads();
    }

    // Epilogue: c0,c1 at (row, col..col+1), c2,c3 at (row+8, ...)
    const int e_row = bm + wm * 64 + (lane >> 2);
    const int e_col = bn + wn * 32 + (lane & 3) * 2;
    #pragma unroll
    for (int mt = 0; mt < 4; mt++) {
        #pragma unroll
        for (int nt = 0; nt < 4; nt++) {
            const int col = e_col + nt * 8;
            const float bz0 = bias[col], bz1 = bias[col + 1];
            #pragma unroll
            for (int half_i = 0; half_i < 2; half_i++) {
                const int row = e_row + mt * 16 + half_i * 8;
                float v0 = acc[mt][nt][half_i * 2 + 0] + bz0;
                float v1 = acc[mt][nt][half_i * 2 + 1] + bz1;
                if (ACT == 1) {
                    v0 = 0.5f * v0 * (1.0f + erff(v0 * 0.70710678118654752f));
                    v1 = 0.5f * v1 * (1.0f + erff(v1 * 0.70710678118654752f));
                }
                if (ACT == 2) {
                    const float2 r2 = *(const float2*)(res + (size_t)row * N + col);
                    v0 += r2.x; v1 += r2.y;
                    float2 o; o.x = v0; o.y = v1;
                    *(float2*)((float*)C + (size_t)row * N + col) = o;
                } else {
                    __half2 h = __floats2half2_rn(v0, v1);
                    *(uint32_t*)((__half*)C + (size_t)row * N + col) = *(uint32_t*)&h;
                }
            }
        }
    }
}

// ---------------------------------------------------------------------------
// FP16 tensor-core attention with hard threshold.
//   out_row = (1/Z > 0.5) ? V[argmax]/Z : 0,   Z = sum exp(s - max)
// 64 q-rows per block, 128-key chunks, fp16 m16n8k16 scores.
// ---------------------------------------------------------------------------
__global__ __launch_bounds__(256, 2)
void attn_mma_kernel(const __half* __restrict__ qkv,
                     __half* __restrict__ out) {
    extern __shared__ __half smh[];
    __half* Qs = smh;                 // [64][LDH]
    __half* Ks = smh + ATTN_Q_H;      // [2 buf][128][LDH]

    __shared__ float part_m[64][4];
    __shared__ float part_z[64][4];
    __shared__ int   part_j[64][4];
    __shared__ float rscale[64];
    __shared__ int   rjmax[64];

    const int bh = blockIdx.y;
    const int b  = bh >> 4;
    const int h  = bh & 15;
    const int r0 = blockIdx.x * 64;
    const int tid = threadIdx.x, lane = tid & 31, warp = tid >> 5;
    const int wm = warp >> 2, wn = warp & 3;

    // load Q tile [64][64]: 512 16B chunks
    #pragma unroll
    for (int i = 0; i < 2; i++) {
        int c = tid + i * 256;
        int r = c >> 3, seg = (c & 7) * 8;
        const __half* src = qkv + ((size_t)(b * NSEQ + r0 + r) * 3) * CDIM
                            + h * HDIM + seg;
        cp_async16((uint32_t)__cvta_generic_to_shared(Qs + r * LDH + seg), src);
    }

    auto load_k = [&](int c0, int buf) {
        __half* base = Ks + buf * (128 * LDH);
        #pragma unroll
        for (int i = 0; i < 4; i++) {
            int c = tid + i * 256;
            int r = c >> 3, seg = (c & 7) * 8;
            const __half* src = qkv + ((size_t)(b * NSEQ + c0 + r) * 3 + 1) * CDIM
                                + h * HDIM + seg;
            cp_async16((uint32_t)__cvta_generic_to_shared(base + r * LDH + seg), src);
        }
    };

    cp_commit();                 // Q group
    load_k(0, 0);
    cp_commit();

    float m_[4], Z_[4];
    int j_[4];
    #pragma unroll
    for (int i = 0; i < 4; i++) { m_[i] = -1e30f; Z_[i] = 0.f; j_[i] = 0; }

    for (int kc = 0; kc < 8; kc++) {
        const int buf = kc & 1;
        cp_wait0();
        __syncthreads();
        if (kc < 7) { load_k((kc + 1) * 128, buf ^ 1); cp_commit(); }

        float acc[2][4][4];
        #pragma unroll
        for (int i = 0; i < 2; i++)
            #pragma unroll
            for (int j = 0; j < 4; j++)
                #pragma unroll
                for (int t = 0; t < 4; t++) acc[i][j][t] = 0.f;

        const __half* kb = Ks + buf * (128 * LDH);
        #pragma unroll
        for (int ks = 0; ks < 4; ks++) {
            uint32_t a[2][4];
            #pragma unroll
            for (int mt = 0; mt < 2; mt++) {
                uint32_t addr = (uint32_t)__cvta_generic_to_shared(
                    Qs + (wm * 32 + mt * 16 + (lane & 15)) * LDH
                       + ks * 16 + (lane >> 4) * 8);
                ldsm_x4(a[mt][0], a[mt][1], a[mt][2], a[mt][3], addr);
            }
            uint32_t bfr[4][2];
            #pragma unroll
            for (int nt = 0; nt < 4; nt++) {
                const __half* bp = kb + (wn * 32 + nt * 8 + (lane >> 2)) * LDH
                                   + ks * 16 + (lane & 3) * 2;
                bfr[nt][0] = *(const uint32_t*)(bp);
                bfr[nt][1] = *(const uint32_t*)(bp + 8);
            }
            #pragma unroll
            for (int mt = 0; mt < 2; mt++)
                #pragma unroll
                for (int nt = 0; nt < 4; nt++)
                    mma_f16(acc[mt][nt], a[mt], bfr[nt]);
        }

        // online (max, argmax, Z) update on fragments
        #pragma unroll
        for (int mt = 0; mt < 2; mt++) {
            #pragma unroll
            for (int half_i = 0; half_i < 2; half_i++) {
                const int si = mt * 2 + half_i;
                const int bcol = kc * 128 + wn * 32 + (lane & 3) * 2;
                float v[8];
                #pragma unroll
                for (int nt = 0; nt < 4; nt++) {
                    v[nt * 2 + 0] = acc[mt][nt][half_i * 2 + 0] * ATT_SCALE;
                    v[nt * 2 + 1] = acc[mt][nt][half_i * 2 + 1] * ATT_SCALE;
                }
                float cmax = v[0]; int cj = bcol;
                #pragma unroll
                for (int q = 1; q < 8; q++) {
                    int col = bcol + (q >> 1) * 8 + (q & 1);
                    if (v[q] > cmax) { cmax = v[q]; cj = col; }
                }
                if (cmax > m_[si]) {
                    Z_[si] *= expf(m_[si] - cmax);
                    m_[si] = cmax;
                    j_[si] = cj;
                }
                float e = 0.f;
                #pragma unroll
                for (int q = 0; q < 8; q++) e += expf(v[q] - m_[si]);
                Z_[si] += e;
            }
        }
    }

    // quad (lane&3) reduce, then cross-warp (wn) reduce via smem
    #pragma unroll
    for (int si = 0; si < 4; si++) {
        float mm = m_[si], zz = Z_[si];
        int jj = j_[si];
        #pragma unroll
        for (int o = 1; o <= 2; o <<= 1) {
            float om = __shfl_xor_sync(0xffffffffu, mm, o);
            float oz = __shfl_xor_sync(0xffffffffu, zz, o);
            int   oj = __shfl_xor_sync(0xffffffffu, jj, o);
            if (om > mm) { zz = zz * expf(mm - om) + oz; mm = om; jj = oj; }
            else         { zz = zz + oz * expf(om - mm); }
        }
        if ((lane & 3) == 0) {
            int row = wm * 32 + (si >> 1) * 16 + (si & 1) * 8 + (lane >> 2);
            part_m[row][wn] = mm;
            part_z[row][wn] = zz;
            part_j[row][wn] = jj;
        }
    }
    __syncthreads();

    if (tid < 64) {
        float mm = part_m[tid][0], zz = part_z[tid][0];
        int jj = part_j[tid][0];
        #pragma unroll
        for (int t = 1; t < 4; t++) {
            float om = part_m[tid][t], oz = part_z[tid][t];
            int   oj = part_j[tid][t];
            if (om > mm) { zz = zz * expf(mm - om) + oz; mm = om; jj = oj; }
            else         { zz = zz + oz * expf(om - mm); }
        }
        const float amax = 1.0f / zz;
        rscale[tid] = (amax > 0.5f) ? amax : 0.0f;
        rjmax[tid]  = jj;
    }
    __syncthreads();

    // gather: out_row = scale * V[jmax] (half in, half out)
    const int r  = tid >> 2;
    const int d0 = (tid & 3) * 16;
    const float sc = rscale[r];
    const int jj = rjmax[r];
    const __half* vrow = qkv + ((size_t)(b * NSEQ + jj) * 3 + 2) * CDIM + h * HDIM;
    __half* orow = out + (size_t)(b * NSEQ + r0 + r) * CDIM + h * HDIM;
    #pragma unroll
    for (int d = d0; d < d0 + 16; d += 4) {
        uint2 o;
        if (sc != 0.0f) {
            const uint2 v = *(const uint2*)(vrow + d);
            __half2 v0 = *(const __half2*)&v.x;
            __half2 v1 = *(const __half2*)&v.y;
            float2 f0 = __half22float2(v0);
            float2 f1 = __half22float2(v1);
            __half2 h0 = __floats2half2_rn(f0.x * sc, f0.y * sc);
            __half2 h1 = __floats2half2_rn(f1.x * sc, f1.y * sc);
            o.x = *(uint32_t*)&h0;
            o.y = *(uint32_t*)&h1;
        } else {
            o.x = 0u; o.y = 0u;
        }
        *(uint2*)(orow + d) = o;
    }
}

// ---------------------------------------------------------------------------
extern "C" void kernel_launch(void* const* d_in, const int* in_sizes, int n_in,
                              void* d_out, int out_size) {
    (void)in_sizes; (void)n_in; (void)out_size;
    const float* x      = (const float*)d_in[0];
    const float* pos    = (const float*)d_in[1];
    const float* qkv_w  = (const float*)d_in[2];
    const float* qkv_b  = (const float*)d_in[3];
    const float* proj_w = (const float*)d_in[4];
    const float* proj_b = (const float*)d_in[5];
    const float* ln1_g  = (const float*)d_in[6];
    const float* ln1_b  = (const float*)d_in[7];
    const float* ln2_g  = (const float*)d_in[8];
    const float* ln2_b  = (const float*)d_in[9];
    const float* fc1_w  = (const float*)d_in[10];
    const float* fc1_b  = (const float*)d_in[11];
    const float* fc2_w  = (const float*)d_in[12];
    const float* fc2_b  = (const float*)d_in[13];
    float* out = (float*)d_out;

    __half *xn, *qkv, *attn, *ff, *wq, *wp, *w1, *w2;
    cudaGetSymbolAddress((void**)&xn,   g_xn);
    cudaGetSymbolAddress((void**)&qkv,  g_qkv);
    cudaGetSymbolAddress((void**)&attn, g_attn);
    cudaGetSymbolAddress((void**)&ff,   g_ff);
    cudaGetSymbolAddress((void**)&wq,   g_wq);
    cudaGetSymbolAddress((void**)&wp,   g_wp);
    cudaGetSymbolAddress((void**)&w1,   g_w1);
    cudaGetSymbolAddress((void**)&w2,   g_w2);

    cudaFuncSetAttribute(hgemm_kernel<1, __half>,
                         cudaFuncAttributeMaxDynamicSharedMemorySize, GEMM_SMEM_BYTES);
    cudaFuncSetAttribute(hgemm_kernel<2, float>,
                         cudaFuncAttributeMaxDynamicSharedMemorySize, GEMM_SMEM_BYTES);
    cudaFuncSetAttribute(hgemm_kernel<3, __half>,
                         cudaFuncAttributeMaxDynamicSharedMemorySize, GEMM_SMEM_BYTES);
    cudaFuncSetAttribute(attn_mma_kernel,
                         cudaFuncAttributeMaxDynamicSharedMemorySize, ATTN_SMEM_BYTES);

    // weight prep: fp16 convert + transpose [K,N] -> [N,K] (once per launch)
    prep_w_kernel<<<dim3(3 * CDIM / 32, CDIM / 32, LAYERS), 256>>>(qkv_w,  wq, CDIM, 3 * CDIM);
    prep_w_kernel<<<dim3(CDIM / 32,     CDIM / 32, LAYERS), 256>>>(proj_w, wp, CDIM, CDIM);
    prep_w_kernel<<<dim3(FFD / 32,      CDIM / 32, LAYERS), 256>>>(fc1_w,  w1, CDIM, FFD);
    prep_w_kernel<<<dim3(CDIM / 32,     FFD / 32,  LAYERS), 256>>>(fc2_w,  w2, FFD, CDIM);

    add_pos_kernel<<<(size_t)TOK * CDIM / 4 / 256, 256>>>(x, pos, out);

    for (int l = 0; l < LAYERS; l++) {
        // --- attention block ---
        ln_kernel<<<TOK, 256>>>(out, ln1_g + (size_t)l * CDIM, ln1_b + (size_t)l * CDIM, xn);
        hgemm_kernel<3, __half><<<dim3(3 * CDIM / 128, TOK / 128), 256, GEMM_SMEM_BYTES>>>(
            xn, wq + (size_t)l * CDIM * 3 * CDIM, qkv_b + (size_t)l * 3 * CDIM,
            nullptr, qkv, TOK, 3 * CDIM, CDIM);
        attn_mma_kernel<<<dim3(NSEQ / 64, BSZ * HEADS), 256, ATTN_SMEM_BYTES>>>(qkv, attn);
        hgemm_kernel<2, float><<<dim3(CDIM / 128, TOK / 128), 256, GEMM_SMEM_BYTES>>>(
            attn, wp + (size_t)l * CDIM * CDIM, proj_b + (size_t)l * CDIM,
            out, out, TOK, CDIM, CDIM);
        // --- MLP block ---
        ln_kernel<<<TOK, 256>>>(out, ln2_g + (size_t)l * CDIM, ln2_b + (size_t)l * CDIM, xn);
        hgemm_kernel<1, __half><<<dim3(FFD / 128, TOK / 128), 256, GEMM_SMEM_BYTES>>>(
            xn, w1 + (size_t)l * CDIM * FFD, fc1_b + (size_t)l * FFD,
            nullptr, ff, TOK, FFD, CDIM);
        hgemm_kernel<2, float><<<dim3(CDIM / 128, TOK / 128), 256, GEMM_SMEM_BYTES>>>(
            ff, w2 + (size_t)l * FFD * CDIM, fc2_b + (size_t)l * CDIM,
            out, out, TOK, CDIM, FFD);
    }
}

// round 7
// speedup vs baseline: 6.4135x; 1.0512x over previous
#include <cuda_runtime.h>
#include <cuda_fp16.h>
#include <math.h>
#include <stdint.h>

#define TOK   4096          // B*N
#define BSZ   4
#define NSEQ  1024
#define CDIM  1024
#define HEADS 16
#define HDIM  64
#define FFD   4096
#define LAYERS 4
#define ATT_SCALE 0.125f    // 64^-0.5

// GEMM smem strides (halves)
#define LDH 72              // 64 halves + 8 pad -> 144 B row stride
#define GEMM_TILE_H (128 * LDH)                 // halves per (A or B) tile
#define STAGE_H (2 * GEMM_TILE_H)               // A + B per stage
#define GEMM_STAGES 3
#define GEMM_SMEM_BYTES (GEMM_STAGES * STAGE_H * 2)   // 110592 B

// attn smem: Q [64][72] + K [2 buf][128][72] halves
#define ATTN_Q_H (64 * LDH)
#define ATTN_K_H (2 * 128 * LDH)
#define ATTN_SMEM_BYTES ((ATTN_Q_H + ATTN_K_H) * 2)

// Scratch (device globals; no allocation allowed)
__device__ __half g_xn  [(size_t)TOK * CDIM];
__device__ __half g_qkv [(size_t)TOK * 3 * CDIM];
__device__ __half g_attn[(size_t)TOK * CDIM];
__device__ __half g_ff  [(size_t)TOK * FFD];
// fp16, TRANSPOSED weights: Wt[N][K]
__device__ __half g_wq[(size_t)LAYERS * CDIM * 3 * CDIM];
__device__ __half g_wp[(size_t)LAYERS * CDIM * CDIM];
__device__ __half g_w1[(size_t)LAYERS * CDIM * FFD];
__device__ __half g_w2[(size_t)LAYERS * FFD * CDIM];

// ---------------------------------------------------------------------------
__device__ __forceinline__ void cp_async16(uint32_t s, const void* g) {
    asm volatile("cp.async.cg.shared.global [%0], [%1], 16;" :: "r"(s), "l"(g));
}
__device__ __forceinline__ void cp_commit() {
    asm volatile("cp.async.commit_group;");
}
__device__ __forceinline__ void cp_wait0() {
    asm volatile("cp.async.wait_group 0;");
}
__device__ __forceinline__ void cp_wait1() {
    asm volatile("cp.async.wait_group 1;");
}
__device__ __forceinline__ void ldsm_x4(uint32_t& r0, uint32_t& r1, uint32_t& r2,
                                        uint32_t& r3, uint32_t addr) {
    asm volatile("ldmatrix.sync.aligned.m8n8.x4.shared.b16 {%0,%1,%2,%3}, [%4];"
                 : "=r"(r0), "=r"(r1), "=r"(r2), "=r"(r3) : "r"(addr));
}
__device__ __forceinline__ void mma_f16(float* c, const uint32_t* a, const uint32_t* b) {
    asm volatile(
        "mma.sync.aligned.m16n8k16.row.col.f32.f16.f16.f32 "
        "{%0,%1,%2,%3}, {%4,%5,%6,%7}, {%8,%9}, {%0,%1,%2,%3};"
        : "+f"(c[0]), "+f"(c[1]), "+f"(c[2]), "+f"(c[3])
        : "r"(a[0]), "r"(a[1]), "r"(a[2]), "r"(a[3]), "r"(b[0]), "r"(b[1]));
}

// ---------------------------------------------------------------------------
// weight prep: fp32 [K,N] -> half [N,K] (transpose + convert), per-layer via z
// ---------------------------------------------------------------------------
__global__ void prep_w_kernel(const float* __restrict__ src,
                              __half* __restrict__ dst, int K, int N) {
    __shared__ __half t[32][33];
    const size_t lo = (size_t)blockIdx.z * K * N;
    const int n0 = blockIdx.x * 32, k0 = blockIdx.y * 32;
    const int tx = threadIdx.x & 31, ty = threadIdx.x >> 5;   // 32x8
    #pragma unroll
    for (int i = 0; i < 4; i++) {
        int k = k0 + ty + i * 8;
        t[ty + i * 8][tx] = __float2half(src[lo + (size_t)k * N + n0 + tx]);
    }
    __syncthreads();
    #pragma unroll
    for (int i = 0; i < 4; i++) {
        int n = n0 + ty + i * 8;
        dst[lo + (size_t)n * K + k0 + tx] = t[tx][ty + i * 8];
    }
}

// ---------------------------------------------------------------------------
// out = x + pos (pos broadcast over batch), fp32
// ---------------------------------------------------------------------------
__global__ void add_pos_kernel(const float* __restrict__ x,
                               const float* __restrict__ pos,
                               float* __restrict__ out) {
    int i = blockIdx.x * blockDim.x + threadIdx.x;
    const float4 a = ((const float4*)x)[i];
    const float4 p = ((const float4*)pos)[i & ((NSEQ * CDIM / 4) - 1)];
    float4 o;
    o.x = a.x + p.x; o.y = a.y + p.y; o.z = a.z + p.z; o.w = a.w + p.w;
    ((float4*)out)[i] = o;
}

// ---------------------------------------------------------------------------
// LayerNorm: one block (256 thr) per row of 1024. fp32 in -> fp16 out.
// ---------------------------------------------------------------------------
__global__ void ln_kernel(const float* __restrict__ in,
                          const float* __restrict__ g,
                          const float* __restrict__ b,
                          __half* __restrict__ out) {
    const int row = blockIdx.x;
    const int tid = threadIdx.x;
    const float4 x = ((const float4*)(in + (size_t)row * CDIM))[tid];
    float s  = x.x + x.y + x.z + x.w;
    float sq = x.x * x.x + x.y * x.y + x.z * x.z + x.w * x.w;

    __shared__ float ssum[8], ssq[8];
    __shared__ float smean, srstd;
    const int lane = tid & 31, wid = tid >> 5;
    #pragma unroll
    for (int o = 16; o > 0; o >>= 1) {
        s  += __shfl_down_sync(0xffffffffu, s, o);
        sq += __shfl_down_sync(0xffffffffu, sq, o);
    }
    if (lane == 0) { ssum[wid] = s; ssq[wid] = sq; }
    __syncthreads();
    if (tid == 0) {
        float S = 0.f, Q = 0.f;
        #pragma unroll
        for (int w = 0; w < 8; w++) { S += ssum[w]; Q += ssq[w]; }
        const float mean = S * (1.0f / CDIM);
        const float var  = Q * (1.0f / CDIM) - mean * mean;
        smean = mean;
        srstd = rsqrtf(var + 1e-5f);
    }
    __syncthreads();
    const float mean = smean, rstd = srstd;
    float4 gg = ((const float4*)g)[tid];
    float4 bb = ((const float4*)b)[tid];
    __half2 h0 = __floats2half2_rn((x.x - mean) * rstd * gg.x + bb.x,
                                   (x.y - mean) * rstd * gg.y + bb.y);
    __half2 h1 = __floats2half2_rn((x.z - mean) * rstd * gg.z + bb.z,
                                   (x.w - mean) * rstd * gg.w + bb.w);
    uint2 o;
    o.x = *(uint32_t*)&h0;
    o.y = *(uint32_t*)&h1;
    ((uint2*)(out + (size_t)row * CDIM))[tid] = o;
}

// ---------------------------------------------------------------------------
// FP16 tensor-core GEMM: C = A[M,K] @ Wt[N,K]^T + bias
// 128x128 CTA tile, BK=64, 256 threads (2x4 warps, 64x32 warp tiles),
// 3-stage cp.async pipeline, ldmatrix for both A and B fragments.
// ACT 1: gelu (half out), 2: +residual (fp32 out), 3: plain (half out)
// ---------------------------------------------------------------------------
template <int ACT, typename OUT_T>
__global__ __launch_bounds__(256)
void hgemm_kernel(const __half* __restrict__ A,
                  const __half* __restrict__ Wt,
                  const float* __restrict__ bias,
                  const float* __restrict__ res,
                  OUT_T* __restrict__ C,
                  int M, int N, int K) {
    extern __shared__ __half smh[];

    const int tid  = threadIdx.x;
    const int lane = tid & 31;
    const int warp = tid >> 5;
    const int wm = warp >> 2;
    const int wn = warp & 3;
    const int bm = blockIdx.y * 128;
    const int bn = blockIdx.x * 128;

    float acc[4][4][4];
    #pragma unroll
    for (int i = 0; i < 4; i++)
        #pragma unroll
        for (int j = 0; j < 4; j++)
            #pragma unroll
            for (int t = 0; t < 4; t++) acc[i][j][t] = 0.f;

    // loaders: each tile is 128 rows x 64 halves = 1024 16B chunks, 4/thread
    auto load_tile = [&](int kt, int st) {
        const __half* Ag = A  + (size_t)bm * K + kt * 64;
        const __half* Bg = Wt + (size_t)bn * K + kt * 64;
        __half* as = smh + st * STAGE_H;
        __half* bs = as + GEMM_TILE_H;
        #pragma unroll
        for (int i = 0; i < 4; i++) {
            int c = tid + i * 256;
            int r = c >> 3, seg = (c & 7) * 8;
            cp_async16((uint32_t)__cvta_generic_to_shared(as + r * LDH + seg),
                       Ag + (size_t)r * K + seg);
            cp_async16((uint32_t)__cvta_generic_to_shared(bs + r * LDH + seg),
                       Bg + (size_t)r * K + seg);
        }
    };

    const int KT = K / 64;
    load_tile(0, 0);
    cp_commit();
    load_tile(1, 1);
    cp_commit();

    const int a_row  = wm * 64 + (lane & 15);
    const int a_koff = (lane >> 4) * 8;
    // B ldmatrix x4 per-lane row/col: group g=lane>>3
    const int b_g = lane >> 3;
    const int b_r = lane & 7;

    for (int kt = 0; kt < KT; kt++) {
        if (kt + 1 < KT) cp_wait1(); else cp_wait0();
        __syncthreads();
        if (kt + 2 < KT) { load_tile(kt + 2, (kt + 2) % GEMM_STAGES); cp_commit(); }

        const __half* as = smh + (kt % GEMM_STAGES) * STAGE_H;
        const __half* bs = as + GEMM_TILE_H;
        #pragma unroll
        for (int ks = 0; ks < 4; ks++) {
            uint32_t a[4][4];
            #pragma unroll
            for (int mt = 0; mt < 4; mt++) {
                uint32_t addr = (uint32_t)__cvta_generic_to_shared(
                    as + (a_row + mt * 16) * LDH + ks * 16 + a_koff);
                ldsm_x4(a[mt][0], a[mt][1], a[mt][2], a[mt][3], addr);
            }
            uint32_t b[4][2];
            #pragma unroll
            for (int c = 0; c < 2; c++) {
                // mats: (nt=2c,klo),(2c,khi),(2c+1,klo),(2c+1,khi)
                int row = wn * 32 + (2 * c + (b_g >> 1)) * 8 + b_r;
                int col = ks * 16 + (b_g & 1) * 8;
                uint32_t addr = (uint32_t)__cvta_generic_to_shared(
                    bs + row * LDH + col);
                ldsm_x4(b[2 * c][0], b[2 * c][1], b[2 * c + 1][0], b[2 * c + 1][1], addr);
            }
            #pragma unroll
            for (int mt = 0; mt < 4; mt++)
                #pragma unroll
                for (int nt = 0; nt < 4; nt++)
                    mma_f16(acc[mt][nt], a[mt], b[nt]);
        }
    }

    // Epilogue: c0,c1 at (row, col..col+1), c2,c3 at (row+8, ...)
    const int e_row = bm + wm * 64 + (lane >> 2);
    const int e_col = bn + wn * 32 + (lane & 3) * 2;
    #pragma unroll
    for (int mt = 0; mt < 4; mt++) {
        #pragma unroll
        for (int nt = 0; nt < 4; nt++) {
            const int col = e_col + nt * 8;
            const float bz0 = bias[col], bz1 = bias[col + 1];
            #pragma unroll
            for (int half_i = 0; half_i < 2; half_i++) {
                const int row = e_row + mt * 16 + half_i * 8;
                float v0 = acc[mt][nt][half_i * 2 + 0] + bz0;
                float v1 = acc[mt][nt][half_i * 2 + 1] + bz1;
                if (ACT == 1) {
                    v0 = 0.5f * v0 * (1.0f + erff(v0 * 0.70710678118654752f));
                    v1 = 0.5f * v1 * (1.0f + erff(v1 * 0.70710678118654752f));
                }
                if (ACT == 2) {
                    const float2 r2 = *(const float2*)(res + (size_t)row * N + col);
                    v0 += r2.x; v1 += r2.y;
                    float2 o; o.x = v0; o.y = v1;
                    *(float2*)((float*)C + (size_t)row * N + col) = o;
                } else {
                    __half2 h = __floats2half2_rn(v0, v1);
                    *(uint32_t*)((__half*)C + (size_t)row * N + col) = *(uint32_t*)&h;
                }
            }
        }
    }
}

// ---------------------------------------------------------------------------
// FP16 tensor-core attention with hard threshold.
//   out_row = (1/Z > 0.5) ? V[argmax]/Z : 0,   Z = sum exp(s - max)
// 64 q-rows per block, 128-key chunks, fp16 m16n8k16 scores.
// ---------------------------------------------------------------------------
__global__ __launch_bounds__(256, 2)
void attn_mma_kernel(const __half* __restrict__ qkv,
                     __half* __restrict__ out) {
    extern __shared__ __half smh[];
    __half* Qs = smh;                 // [64][LDH]
    __half* Ks = smh + ATTN_Q_H;      // [2 buf][128][LDH]

    __shared__ float part_m[64][4];
    __shared__ float part_z[64][4];
    __shared__ int   part_j[64][4];
    __shared__ float rscale[64];
    __shared__ int   rjmax[64];

    const int bh = blockIdx.y;
    const int b  = bh >> 4;
    const int h  = bh & 15;
    const int r0 = blockIdx.x * 64;
    const int tid = threadIdx.x, lane = tid & 31, warp = tid >> 5;
    const int wm = warp >> 2, wn = warp & 3;

    // load Q tile [64][64]: 512 16B chunks
    #pragma unroll
    for (int i = 0; i < 2; i++) {
        int c = tid + i * 256;
        int r = c >> 3, seg = (c & 7) * 8;
        const __half* src = qkv + ((size_t)(b * NSEQ + r0 + r) * 3) * CDIM
                            + h * HDIM + seg;
        cp_async16((uint32_t)__cvta_generic_to_shared(Qs + r * LDH + seg), src);
    }

    auto load_k = [&](int c0, int buf) {
        __half* base = Ks + buf * (128 * LDH);
        #pragma unroll
        for (int i = 0; i < 4; i++) {
            int c = tid + i * 256;
            int r = c >> 3, seg = (c & 7) * 8;
            const __half* src = qkv + ((size_t)(b * NSEQ + c0 + r) * 3 + 1) * CDIM
                                + h * HDIM + seg;
            cp_async16((uint32_t)__cvta_generic_to_shared(base + r * LDH + seg), src);
        }
    };

    cp_commit();                 // Q group
    load_k(0, 0);
    cp_commit();

    float m_[4], Z_[4];
    int j_[4];
    #pragma unroll
    for (int i = 0; i < 4; i++) { m_[i] = -1e30f; Z_[i] = 0.f; j_[i] = 0; }

    const int b_g = lane >> 3;
    const int b_r = lane & 7;

    for (int kc = 0; kc < 8; kc++) {
        const int buf = kc & 1;
        cp_wait0();
        __syncthreads();
        if (kc < 7) { load_k((kc + 1) * 128, buf ^ 1); cp_commit(); }

        float acc[2][4][4];
        #pragma unroll
        for (int i = 0; i < 2; i++)
            #pragma unroll
            for (int j = 0; j < 4; j++)
                #pragma unroll
                for (int t = 0; t < 4; t++) acc[i][j][t] = 0.f;

        const __half* kb = Ks + buf * (128 * LDH);
        #pragma unroll
        for (int ks = 0; ks < 4; ks++) {
            uint32_t a[2][4];
            #pragma unroll
            for (int mt = 0; mt < 2; mt++) {
                uint32_t addr = (uint32_t)__cvta_generic_to_shared(
                    Qs + (wm * 32 + mt * 16 + (lane & 15)) * LDH
                       + ks * 16 + (lane >> 4) * 8);
                ldsm_x4(a[mt][0], a[mt][1], a[mt][2], a[mt][3], addr);
            }
            uint32_t bfr[4][2];
            #pragma unroll
            for (int c = 0; c < 2; c++) {
                int row = wn * 32 + (2 * c + (b_g >> 1)) * 8 + b_r;
                int col = ks * 16 + (b_g & 1) * 8;
                uint32_t addr = (uint32_t)__cvta_generic_to_shared(
                    kb + row * LDH + col);
                ldsm_x4(bfr[2 * c][0], bfr[2 * c][1], bfr[2 * c + 1][0], bfr[2 * c + 1][1], addr);
            }
            #pragma unroll
            for (int mt = 0; mt < 2; mt++)
                #pragma unroll
                for (int nt = 0; nt < 4; nt++)
                    mma_f16(acc[mt][nt], a[mt], bfr[nt]);
        }

        // online (max, argmax, Z) update on fragments
        #pragma unroll
        for (int mt = 0; mt < 2; mt++) {
            #pragma unroll
            for (int half_i = 0; half_i < 2; half_i++) {
                const int si = mt * 2 + half_i;
                const int bcol = kc * 128 + wn * 32 + (lane & 3) * 2;
                float v[8];
                #pragma unroll
                for (int nt = 0; nt < 4; nt++) {
                    v[nt * 2 + 0] = acc[mt][nt][half_i * 2 + 0] * ATT_SCALE;
                    v[nt * 2 + 1] = acc[mt][nt][half_i * 2 + 1] * ATT_SCALE;
                }
                float cmax = v[0]; int cj = bcol;
                #pragma unroll
                for (int q = 1; q < 8; q++) {
                    int col = bcol + (q >> 1) * 8 + (q & 1);
                    if (v[q] > cmax) { cmax = v[q]; cj = col; }
                }
                if (cmax > m_[si]) {
                    Z_[si] *= __expf(m_[si] - cmax);
                    m_[si] = cmax;
                    j_[si] = cj;
                }
                float e = 0.f;
                #pragma unroll
                for (int q = 0; q < 8; q++) e += __expf(v[q] - m_[si]);
                Z_[si] += e;
            }
        }
    }

    // quad (lane&3) reduce, then cross-warp (wn) reduce via smem
    #pragma unroll
    for (int si = 0; si < 4; si++) {
        float mm = m_[si], zz = Z_[si];
        int jj = j_[si];
        #pragma unroll
        for (int o = 1; o <= 2; o <<= 1) {
            float om = __shfl_xor_sync(0xffffffffu, mm, o);
            float oz = __shfl_xor_sync(0xffffffffu, zz, o);
            int   oj = __shfl_xor_sync(0xffffffffu, jj, o);
            if (om > mm) { zz = zz * __expf(mm - om) + oz; mm = om; jj = oj; }
            else         { zz = zz + oz * __expf(om - mm); }
        }
        if ((lane & 3) == 0) {
            int row = wm * 32 + (si >> 1) * 16 + (si & 1) * 8 + (lane >> 2);
            part_m[row][wn] = mm;
            part_z[row][wn] = zz;
            part_j[row][wn] = jj;
        }
    }
    __syncthreads();

    if (tid < 64) {
        float mm = part_m[tid][0], zz = part_z[tid][0];
        int jj = part_j[tid][0];
        #pragma unroll
        for (int t = 1; t < 4; t++) {
            float om = part_m[tid][t], oz = part_z[tid][t];
            int   oj = part_j[tid][t];
            if (om > mm) { zz = zz * __expf(mm - om) + oz; mm = om; jj = oj; }
            else         { zz = zz + oz * __expf(om - mm); }
        }
        const float amax = 1.0f / zz;
        rscale[tid] = (amax > 0.5f) ? amax : 0.0f;
        rjmax[tid]  = jj;
    }
    __syncthreads();

    // gather: out_row = scale * V[jmax] (half in, half out)
    const int r  = tid >> 2;
    const int d0 = (tid & 3) * 16;
    const float sc = rscale[r];
    const int jj = rjmax[r];
    const __half* vrow = qkv + ((size_t)(b * NSEQ + jj) * 3 + 2) * CDIM + h * HDIM;
    __half* orow = out + (size_t)(b * NSEQ + r0 + r) * CDIM + h * HDIM;
    #pragma unroll
    for (int d = d0; d < d0 + 16; d += 4) {
        uint2 o;
        if (sc != 0.0f) {
            const uint2 v = *(const uint2*)(vrow + d);
            __half2 v0 = *(const __half2*)&v.x;
            __half2 v1 = *(const __half2*)&v.y;
            float2 f0 = __half22float2(v0);
            float2 f1 = __half22float2(v1);
            __half2 h0 = __floats2half2_rn(f0.x * sc, f0.y * sc);
            __half2 h1 = __floats2half2_rn(f1.x * sc, f1.y * sc);
            o.x = *(uint32_t*)&h0;
            o.y = *(uint32_t*)&h1;
        } else {
            o.x = 0u; o.y = 0u;
        }
        *(uint2*)(orow + d) = o;
    }
}

// ---------------------------------------------------------------------------
extern "C" void kernel_launch(void* const* d_in, const int* in_sizes, int n_in,
                              void* d_out, int out_size) {
    (void)in_sizes; (void)n_in; (void)out_size;
    const float* x      = (const float*)d_in[0];
    const float* pos    = (const float*)d_in[1];
    const float* qkv_w  = (const float*)d_in[2];
    const float* qkv_b  = (const float*)d_in[3];
    const float* proj_w = (const float*)d_in[4];
    const float* proj_b = (const float*)d_in[5];
    const float* ln1_g  = (const float*)d_in[6];
    const float* ln1_b  = (const float*)d_in[7];
    const float* ln2_g  = (const float*)d_in[8];
    const float* ln2_b  = (const float*)d_in[9];
    const float* fc1_w  = (const float*)d_in[10];
    const float* fc1_b  = (const float*)d_in[11];
    const float* fc2_w  = (const float*)d_in[12];
    const float* fc2_b  = (const float*)d_in[13];
    float* out = (float*)d_out;

    __half *xn, *qkv, *attn, *ff, *wq, *wp, *w1, *w2;
    cudaGetSymbolAddress((void**)&xn,   g_xn);
    cudaGetSymbolAddress((void**)&qkv,  g_qkv);
    cudaGetSymbolAddress((void**)&attn, g_attn);
    cudaGetSymbolAddress((void**)&ff,   g_ff);
    cudaGetSymbolAddress((void**)&wq,   g_wq);
    cudaGetSymbolAddress((void**)&wp,   g_wp);
    cudaGetSymbolAddress((void**)&w1,   g_w1);
    cudaGetSymbolAddress((void**)&w2,   g_w2);

    cudaFuncSetAttribute(hgemm_kernel<1, __half>,
                         cudaFuncAttributeMaxDynamicSharedMemorySize, GEMM_SMEM_BYTES);
    cudaFuncSetAttribute(hgemm_kernel<2, float>,
                         cudaFuncAttributeMaxDynamicSharedMemorySize, GEMM_SMEM_BYTES);
    cudaFuncSetAttribute(hgemm_kernel<3, __half>,
                         cudaFuncAttributeMaxDynamicSharedMemorySize, GEMM_SMEM_BYTES);
    cudaFuncSetAttribute(attn_mma_kernel,
                         cudaFuncAttributeMaxDynamicSharedMemorySize, ATTN_SMEM_BYTES);

    // weight prep: fp16 convert + transpose [K,N] -> [N,K] (once per launch)
    prep_w_kernel<<<dim3(3 * CDIM / 32, CDIM / 32, LAYERS), 256>>>(qkv_w,  wq, CDIM, 3 * CDIM);
    prep_w_kernel<<<dim3(CDIM / 32,     CDIM / 32, LAYERS), 256>>>(proj_w, wp, CDIM, CDIM);
    prep_w_kernel<<<dim3(FFD / 32,      CDIM / 32, LAYERS), 256>>>(fc1_w,  w1, CDIM, FFD);
    prep_w_kernel<<<dim3(CDIM / 32,     FFD / 32,  LAYERS), 256>>>(fc2_w,  w2, FFD, CDIM);

    add_pos_kernel<<<(size_t)TOK * CDIM / 4 / 256, 256>>>(x, pos, out);

    for (int l = 0; l < LAYERS; l++) {
        // --- attention block ---
        ln_kernel<<<TOK, 256>>>(out, ln1_g + (size_t)l * CDIM, ln1_b + (size_t)l * CDIM, xn);
        hgemm_kernel<3, __half><<<dim3(3 * CDIM / 128, TOK / 128), 256, GEMM_SMEM_BYTES>>>(
            xn, wq + (size_t)l * CDIM * 3 * CDIM, qkv_b + (size_t)l * 3 * CDIM,
            nullptr, qkv, TOK, 3 * CDIM, CDIM);
        attn_mma_kernel<<<dim3(NSEQ / 64, BSZ * HEADS), 256, ATTN_SMEM_BYTES>>>(qkv, attn);
        hgemm_kernel<2, float><<<dim3(CDIM / 128, TOK / 128), 256, GEMM_SMEM_BYTES>>>(
            attn, wp + (size_t)l * CDIM * CDIM, proj_b + (size_t)l * CDIM,
            out, out, TOK, CDIM, CDIM);
        // --- MLP block ---
        ln_kernel<<<TOK, 256>>>(out, ln2_g + (size_t)l * CDIM, ln2_b + (size_t)l * CDIM, xn);
        hgemm_kernel<1, __half><<<dim3(FFD / 128, TOK / 128), 256, GEMM_SMEM_BYTES>>>(
            xn, w1 + (size_t)l * CDIM * FFD, fc1_b + (size_t)l * FFD,
            nullptr, ff, TOK, FFD, CDIM);
        hgemm_kernel<2, float><<<dim3(CDIM / 128, TOK / 128), 256, GEMM_SMEM_BYTES>>>(
            ff, w2 + (size_t)l * FFD * CDIM, fc2_b + (size_t)l * CDIM,
            out, out, TOK, CDIM, FFD);
    }
}

// round 8
// speedup vs baseline: 6.4531x; 1.0062x over previous
#include <cuda_runtime.h>
#include <cuda_fp16.h>
#include <math.h>
#include <stdint.h>

#define TOK   4096          // B*N
#define BSZ   4
#define NSEQ  1024
#define CDIM  1024
#define HEADS 16
#define HDIM  64
#define FFD   4096
#define LAYERS 4
#define ATT_SCALE 0.125f    // 64^-0.5

// GEMM smem strides (halves)
#define LDH 72              // 64 halves + 8 pad -> 144 B row stride
#define GEMM_TILE_H (128 * LDH)                 // halves per (A or B) tile
#define STAGE_H (2 * GEMM_TILE_H)               // A + B per stage
#define GEMM_STAGES 3
#define GEMM_SMEM_BYTES (GEMM_STAGES * STAGE_H * 2)   // 110592 B

// attn smem: Q [64][72] + K [2 buf][128][72] halves
#define ATTN_Q_H (64 * LDH)
#define ATTN_K_H (2 * 128 * LDH)
#define ATTN_SMEM_BYTES ((ATTN_Q_H + ATTN_K_H) * 2)

// Scratch (device globals; no allocation allowed)
__device__ __half g_xn  [(size_t)TOK * CDIM];
__device__ __half g_qkv [(size_t)TOK * 3 * CDIM];
__device__ __half g_attn[(size_t)TOK * CDIM];
__device__ __half g_ff  [(size_t)TOK * FFD];
// fp16, TRANSPOSED weights: Wt[N][K]
__device__ __half g_wq[(size_t)LAYERS * CDIM * 3 * CDIM];
__device__ __half g_wp[(size_t)LAYERS * CDIM * CDIM];
__device__ __half g_w1[(size_t)LAYERS * CDIM * FFD];
__device__ __half g_w2[(size_t)LAYERS * FFD * CDIM];

// ---------------------------------------------------------------------------
__device__ __forceinline__ void cp_async16(uint32_t s, const void* g) {
    asm volatile("cp.async.cg.shared.global [%0], [%1], 16;" :: "r"(s), "l"(g));
}
__device__ __forceinline__ void cp_commit() {
    asm volatile("cp.async.commit_group;");
}
__device__ __forceinline__ void cp_wait0() {
    asm volatile("cp.async.wait_group 0;");
}
__device__ __forceinline__ void cp_wait1() {
    asm volatile("cp.async.wait_group 1;");
}
__device__ __forceinline__ void ldsm_x4(uint32_t& r0, uint32_t& r1, uint32_t& r2,
                                        uint32_t& r3, uint32_t addr) {
    asm volatile("ldmatrix.sync.aligned.m8n8.x4.shared.b16 {%0,%1,%2,%3}, [%4];"
                 : "=r"(r0), "=r"(r1), "=r"(r2), "=r"(r3) : "r"(addr));
}
__device__ __forceinline__ void mma_f16(float* c, const uint32_t* a, const uint32_t* b) {
    asm volatile(
        "mma.sync.aligned.m16n8k16.row.col.f32.f16.f16.f32 "
        "{%0,%1,%2,%3}, {%4,%5,%6,%7}, {%8,%9}, {%0,%1,%2,%3};"
        : "+f"(c[0]), "+f"(c[1]), "+f"(c[2]), "+f"(c[3])
        : "r"(a[0]), "r"(a[1]), "r"(a[2]), "r"(a[3]), "r"(b[0]), "r"(b[1]));
}

// ---------------------------------------------------------------------------
// weight prep: fp32 [K,N] -> half [N,K] (transpose + convert), per-layer via z
// smem stride 34 halves (68 B, x17 words, odd) -> conflict-free both phases
// ---------------------------------------------------------------------------
__global__ void prep_w_kernel(const float* __restrict__ src,
                              __half* __restrict__ dst, int K, int N) {
    __shared__ __half t[32][34];
    const size_t lo = (size_t)blockIdx.z * K * N;
    const int n0 = blockIdx.x * 32, k0 = blockIdx.y * 32;
    const int tx = threadIdx.x & 31, ty = threadIdx.x >> 5;   // 32x8
    #pragma unroll
    for (int i = 0; i < 4; i++) {
        int k = k0 + ty + i * 8;
        t[ty + i * 8][tx] = __float2half(src[lo + (size_t)k * N + n0 + tx]);
    }
    __syncthreads();
    #pragma unroll
    for (int i = 0; i < 4; i++) {
        int n = n0 + ty + i * 8;
        dst[lo + (size_t)n * K + k0 + tx] = t[tx][ty + i * 8];
    }
}

// ---------------------------------------------------------------------------
// out = x + pos (pos broadcast over batch), fp32
// ---------------------------------------------------------------------------
__global__ void add_pos_kernel(const float* __restrict__ x,
                               const float* __restrict__ pos,
                               float* __restrict__ out) {
    int i = blockIdx.x * blockDim.x + threadIdx.x;
    const float4 a = ((const float4*)x)[i];
    const float4 p = ((const float4*)pos)[i & ((NSEQ * CDIM / 4) - 1)];
    float4 o;
    o.x = a.x + p.x; o.y = a.y + p.y; o.z = a.z + p.z; o.w = a.w + p.w;
    ((float4*)out)[i] = o;
}

// ---------------------------------------------------------------------------
// LayerNorm: ONE WARP per row (8 rows / 256-thr block), no block syncs.
// fp32 in -> fp16 out.
// ---------------------------------------------------------------------------
__global__ __launch_bounds__(256)
void ln_kernel(const float* __restrict__ in,
               const float* __restrict__ g,
               const float* __restrict__ b,
               __half* __restrict__ out) {
    const int row  = blockIdx.x * 8 + (threadIdx.x >> 5);
    const int lane = threadIdx.x & 31;
    const float4* rp = (const float4*)(in + (size_t)row * CDIM);

    float4 xv[8];
    float s = 0.f, sq = 0.f;
    #pragma unroll
    for (int i = 0; i < 8; i++) {
        xv[i] = rp[i * 32 + lane];
        s  += xv[i].x + xv[i].y + xv[i].z + xv[i].w;
        sq += xv[i].x * xv[i].x + xv[i].y * xv[i].y
            + xv[i].z * xv[i].z + xv[i].w * xv[i].w;
    }
    #pragma unroll
    for (int o = 16; o > 0; o >>= 1) {
        s  += __shfl_xor_sync(0xffffffffu, s, o);
        sq += __shfl_xor_sync(0xffffffffu, sq, o);
    }
    const float mean = s * (1.0f / CDIM);
    const float var  = sq * (1.0f / CDIM) - mean * mean;
    const float rstd = rsqrtf(var + 1e-5f);

    const float4* gp = (const float4*)g;
    const float4* bp = (const float4*)b;
    uint2* op = (uint2*)(out + (size_t)row * CDIM);
    #pragma unroll
    for (int i = 0; i < 8; i++) {
        const float4 gg = gp[i * 32 + lane];
        const float4 bb = bp[i * 32 + lane];
        __half2 h0 = __floats2half2_rn((xv[i].x - mean) * rstd * gg.x + bb.x,
                                       (xv[i].y - mean) * rstd * gg.y + bb.y);
        __half2 h1 = __floats2half2_rn((xv[i].z - mean) * rstd * gg.z + bb.z,
                                       (xv[i].w - mean) * rstd * gg.w + bb.w);
        uint2 o;
        o.x = *(uint32_t*)&h0;
        o.y = *(uint32_t*)&h1;
        op[i * 32 + lane] = o;
    }
}

// ---------------------------------------------------------------------------
// FP16 tensor-core GEMM: C = A[M,K] @ Wt[N,K]^T + bias
// 128x128 CTA tile, BK=64, 256 threads (2x4 warps, 64x32 warp tiles),
// 3-stage cp.async pipeline, ldmatrix for A and B, FORCED 2 CTAs/SM.
// ACT 1: gelu (half out), 2: +residual (fp32 out), 3: plain (half out)
// ---------------------------------------------------------------------------
template <int ACT, typename OUT_T>
__global__ __launch_bounds__(256, 2)
void hgemm_kernel(const __half* __restrict__ A,
                  const __half* __restrict__ Wt,
                  const float* __restrict__ bias,
                  const float* __restrict__ res,
                  OUT_T* __restrict__ C,
                  int M, int N, int K) {
    extern __shared__ __half smh[];

    const int tid  = threadIdx.x;
    const int lane = tid & 31;
    const int warp = tid >> 5;
    const int wm = warp >> 2;
    const int wn = warp & 3;
    const int bm = blockIdx.y * 128;
    const int bn = blockIdx.x * 128;

    float acc[4][4][4];
    #pragma unroll
    for (int i = 0; i < 4; i++)
        #pragma unroll
        for (int j = 0; j < 4; j++)
            #pragma unroll
            for (int t = 0; t < 4; t++) acc[i][j][t] = 0.f;

    // loaders: each tile is 128 rows x 64 halves = 1024 16B chunks, 4/thread
    auto load_tile = [&](int kt, int st) {
        const __half* Ag = A  + (size_t)bm * K + kt * 64;
        const __half* Bg = Wt + (size_t)bn * K + kt * 64;
        __half* as = smh + st * STAGE_H;
        __half* bs = as + GEMM_TILE_H;
        #pragma unroll
        for (int i = 0; i < 4; i++) {
            int c = tid + i * 256;
            int r = c >> 3, seg = (c & 7) * 8;
            cp_async16((uint32_t)__cvta_generic_to_shared(as + r * LDH + seg),
                       Ag + (size_t)r * K + seg);
            cp_async16((uint32_t)__cvta_generic_to_shared(bs + r * LDH + seg),
                       Bg + (size_t)r * K + seg);
        }
    };

    const int KT = K / 64;
    load_tile(0, 0);
    cp_commit();
    load_tile(1, 1);
    cp_commit();

    const int a_row  = wm * 64 + (lane & 15);
    const int a_koff = (lane >> 4) * 8;
    const int b_g = lane >> 3;
    const int b_r = lane & 7;

    for (int kt = 0; kt < KT; kt++) {
        if (kt + 1 < KT) cp_wait1(); else cp_wait0();
        __syncthreads();
        if (kt + 2 < KT) { load_tile(kt + 2, (kt + 2) % GEMM_STAGES); cp_commit(); }

        const __half* as = smh + (kt % GEMM_STAGES) * STAGE_H;
        const __half* bs = as + GEMM_TILE_H;
        #pragma unroll
        for (int ks = 0; ks < 4; ks++) {
            uint32_t a[4][4];
            #pragma unroll
            for (int mt = 0; mt < 4; mt++) {
                uint32_t addr = (uint32_t)__cvta_generic_to_shared(
                    as + (a_row + mt * 16) * LDH + ks * 16 + a_koff);
                ldsm_x4(a[mt][0], a[mt][1], a[mt][2], a[mt][3], addr);
            }
            uint32_t b[4][2];
            #pragma unroll
            for (int c = 0; c < 2; c++) {
                int row = wn * 32 + (2 * c + (b_g >> 1)) * 8 + b_r;
                int col = ks * 16 + (b_g & 1) * 8;
                uint32_t addr = (uint32_t)__cvta_generic_to_shared(
                    bs + row * LDH + col);
                ldsm_x4(b[2 * c][0], b[2 * c][1], b[2 * c + 1][0], b[2 * c + 1][1], addr);
            }
            #pragma unroll
            for (int mt = 0; mt < 4; mt++)
                #pragma unroll
                for (int nt = 0; nt < 4; nt++)
                    mma_f16(acc[mt][nt], a[mt], b[nt]);
        }
    }

    // Epilogue: c0,c1 at (row, col..col+1), c2,c3 at (row+8, ...)
    const int e_row = bm + wm * 64 + (lane >> 2);
    const int e_col = bn + wn * 32 + (lane & 3) * 2;
    #pragma unroll
    for (int mt = 0; mt < 4; mt++) {
        #pragma unroll
        for (int nt = 0; nt < 4; nt++) {
            const int col = e_col + nt * 8;
            const float bz0 = bias[col], bz1 = bias[col + 1];
            #pragma unroll
            for (int half_i = 0; half_i < 2; half_i++) {
                const int row = e_row + mt * 16 + half_i * 8;
                float v0 = acc[mt][nt][half_i * 2 + 0] + bz0;
                float v1 = acc[mt][nt][half_i * 2 + 1] + bz1;
                if (ACT == 1) {
                    v0 = 0.5f * v0 * (1.0f + erff(v0 * 0.70710678118654752f));
                    v1 = 0.5f * v1 * (1.0f + erff(v1 * 0.70710678118654752f));
                }
                if (ACT == 2) {
                    const float2 r2 = *(const float2*)(res + (size_t)row * N + col);
                    v0 += r2.x; v1 += r2.y;
                    float2 o; o.x = v0; o.y = v1;
                    *(float2*)((float*)C + (size_t)row * N + col) = o;
                } else {
                    __half2 h = __floats2half2_rn(v0, v1);
                    *(uint32_t*)((__half*)C + (size_t)row * N + col) = *(uint32_t*)&h;
                }
            }
        }
    }
}

// ---------------------------------------------------------------------------
// FP16 tensor-core attention with hard threshold.
//   out_row = (1/Z > 0.5) ? V[argmax]/Z : 0,   Z = sum exp(s - max)
// 64 q-rows per block, 128-key chunks, fp16 m16n8k16 scores.
// ---------------------------------------------------------------------------
__global__ __launch_bounds__(256, 2)
void attn_mma_kernel(const __half* __restrict__ qkv,
                     __half* __restrict__ out) {
    extern __shared__ __half smh[];
    __half* Qs = smh;                 // [64][LDH]
    __half* Ks = smh + ATTN_Q_H;      // [2 buf][128][LDH]

    __shared__ float part_m[64][4];
    __shared__ float part_z[64][4];
    __shared__ int   part_j[64][4];
    __shared__ float rscale[64];
    __shared__ int   rjmax[64];

    const int bh = blockIdx.y;
    const int b  = bh >> 4;
    const int h  = bh & 15;
    const int r0 = blockIdx.x * 64;
    const int tid = threadIdx.x, lane = tid & 31, warp = tid >> 5;
    const int wm = warp >> 2, wn = warp & 3;

    // load Q tile [64][64]: 512 16B chunks
    #pragma unroll
    for (int i = 0; i < 2; i++) {
        int c = tid + i * 256;
        int r = c >> 3, seg = (c & 7) * 8;
        const __half* src = qkv + ((size_t)(b * NSEQ + r0 + r) * 3) * CDIM
                            + h * HDIM + seg;
        cp_async16((uint32_t)__cvta_generic_to_shared(Qs + r * LDH + seg), src);
    }

    auto load_k = [&](int c0, int buf) {
        __half* base = Ks + buf * (128 * LDH);
        #pragma unroll
        for (int i = 0; i < 4; i++) {
            int c = tid + i * 256;
            int r = c >> 3, seg = (c & 7) * 8;
            const __half* src = qkv + ((size_t)(b * NSEQ + c0 + r) * 3 + 1) * CDIM
                                + h * HDIM + seg;
            cp_async16((uint32_t)__cvta_generic_to_shared(base + r * LDH + seg), src);
        }
    };

    cp_commit();                 // Q group
    load_k(0, 0);
    cp_commit();

    float m_[4], Z_[4];
    int j_[4];
    #pragma unroll
    for (int i = 0; i < 4; i++) { m_[i] = -1e30f; Z_[i] = 0.f; j_[i] = 0; }

    const int b_g = lane >> 3;
    const int b_r = lane & 7;

    for (int kc = 0; kc < 8; kc++) {
        const int buf = kc & 1;
        cp_wait0();
        __syncthreads();
        if (kc < 7) { load_k((kc + 1) * 128, buf ^ 1); cp_commit(); }

        float acc[2][4][4];
        #pragma unroll
        for (int i = 0; i < 2; i++)
            #pragma unroll
            for (int j = 0; j < 4; j++)
                #pragma unroll
                for (int t = 0; t < 4; t++) acc[i][j][t] = 0.f;

        const __half* kb = Ks + buf * (128 * LDH);
        #pragma unroll
        for (int ks = 0; ks < 4; ks++) {
            uint32_t a[2][4];
            #pragma unroll
            for (int mt = 0; mt < 2; mt++) {
                uint32_t addr = (uint32_t)__cvta_generic_to_shared(
                    Qs + (wm * 32 + mt * 16 + (lane & 15)) * LDH
                       + ks * 16 + (lane >> 4) * 8);
                ldsm_x4(a[mt][0], a[mt][1], a[mt][2], a[mt][3], addr);
            }
            uint32_t bfr[4][2];
            #pragma unroll
            for (int c = 0; c < 2; c++) {
                int row = wn * 32 + (2 * c + (b_g >> 1)) * 8 + b_r;
                int col = ks * 16 + (b_g & 1) * 8;
                uint32_t addr = (uint32_t)__cvta_generic_to_shared(
                    kb + row * LDH + col);
                ldsm_x4(bfr[2 * c][0], bfr[2 * c][1], bfr[2 * c + 1][0], bfr[2 * c + 1][1], addr);
            }
            #pragma unroll
            for (int mt = 0; mt < 2; mt++)
                #pragma unroll
                for (int nt = 0; nt < 4; nt++)
                    mma_f16(acc[mt][nt], a[mt], bfr[nt]);
        }

        // online (max, argmax, Z) update on fragments
        #pragma unroll
        for (int mt = 0; mt < 2; mt++) {
            #pragma unroll
            for (int half_i = 0; half_i < 2; half_i++) {
                const int si = mt * 2 + half_i;
                const int bcol = kc * 128 + wn * 32 + (lane & 3) * 2;
                float v[8];
                #pragma unroll
                for (int nt = 0; nt < 4; nt++) {
                    v[nt * 2 + 0] = acc[mt][nt][half_i * 2 + 0] * ATT_SCALE;
                    v[nt * 2 + 1] = acc[mt][nt][half_i * 2 + 1] * ATT_SCALE;
                }
                float cmax = v[0]; int cj = bcol;
                #pragma unroll
                for (int q = 1; q < 8; q++) {
                    int col = bcol + (q >> 1) * 8 + (q & 1);
                    if (v[q] > cmax) { cmax = v[q]; cj = col; }
                }
                if (cmax > m_[si]) {
                    Z_[si] *= __expf(m_[si] - cmax);
                    m_[si] = cmax;
                    j_[si] = cj;
                }
                float e = 0.f;
                #pragma unroll
                for (int q = 0; q < 8; q++) e += __expf(v[q] - m_[si]);
                Z_[si] += e;
            }
        }
    }

    // quad (lane&3) reduce, then cross-warp (wn) reduce via smem
    #pragma unroll
    for (int si = 0; si < 4; si++) {
        float mm = m_[si], zz = Z_[si];
        int jj = j_[si];
        #pragma unroll
        for (int o = 1; o <= 2; o <<= 1) {
            float om = __shfl_xor_sync(0xffffffffu, mm, o);
            float oz = __shfl_xor_sync(0xffffffffu, zz, o);
            int   oj = __shfl_xor_sync(0xffffffffu, jj, o);
            if (om > mm) { zz = zz * __expf(mm - om) + oz; mm = om; jj = oj; }
            else         { zz = zz + oz * __expf(om - mm); }
        }
        if ((lane & 3) == 0) {
            int row = wm * 32 + (si >> 1) * 16 + (si & 1) * 8 + (lane >> 2);
            part_m[row][wn] = mm;
            part_z[row][wn] = zz;
            part_j[row][wn] = jj;
        }
    }
    __syncthreads();

    if (tid < 64) {
        float mm = part_m[tid][0], zz = part_z[tid][0];
        int jj = part_j[tid][0];
        #pragma unroll
        for (int t = 1; t < 4; t++) {
            float om = part_m[tid][t], oz = part_z[tid][t];
            int   oj = part_j[tid][t];
            if (om > mm) { zz = zz * __expf(mm - om) + oz; mm = om; jj = oj; }
            else         { zz = zz + oz * __expf(om - mm); }
        }
        const float amax = 1.0f / zz;
        rscale[tid] = (amax > 0.5f) ? amax : 0.0f;
        rjmax[tid]  = jj;
    }
    __syncthreads();

    // gather: out_row = scale * V[jmax] (half in, half out)
    const int r  = tid >> 2;
    const int d0 = (tid & 3) * 16;
    const float sc = rscale[r];
    const int jj = rjmax[r];
    const __half* vrow = qkv + ((size_t)(b * NSEQ + jj) * 3 + 2) * CDIM + h * HDIM;
    __half* orow = out + (size_t)(b * NSEQ + r0 + r) * CDIM + h * HDIM;
    #pragma unroll
    for (int d = d0; d < d0 + 16; d += 4) {
        uint2 o;
        if (sc != 0.0f) {
            const uint2 v = *(const uint2*)(vrow + d);
            __half2 v0 = *(const __half2*)&v.x;
            __half2 v1 = *(const __half2*)&v.y;
            float2 f0 = __half22float2(v0);
            float2 f1 = __half22float2(v1);
            __half2 h0 = __floats2half2_rn(f0.x * sc, f0.y * sc);
            __half2 h1 = __floats2half2_rn(f1.x * sc, f1.y * sc);
            o.x = *(uint32_t*)&h0;
            o.y = *(uint32_t*)&h1;
        } else {
            o.x = 0u; o.y = 0u;
        }
        *(uint2*)(orow + d) = o;
    }
}

// ---------------------------------------------------------------------------
extern "C" void kernel_launch(void* const* d_in, const int* in_sizes, int n_in,
                              void* d_out, int out_size) {
    (void)in_sizes; (void)n_in; (void)out_size;
    const float* x      = (const float*)d_in[0];
    const float* pos    = (const float*)d_in[1];
    const float* qkv_w  = (const float*)d_in[2];
    const float* qkv_b  = (const float*)d_in[3];
    const float* proj_w = (const float*)d_in[4];
    const float* proj_b = (const float*)d_in[5];
    const float* ln1_g  = (const float*)d_in[6];
    const float* ln1_b  = (const float*)d_in[7];
    const float* ln2_g  = (const float*)d_in[8];
    const float* ln2_b  = (const float*)d_in[9];
    const float* fc1_w  = (const float*)d_in[10];
    const float* fc1_b  = (const float*)d_in[11];
    const float* fc2_w  = (const float*)d_in[12];
    const float* fc2_b  = (const float*)d_in[13];
    float* out = (float*)d_out;

    __half *xn, *qkv, *attn, *ff, *wq, *wp, *w1, *w2;
    cudaGetSymbolAddress((void**)&xn,   g_xn);
    cudaGetSymbolAddress((void**)&qkv,  g_qkv);
    cudaGetSymbolAddress((void**)&attn, g_attn);
    cudaGetSymbolAddress((void**)&ff,   g_ff);
    cudaGetSymbolAddress((void**)&wq,   g_wq);
    cudaGetSymbolAddress((void**)&wp,   g_wp);
    cudaGetSymbolAddress((void**)&w1,   g_w1);
    cudaGetSymbolAddress((void**)&w2,   g_w2);

    cudaFuncSetAttribute(hgemm_kernel<1, __half>,
                         cudaFuncAttributeMaxDynamicSharedMemorySize, GEMM_SMEM_BYTES);
    cudaFuncSetAttribute(hgemm_kernel<2, float>,
                         cudaFuncAttributeMaxDynamicSharedMemorySize, GEMM_SMEM_BYTES);
    cudaFuncSetAttribute(hgemm_kernel<3, __half>,
                         cudaFuncAttributeMaxDynamicSharedMemorySize, GEMM_SMEM_BYTES);
    cudaFuncSetAttribute(attn_mma_kernel,
                         cudaFuncAttributeMaxDynamicSharedMemorySize, ATTN_SMEM_BYTES);

    // weight prep: fp16 convert + transpose [K,N] -> [N,K] (once per launch)
    prep_w_kernel<<<dim3(3 * CDIM / 32, CDIM / 32, LAYERS), 256>>>(qkv_w,  wq, CDIM, 3 * CDIM);
    prep_w_kernel<<<dim3(CDIM / 32,     CDIM / 32, LAYERS), 256>>>(proj_w, wp, CDIM, CDIM);
    prep_w_kernel<<<dim3(FFD / 32,      CDIM / 32, LAYERS), 256>>>(fc1_w,  w1, CDIM, FFD);
    prep_w_kernel<<<dim3(CDIM / 32,     FFD / 32,  LAYERS), 256>>>(fc2_w,  w2, FFD, CDIM);

    add_pos_kernel<<<(size_t)TOK * CDIM / 4 / 256, 256>>>(x, pos, out);

    for (int l = 0; l < LAYERS; l++) {
        // --- attention block ---
        ln_kernel<<<TOK / 8, 256>>>(out, ln1_g + (size_t)l * CDIM, ln1_b + (size_t)l * CDIM, xn);
        hgemm_kernel<3, __half><<<dim3(3 * CDIM / 128, TOK / 128), 256, GEMM_SMEM_BYTES>>>(
            xn, wq + (size_t)l * CDIM * 3 * CDIM, qkv_b + (size_t)l * 3 * CDIM,
            nullptr, qkv, TOK, 3 * CDIM, CDIM);
        attn_mma_kernel<<<dim3(NSEQ / 64, BSZ * HEADS), 256, ATTN_SMEM_BYTES>>>(qkv, attn);
        hgemm_kernel<2, float><<<dim3(CDIM / 128, TOK / 128), 256, GEMM_SMEM_BYTES>>>(
            attn, wp + (size_t)l * CDIM * CDIM, proj_b + (size_t)l * CDIM,
            out, out, TOK, CDIM, CDIM);
        // --- MLP block ---
        ln_kernel<<<TOK / 8, 256>>>(out, ln2_g + (size_t)l * CDIM, ln2_b + (size_t)l * CDIM, xn);
        hgemm_kernel<1, __half><<<dim3(FFD / 128, TOK / 128), 256, GEMM_SMEM_BYTES>>>(
            xn, w1 + (size_t)l * CDIM * FFD, fc1_b + (size_t)l * FFD,
            nullptr, ff, TOK, FFD, CDIM);
        hgemm_kernel<2, float><<<dim3(CDIM / 128, TOK / 128), 256, GEMM_SMEM_BYTES>>>(
            ff, w2 + (size_t)l * FFD * CDIM, fc2_b + (size_t)l * CDIM,
            out, out, TOK, CDIM, FFD);
    }
}

// round 9
// speedup vs baseline: 7.3951x; 1.1460x over previous
#include <cuda_runtime.h>
#include <cuda_fp16.h>
#include <math.h>
#include <stdint.h>

#define TOK   4096          // B*N
#define BSZ   4
#define NSEQ  1024
#define CDIM  1024
#define HEADS 16
#define HDIM  64
#define FFD   4096
#define LAYERS 4
#define ATT_SCALE 0.125f    // 64^-0.5

// GEMM smem strides (halves)
#define LDH 72              // 64 halves + 8 pad -> 144 B row stride
#define GEMM_TILE_H (128 * LDH)                 // halves per (A or B) tile
#define STAGE_H (2 * GEMM_TILE_H)               // A + B per stage
#define GEMM_STAGES 3
#define GEMM_SMEM_BYTES (GEMM_STAGES * STAGE_H * 2)   // 110592 B

// attn smem: Q [64][72] + K [2 buf][128][72] halves
#define ATTN_Q_H (64 * LDH)
#define ATTN_K_H (2 * 128 * LDH)
#define ATTN_SMEM_BYTES ((ATTN_Q_H + ATTN_K_H) * 2)

// Scratch (device globals; no allocation allowed)
__device__ __half g_xn  [(size_t)TOK * CDIM];
__device__ __half g_qk  [(size_t)TOK * 2 * CDIM];   // [tok][Q(0..C) K(C..2C)]
__device__ __half g_attn[(size_t)TOK * CDIM];
__device__ __half g_ff  [(size_t)TOK * FFD];
__device__ int    g_flags[TOK / 128];               // per-128-token-tile nonzero flag
// fp16, TRANSPOSED weights: Wt[N][K]
__device__ __half g_wq[(size_t)LAYERS * CDIM * 3 * CDIM];
__device__ __half g_wp[(size_t)LAYERS * CDIM * CDIM];
__device__ __half g_w1[(size_t)LAYERS * CDIM * FFD];
__device__ __half g_w2[(size_t)LAYERS * FFD * CDIM];

// ---------------------------------------------------------------------------
__device__ __forceinline__ void cp_async16(uint32_t s, const void* g) {
    asm volatile("cp.async.cg.shared.global [%0], [%1], 16;" :: "r"(s), "l"(g));
}
__device__ __forceinline__ void cp_commit() {
    asm volatile("cp.async.commit_group;");
}
__device__ __forceinline__ void cp_wait0() {
    asm volatile("cp.async.wait_group 0;");
}
__device__ __forceinline__ void cp_wait1() {
    asm volatile("cp.async.wait_group 1;");
}
__device__ __forceinline__ void ldsm_x4(uint32_t& r0, uint32_t& r1, uint32_t& r2,
                                        uint32_t& r3, uint32_t addr) {
    asm volatile("ldmatrix.sync.aligned.m8n8.x4.shared.b16 {%0,%1,%2,%3}, [%4];"
                 : "=r"(r0), "=r"(r1), "=r"(r2), "=r"(r3) : "r"(addr));
}
__device__ __forceinline__ void mma_f16(float* c, const uint32_t* a, const uint32_t* b) {
    asm volatile(
        "mma.sync.aligned.m16n8k16.row.col.f32.f16.f16.f32 "
        "{%0,%1,%2,%3}, {%4,%5,%6,%7}, {%8,%9}, {%0,%1,%2,%3};"
        : "+f"(c[0]), "+f"(c[1]), "+f"(c[2]), "+f"(c[3])
        : "r"(a[0]), "r"(a[1]), "r"(a[2]), "r"(a[3]), "r"(b[0]), "r"(b[1]));
}

// ---------------------------------------------------------------------------
// weight prep: fp32 [K,N] -> half [N,K] (transpose + convert), per-layer via z
// ---------------------------------------------------------------------------
__global__ void prep_w_kernel(const float* __restrict__ src,
                              __half* __restrict__ dst, int K, int N) {
    __shared__ __half t[32][34];
    const size_t lo = (size_t)blockIdx.z * K * N;
    const int n0 = blockIdx.x * 32, k0 = blockIdx.y * 32;
    const int tx = threadIdx.x & 31, ty = threadIdx.x >> 5;   // 32x8
    #pragma unroll
    for (int i = 0; i < 4; i++) {
        int k = k0 + ty + i * 8;
        t[ty + i * 8][tx] = __float2half(src[lo + (size_t)k * N + n0 + tx]);
    }
    __syncthreads();
    #pragma unroll
    for (int i = 0; i < 4; i++) {
        int n = n0 + ty + i * 8;
        dst[lo + (size_t)n * K + k0 + tx] = t[tx][ty + i * 8];
    }
}

// ---------------------------------------------------------------------------
// out = x + pos (pos broadcast over batch), fp32
// ---------------------------------------------------------------------------
__global__ void add_pos_kernel(const float* __restrict__ x,
                               const float* __restrict__ pos,
                               float* __restrict__ out) {
    int i = blockIdx.x * blockDim.x + threadIdx.x;
    const float4 a = ((const float4*)x)[i];
    const float4 p = ((const float4*)pos)[i & ((NSEQ * CDIM / 4) - 1)];
    float4 o;
    o.x = a.x + p.x; o.y = a.y + p.y; o.z = a.z + p.z; o.w = a.w + p.w;
    ((float4*)out)[i] = o;
}

// ---------------------------------------------------------------------------
// LayerNorm: ONE WARP per row (8 rows / 256-thr block). fp32 in -> fp16 out.
// Block 0 also zeroes the attention-sparsity flags (consumed later in layer).
// ---------------------------------------------------------------------------
__global__ __launch_bounds__(256)
void ln_kernel(const float* __restrict__ in,
               const float* __restrict__ g,
               const float* __restrict__ b,
               __half* __restrict__ out,
               int* __restrict__ flags) {
    if (blockIdx.x == 0 && threadIdx.x < TOK / 128) flags[threadIdx.x] = 0;

    const int row  = blockIdx.x * 8 + (threadIdx.x >> 5);
    const int lane = threadIdx.x & 31;
    const float4* rp = (const float4*)(in + (size_t)row * CDIM);

    float4 xv[8];
    float s = 0.f, sq = 0.f;
    #pragma unroll
    for (int i = 0; i < 8; i++) {
        xv[i] = rp[i * 32 + lane];
        s  += xv[i].x + xv[i].y + xv[i].z + xv[i].w;
        sq += xv[i].x * xv[i].x + xv[i].y * xv[i].y
            + xv[i].z * xv[i].z + xv[i].w * xv[i].w;
    }
    #pragma unroll
    for (int o = 16; o > 0; o >>= 1) {
        s  += __shfl_xor_sync(0xffffffffu, s, o);
        sq += __shfl_xor_sync(0xffffffffu, sq, o);
    }
    const float mean = s * (1.0f / CDIM);
    const float var  = sq * (1.0f / CDIM) - mean * mean;
    const float rstd = rsqrtf(var + 1e-5f);

    const float4* gp = (const float4*)g;
    const float4* bp = (const float4*)b;
    uint2* op = (uint2*)(out + (size_t)row * CDIM);
    #pragma unroll
    for (int i = 0; i < 8; i++) {
        const float4 gg = gp[i * 32 + lane];
        const float4 bb = bp[i * 32 + lane];
        __half2 h0 = __floats2half2_rn((xv[i].x - mean) * rstd * gg.x + bb.x,
                                       (xv[i].y - mean) * rstd * gg.y + bb.y);
        __half2 h1 = __floats2half2_rn((xv[i].z - mean) * rstd * gg.z + bb.z,
                                       (xv[i].w - mean) * rstd * gg.w + bb.w);
        uint2 o;
        o.x = *(uint32_t*)&h0;
        o.y = *(uint32_t*)&h1;
        op[i * 32 + lane] = o;
    }
}

// ---------------------------------------------------------------------------
// FP16 tensor-core GEMM: C = A[M,K] @ Wt[N,K]^T + bias
// 128x128 CTA tile, BK=64, 256 threads, 3-stage cp.async, ldmatrix A+B.
// ACT 1: gelu (half out), 2: +residual (fp32 out, optional tile-skip via
//        flags: flag==0 means A-tile is exactly zero), 3: plain (half out)
// ---------------------------------------------------------------------------
template <int ACT, typename OUT_T>
__global__ __launch_bounds__(256, 2)
void hgemm_kernel(const __half* __restrict__ A,
                  const __half* __restrict__ Wt,
                  const float* __restrict__ bias,
                  const float* __restrict__ res,
                  OUT_T* __restrict__ C,
                  int M, int N, int K,
                  const int* __restrict__ flags) {
    extern __shared__ __half smh[];

    const int tid  = threadIdx.x;
    const int lane = tid & 31;
    const int warp = tid >> 5;
    const int wm = warp >> 2;
    const int wn = warp & 3;
    const int bm = blockIdx.y * 128;
    const int bn = blockIdx.x * 128;

    float acc[4][4][4];
    #pragma unroll
    for (int i = 0; i < 4; i++)
        #pragma unroll
        for (int j = 0; j < 4; j++)
            #pragma unroll
            for (int t = 0; t < 4; t++) acc[i][j][t] = 0.f;

    const bool skip = (ACT == 2) && flags && (flags[blockIdx.y] == 0);

    if (!skip) {
        auto load_tile = [&](int kt, int st) {
            const __half* Ag = A  + (size_t)bm * K + kt * 64;
            const __half* Bg = Wt + (size_t)bn * K + kt * 64;
            __half* as = smh + st * STAGE_H;
            __half* bs = as + GEMM_TILE_H;
            #pragma unroll
            for (int i = 0; i < 4; i++) {
                int c = tid + i * 256;
                int r = c >> 3, seg = (c & 7) * 8;
                cp_async16((uint32_t)__cvta_generic_to_shared(as + r * LDH + seg),
                           Ag + (size_t)r * K + seg);
                cp_async16((uint32_t)__cvta_generic_to_shared(bs + r * LDH + seg),
                           Bg + (size_t)r * K + seg);
            }
        };

        const int KT = K / 64;
        load_tile(0, 0);
        cp_commit();
        load_tile(1, 1);
        cp_commit();

        const int a_row  = wm * 64 + (lane & 15);
        const int a_koff = (lane >> 4) * 8;
        const int b_g = lane >> 3;
        const int b_r = lane & 7;

        for (int kt = 0; kt < KT; kt++) {
            if (kt + 1 < KT) cp_wait1(); else cp_wait0();
            __syncthreads();
            if (kt + 2 < KT) { load_tile(kt + 2, (kt + 2) % GEMM_STAGES); cp_commit(); }

            const __half* as = smh + (kt % GEMM_STAGES) * STAGE_H;
            const __half* bs = as + GEMM_TILE_H;
            #pragma unroll
            for (int ks = 0; ks < 4; ks++) {
                uint32_t a[4][4];
                #pragma unroll
                for (int mt = 0; mt < 4; mt++) {
                    uint32_t addr = (uint32_t)__cvta_generic_to_shared(
                        as + (a_row + mt * 16) * LDH + ks * 16 + a_koff);
                    ldsm_x4(a[mt][0], a[mt][1], a[mt][2], a[mt][3], addr);
                }
                uint32_t b[4][2];
                #pragma unroll
                for (int c = 0; c < 2; c++) {
                    int row = wn * 32 + (2 * c + (b_g >> 1)) * 8 + b_r;
                    int col = ks * 16 + (b_g & 1) * 8;
                    uint32_t addr = (uint32_t)__cvta_generic_to_shared(
                        bs + row * LDH + col);
                    ldsm_x4(b[2 * c][0], b[2 * c][1], b[2 * c + 1][0], b[2 * c + 1][1], addr);
                }
                #pragma unroll
                for (int mt = 0; mt < 4; mt++)
                    #pragma unroll
                    for (int nt = 0; nt < 4; nt++)
                        mma_f16(acc[mt][nt], a[mt], b[nt]);
            }
        }
    }

    // Epilogue
    const int e_row = bm + wm * 64 + (lane >> 2);
    const int e_col = bn + wn * 32 + (lane & 3) * 2;
    #pragma unroll
    for (int mt = 0; mt < 4; mt++) {
        #pragma unroll
        for (int nt = 0; nt < 4; nt++) {
            const int col = e_col + nt * 8;
            const float bz0 = bias[col], bz1 = bias[col + 1];
            #pragma unroll
            for (int half_i = 0; half_i < 2; half_i++) {
                const int row = e_row + mt * 16 + half_i * 8;
                float v0 = acc[mt][nt][half_i * 2 + 0] + bz0;
                float v1 = acc[mt][nt][half_i * 2 + 1] + bz1;
                if (ACT == 1) {
                    v0 = 0.5f * v0 * (1.0f + erff(v0 * 0.70710678118654752f));
                    v1 = 0.5f * v1 * (1.0f + erff(v1 * 0.70710678118654752f));
                }
                if (ACT == 2) {
                    const float2 r2 = *(const float2*)(res + (size_t)row * N + col);
                    v0 += r2.x; v1 += r2.y;
                    float2 o; o.x = v0; o.y = v1;
                    *(float2*)((float*)C + (size_t)row * N + col) = o;
                } else {
                    __half2 h = __floats2half2_rn(v0, v1);
                    *(uint32_t*)((__half*)C + (size_t)row * N + col) = *(uint32_t*)&h;
                }
            }
        }
    }
}

// ---------------------------------------------------------------------------
// FP16 tensor-core attention with hard threshold.
//   out_row = (1/Z > 0.5) ? (xn[j*] @ Wv + bv)/Z : 0   (V computed on demand)
// qk layout: [tok][2*CDIM]: Q at 0, K at CDIM. Sets per-M-tile nonzero flags.
// ---------------------------------------------------------------------------
__global__ __launch_bounds__(256, 2)
void attn_mma_kernel(const __half* __restrict__ qk,
                     const __half* __restrict__ xn,
                     const __half* __restrict__ wt,     // full qkv Wt[3C][C]
                     const float* __restrict__ qkv_b,
                     __half* __restrict__ out,
                     int* __restrict__ flags) {
    extern __shared__ __half smh[];
    __half* Qs = smh;                 // [64][LDH]
    __half* Ks = smh + ATTN_Q_H;      // [2 buf][128][LDH]

    __shared__ float part_m[64][4];
    __shared__ float part_z[64][4];
    __shared__ int   part_j[64][4];
    __shared__ float rscale[64];
    __shared__ int   rjmax[64];
    __shared__ int   s_any;

    const int bh = blockIdx.y;
    const int b  = bh >> 4;
    const int h  = bh & 15;
    const int r0 = blockIdx.x * 64;
    const int tid = threadIdx.x, lane = tid & 31, warp = tid >> 5;
    const int wm = warp >> 2, wn = warp & 3;

    if (tid == 0) s_any = 0;

    // load Q tile [64][64]: 512 16B chunks
    #pragma unroll
    for (int i = 0; i < 2; i++) {
        int c = tid + i * 256;
        int r = c >> 3, seg = (c & 7) * 8;
        const __half* src = qk + (size_t)(b * NSEQ + r0 + r) * 2 * CDIM
                            + h * HDIM + seg;
        cp_async16((uint32_t)__cvta_generic_to_shared(Qs + r * LDH + seg), src);
    }

    auto load_k = [&](int c0, int buf) {
        __half* base = Ks + buf * (128 * LDH);
        #pragma unroll
        for (int i = 0; i < 4; i++) {
            int c = tid + i * 256;
            int r = c >> 3, seg = (c & 7) * 8;
            const __half* src = qk + (size_t)(b * NSEQ + c0 + r) * 2 * CDIM
                                + CDIM + h * HDIM + seg;
            cp_async16((uint32_t)__cvta_generic_to_shared(base + r * LDH + seg), src);
        }
    };

    cp_commit();                 // Q group
    load_k(0, 0);
    cp_commit();

    float m_[4], Z_[4];
    int j_[4];
    #pragma unroll
    for (int i = 0; i < 4; i++) { m_[i] = -1e30f; Z_[i] = 0.f; j_[i] = 0; }

    const int b_g = lane >> 3;
    const int b_r = lane & 7;

    for (int kc = 0; kc < 8; kc++) {
        const int buf = kc & 1;
        cp_wait0();
        __syncthreads();
        if (kc < 7) { load_k((kc + 1) * 128, buf ^ 1); cp_commit(); }

        float acc[2][4][4];
        #pragma unroll
        for (int i = 0; i < 2; i++)
            #pragma unroll
            for (int j = 0; j < 4; j++)
                #pragma unroll
                for (int t = 0; t < 4; t++) acc[i][j][t] = 0.f;

        const __half* kb = Ks + buf * (128 * LDH);
        #pragma unroll
        for (int ks = 0; ks < 4; ks++) {
            uint32_t a[2][4];
            #pragma unroll
            for (int mt = 0; mt < 2; mt++) {
                uint32_t addr = (uint32_t)__cvta_generic_to_shared(
                    Qs + (wm * 32 + mt * 16 + (lane & 15)) * LDH
                       + ks * 16 + (lane >> 4) * 8);
                ldsm_x4(a[mt][0], a[mt][1], a[mt][2], a[mt][3], addr);
            }
            uint32_t bfr[4][2];
            #pragma unroll
            for (int c = 0; c < 2; c++) {
                int row = wn * 32 + (2 * c + (b_g >> 1)) * 8 + b_r;
                int col = ks * 16 + (b_g & 1) * 8;
                uint32_t addr = (uint32_t)__cvta_generic_to_shared(
                    kb + row * LDH + col);
                ldsm_x4(bfr[2 * c][0], bfr[2 * c][1], bfr[2 * c + 1][0], bfr[2 * c + 1][1], addr);
            }
            #pragma unroll
            for (int mt = 0; mt < 2; mt++)
                #pragma unroll
                for (int nt = 0; nt < 4; nt++)
                    mma_f16(acc[mt][nt], a[mt], bfr[nt]);
        }

        // online (max, argmax, Z) update on fragments
        #pragma unroll
        for (int mt = 0; mt < 2; mt++) {
            #pragma unroll
            for (int half_i = 0; half_i < 2; half_i++) {
                const int si = mt * 2 + half_i;
                const int bcol = kc * 128 + wn * 32 + (lane & 3) * 2;
                float v[8];
                #pragma unroll
                for (int nt = 0; nt < 4; nt++) {
                    v[nt * 2 + 0] = acc[mt][nt][half_i * 2 + 0] * ATT_SCALE;
                    v[nt * 2 + 1] = acc[mt][nt][half_i * 2 + 1] * ATT_SCALE;
                }
                float cmax = v[0]; int cj = bcol;
                #pragma unroll
                for (int q = 1; q < 8; q++) {
                    int col = bcol + (q >> 1) * 8 + (q & 1);
                    if (v[q] > cmax) { cmax = v[q]; cj = col; }
                }
                if (cmax > m_[si]) {
                    Z_[si] *= __expf(m_[si] - cmax);
                    m_[si] = cmax;
                    j_[si] = cj;
                }
                float e = 0.f;
                #pragma unroll
                for (int q = 0; q < 8; q++) e += __expf(v[q] - m_[si]);
                Z_[si] += e;
            }
        }
    }

    // quad (lane&3) reduce, then cross-warp (wn) reduce via smem
    #pragma unroll
    for (int si = 0; si < 4; si++) {
        float mm = m_[si], zz = Z_[si];
        int jj = j_[si];
        #pragma unroll
        for (int o = 1; o <= 2; o <<= 1) {
            float om = __shfl_xor_sync(0xffffffffu, mm, o);
            float oz = __shfl_xor_sync(0xffffffffu, zz, o);
            int   oj = __shfl_xor_sync(0xffffffffu, jj, o);
            if (om > mm) { zz = zz * __expf(mm - om) + oz; mm = om; jj = oj; }
            else         { zz = zz + oz * __expf(om - mm); }
        }
        if ((lane & 3) == 0) {
            int row = wm * 32 + (si >> 1) * 16 + (si & 1) * 8 + (lane >> 2);
            part_m[row][wn] = mm;
            part_z[row][wn] = zz;
            part_j[row][wn] = jj;
        }
    }
    __syncthreads();

    if (tid < 64) {
        float mm = part_m[tid][0], zz = part_z[tid][0];
        int jj = part_j[tid][0];
        #pragma unroll
        for (int t = 1; t < 4; t++) {
            float om = part_m[tid][t], oz = part_z[tid][t];
            int   oj = part_j[tid][t];
            if (om > mm) { zz = zz * __expf(mm - om) + oz; mm = om; jj = oj; }
            else         { zz = zz + oz * __expf(om - mm); }
        }
        const float amax = 1.0f / zz;
        const float sc = (amax > 0.5f) ? amax : 0.0f;
        rscale[tid] = sc;
        rjmax[tid]  = jj;
        if (sc != 0.0f) s_any = 1;
    }
    __syncthreads();

    if (tid == 0 && s_any) {
        atomicOr(&flags[(b * NSEQ + r0) >> 7], 1);
    }

    // gather: out_row = sc * (xn[j*] @ Wv + bv); zero otherwise
    const int r  = tid >> 2;
    const int d0 = (tid & 3) * 16;
    const float sc = rscale[r];
    const int jj = rjmax[r];
    __half* orow = out + (size_t)(b * NSEQ + r0 + r) * CDIM + h * HDIM;
    if (sc != 0.0f) {
        // on-demand V: rare path (requires a softmax prob > 0.5)
        const __half* xrow = xn + (size_t)(b * NSEQ + jj) * CDIM;
        #pragma unroll 1
        for (int d = d0; d < d0 + 16; d++) {
            const __half* wrow = wt + (size_t)(2 * CDIM + h * HDIM + d) * CDIM;
            float accv = 0.f;
            const __half2* xp = (const __half2*)xrow;
            const __half2* wp = (const __half2*)wrow;
            #pragma unroll 8
            for (int k2 = 0; k2 < CDIM / 2; k2++) {
                float2 xf = __half22float2(xp[k2]);
                float2 wf = __half22float2(wp[k2]);
                accv += xf.x * wf.x + xf.y * wf.y;
            }
            accv += qkv_b[2 * CDIM + h * HDIM + d];
            orow[d] = __float2half(accv * sc);
        }
    } else {
        #pragma unroll
        for (int d = d0; d < d0 + 16; d += 4) {
            uint2 o; o.x = 0u; o.y = 0u;
            *(uint2*)(orow + d) = o;
        }
    }
}

// ---------------------------------------------------------------------------
extern "C" void kernel_launch(void* const* d_in, const int* in_sizes, int n_in,
                              void* d_out, int out_size) {
    (void)in_sizes; (void)n_in; (void)out_size;
    const float* x      = (const float*)d_in[0];
    const float* pos    = (const float*)d_in[1];
    const float* qkv_w  = (const float*)d_in[2];
    const float* qkv_b  = (const float*)d_in[3];
    const float* proj_w = (const float*)d_in[4];
    const float* proj_b = (const float*)d_in[5];
    const float* ln1_g  = (const float*)d_in[6];
    const float* ln1_b  = (const float*)d_in[7];
    const float* ln2_g  = (const float*)d_in[8];
    const float* ln2_b  = (const float*)d_in[9];
    const float* fc1_w  = (const float*)d_in[10];
    const float* fc1_b  = (const float*)d_in[11];
    const float* fc2_w  = (const float*)d_in[12];
    const float* fc2_b  = (const float*)d_in[13];
    float* out = (float*)d_out;

    __half *xn, *qk, *attn, *ff, *wq, *wp, *w1, *w2;
    int* flags;
    cudaGetSymbolAddress((void**)&xn,   g_xn);
    cudaGetSymbolAddress((void**)&qk,   g_qk);
    cudaGetSymbolAddress((void**)&attn, g_attn);
    cudaGetSymbolAddress((void**)&ff,   g_ff);
    cudaGetSymbolAddress((void**)&wq,   g_wq);
    cudaGetSymbolAddress((void**)&wp,   g_wp);
    cudaGetSymbolAddress((void**)&w1,   g_w1);
    cudaGetSymbolAddress((void**)&w2,   g_w2);
    cudaGetSymbolAddress((void**)&flags, g_flags);

    cudaFuncSetAttribute(hgemm_kernel<1, __half>,
                         cudaFuncAttributeMaxDynamicSharedMemorySize, GEMM_SMEM_BYTES);
    cudaFuncSetAttribute(hgemm_kernel<2, float>,
                         cudaFuncAttributeMaxDynamicSharedMemorySize, GEMM_SMEM_BYTES);
    cudaFuncSetAttribute(hgemm_kernel<3, __half>,
                         cudaFuncAttributeMaxDynamicSharedMemorySize, GEMM_SMEM_BYTES);
    cudaFuncSetAttribute(attn_mma_kernel,
                         cudaFuncAttributeMaxDynamicSharedMemorySize, ATTN_SMEM_BYTES);

    // weight prep: fp16 convert + transpose [K,N] -> [N,K] (once per launch)
    prep_w_kernel<<<dim3(3 * CDIM / 32, CDIM / 32, LAYERS), 256>>>(qkv_w,  wq, CDIM, 3 * CDIM);
    prep_w_kernel<<<dim3(CDIM / 32,     CDIM / 32, LAYERS), 256>>>(proj_w, wp, CDIM, CDIM);
    prep_w_kernel<<<dim3(FFD / 32,      CDIM / 32, LAYERS), 256>>>(fc1_w,  w1, CDIM, FFD);
    prep_w_kernel<<<dim3(CDIM / 32,     FFD / 32,  LAYERS), 256>>>(fc2_w,  w2, FFD, CDIM);

    add_pos_kernel<<<(size_t)TOK * CDIM / 4 / 256, 256>>>(x, pos, out);

    for (int l = 0; l < LAYERS; l++) {
        const __half* wql = wq + (size_t)l * CDIM * 3 * CDIM;
        // --- attention block ---
        ln_kernel<<<TOK / 8, 256>>>(out, ln1_g + (size_t)l * CDIM,
                                    ln1_b + (size_t)l * CDIM, xn, flags);
        // Q,K only (Wt rows 0..2C): N = 2048
        hgemm_kernel<3, __half><<<dim3(2 * CDIM / 128, TOK / 128), 256, GEMM_SMEM_BYTES>>>(
            xn, wql, qkv_b + (size_t)l * 3 * CDIM,
            nullptr, qk, TOK, 2 * CDIM, CDIM, nullptr);
        attn_mma_kernel<<<dim3(NSEQ / 64, BSZ * HEADS), 256, ATTN_SMEM_BYTES>>>(
            qk, xn, wql, qkv_b + (size_t)l * 3 * CDIM, attn, flags);
        hgemm_kernel<2, float><<<dim3(CDIM / 128, TOK / 128), 256, GEMM_SMEM_BYTES>>>(
            attn, wp + (size_t)l * CDIM * CDIM, proj_b + (size_t)l * CDIM,
            out, out, TOK, CDIM, CDIM, flags);
        // --- MLP block ---
        ln_kernel<<<TOK / 8, 256>>>(out, ln2_g + (size_t)l * CDIM,
                                    ln2_b + (size_t)l * CDIM, xn, flags);
        hgemm_kernel<1, __half><<<dim3(FFD / 128, TOK / 128), 256, GEMM_SMEM_BYTES>>>(
            xn, w1 + (size_t)l * CDIM * FFD, fc1_b + (size_t)l * FFD,
            nullptr, ff, TOK, FFD, CDIM, nullptr);
        hgemm_kernel<2, float><<<dim3(CDIM / 128, TOK / 128), 256, GEMM_SMEM_BYTES>>>(
            ff, w2 + (size_t)l * FFD * CDIM, fc2_b + (size_t)l * CDIM,
            out, out, TOK, CDIM, FFD, nullptr);
    }
}

// round 10
// speedup vs baseline: 7.8084x; 1.0559x over previous
#include <cuda_runtime.h>
#include <cuda_fp16.h>
#include <math.h>
#include <stdint.h>

#define TOK   4096          // B*N
#define BSZ   4
#define NSEQ  1024
#define CDIM  1024
#define HEADS 16
#define HDIM  64
#define FFD   4096
#define LAYERS 4
#define ATT_SCALE 0.125f    // 64^-0.5

// GEMM smem strides (halves)
#define LDH 72              // 64 halves + 8 pad -> 144 B row stride
#define GEMM_TILE_H (128 * LDH)                 // halves per (A or B) tile
#define STAGE_H (2 * GEMM_TILE_H)               // A + B per stage
#define GEMM_STAGES 3
#define GEMM_SMEM_BYTES (GEMM_STAGES * STAGE_H * 2)   // 110592 B

// attn smem: Q [64][72] + K [2 buf][128][72] halves
#define ATTN_Q_H (64 * LDH)
#define ATTN_K_H (2 * 128 * LDH)
#define ATTN_SMEM_BYTES ((ATTN_Q_H + ATTN_K_H) * 2)

// Scratch (device globals; no allocation allowed)
__device__ __half g_xn  [(size_t)TOK * CDIM];
__device__ __half g_qk  [(size_t)TOK * 2 * CDIM];   // [tok][Q(0..C) K(C..2C)]
__device__ __half g_attn[(size_t)TOK * CDIM];
__device__ __half g_ff  [(size_t)TOK * FFD];
__device__ int    g_flags[TOK / 128];               // per-128-token-tile nonzero flag
// fp16, TRANSPOSED weights: Wt[N][K]
__device__ __half g_wq[(size_t)LAYERS * CDIM * 3 * CDIM];
__device__ __half g_wp[(size_t)LAYERS * CDIM * CDIM];
__device__ __half g_w1[(size_t)LAYERS * CDIM * FFD];
__device__ __half g_w2[(size_t)LAYERS * FFD * CDIM];

// ---------------------------------------------------------------------------
__device__ __forceinline__ void cp_async16(uint32_t s, const void* g) {
    asm volatile("cp.async.cg.shared.global [%0], [%1], 16;" :: "r"(s), "l"(g));
}
__device__ __forceinline__ void cp_commit() {
    asm volatile("cp.async.commit_group;");
}
__device__ __forceinline__ void cp_wait0() {
    asm volatile("cp.async.wait_group 0;");
}
__device__ __forceinline__ void cp_wait1() {
    asm volatile("cp.async.wait_group 1;");
}
__device__ __forceinline__ void ldsm_x4(uint32_t& r0, uint32_t& r1, uint32_t& r2,
                                        uint32_t& r3, uint32_t addr) {
    asm volatile("ldmatrix.sync.aligned.m8n8.x4.shared.b16 {%0,%1,%2,%3}, [%4];"
                 : "=r"(r0), "=r"(r1), "=r"(r2), "=r"(r3) : "r"(addr));
}
__device__ __forceinline__ void mma_f16(float* c, const uint32_t* a, const uint32_t* b) {
    asm volatile(
        "mma.sync.aligned.m16n8k16.row.col.f32.f16.f16.f32 "
        "{%0,%1,%2,%3}, {%4,%5,%6,%7}, {%8,%9}, {%0,%1,%2,%3};"
        : "+f"(c[0]), "+f"(c[1]), "+f"(c[2]), "+f"(c[3])
        : "r"(a[0]), "r"(a[1]), "r"(a[2]), "r"(a[3]), "r"(b[0]), "r"(b[1]));
}
__device__ __forceinline__ float tanh_fast(float x) {
    float y;
    asm("tanh.approx.f32 %0, %1;" : "=f"(y) : "f"(x));
    return y;
}
__device__ __forceinline__ float gelu_fast(float v) {
    // tanh-form gelu with HW tanh; |delta vs erf-form| <~4e-4 abs
    const float c0 = 0.7978845608028654f, c1 = 0.044715f;
    return 0.5f * v * (1.0f + tanh_fast(c0 * (v + c1 * v * v * v)));
}

// ---------------------------------------------------------------------------
// weight prep: fp32 [K,N] -> half [N,K] (transpose + convert), per-layer via z
// 64x64 tiles; coalesced 128B reads AND writes.
// ---------------------------------------------------------------------------
__global__ __launch_bounds__(256)
void prep_w_kernel(const float* __restrict__ src,
                   __half* __restrict__ dst, int K, int N) {
    __shared__ __half t[64][65];
    const size_t lo = (size_t)blockIdx.z * K * N;
    const int n0 = blockIdx.x * 64, k0 = blockIdx.y * 64;
    const int tx = threadIdx.x & 15, ty = threadIdx.x >> 4;   // 16x16

    #pragma unroll
    for (int ii = 0; ii < 4; ii++) {
        const int k = k0 + ty + ii * 16;
        const float4 v = *(const float4*)&src[lo + (size_t)k * N + n0 + tx * 4];
        t[tx * 4 + 0][ty + ii * 16] = __float2half(v.x);
        t[tx * 4 + 1][ty + ii * 16] = __float2half(v.y);
        t[tx * 4 + 2][ty + ii * 16] = __float2half(v.z);
        t[tx * 4 + 3][ty + ii * 16] = __float2half(v.w);
    }
    __syncthreads();

    const int w = threadIdx.x >> 5, l = threadIdx.x & 31;
    #pragma unroll
    for (int r = 0; r < 8; r++) {
        const int n = w * 8 + r;
        __half2 h = __halves2half2(t[n][2 * l], t[n][2 * l + 1]);
        *(uint32_t*)&dst[lo + (size_t)(n0 + n) * K + k0 + 2 * l] = *(uint32_t*)&h;
    }
}

// ---------------------------------------------------------------------------
// out = x + pos (pos broadcast over batch), fp32
// ---------------------------------------------------------------------------
__global__ void add_pos_kernel(const float* __restrict__ x,
                               const float* __restrict__ pos,
                               float* __restrict__ out) {
    int i = blockIdx.x * blockDim.x + threadIdx.x;
    const float4 a = ((const float4*)x)[i];
    const float4 p = ((const float4*)pos)[i & ((NSEQ * CDIM / 4) - 1)];
    float4 o;
    o.x = a.x + p.x; o.y = a.y + p.y; o.z = a.z + p.z; o.w = a.w + p.w;
    ((float4*)out)[i] = o;
}

// ---------------------------------------------------------------------------
// LayerNorm: ONE WARP per row (8 rows / 256-thr block). fp32 in -> fp16 out.
// Block 0 also zeroes the attention-sparsity flags (consumed later in layer).
// ---------------------------------------------------------------------------
__global__ __launch_bounds__(256)
void ln_kernel(const float* __restrict__ in,
               const float* __restrict__ g,
               const float* __restrict__ b,
               __half* __restrict__ out,
               int* __restrict__ flags) {
    if (blockIdx.x == 0 && threadIdx.x < TOK / 128) flags[threadIdx.x] = 0;

    const int row  = blockIdx.x * 8 + (threadIdx.x >> 5);
    const int lane = threadIdx.x & 31;
    const float4* rp = (const float4*)(in + (size_t)row * CDIM);

    float4 xv[8];
    float s = 0.f, sq = 0.f;
    #pragma unroll
    for (int i = 0; i < 8; i++) {
        xv[i] = rp[i * 32 + lane];
        s  += xv[i].x + xv[i].y + xv[i].z + xv[i].w;
        sq += xv[i].x * xv[i].x + xv[i].y * xv[i].y
            + xv[i].z * xv[i].z + xv[i].w * xv[i].w;
    }
    #pragma unroll
    for (int o = 16; o > 0; o >>= 1) {
        s  += __shfl_xor_sync(0xffffffffu, s, o);
        sq += __shfl_xor_sync(0xffffffffu, sq, o);
    }
    const float mean = s * (1.0f / CDIM);
    const float var  = sq * (1.0f / CDIM) - mean * mean;
    const float rstd = rsqrtf(var + 1e-5f);

    const float4* gp = (const float4*)g;
    const float4* bp = (const float4*)b;
    uint2* op = (uint2*)(out + (size_t)row * CDIM);
    #pragma unroll
    for (int i = 0; i < 8; i++) {
        const float4 gg = gp[i * 32 + lane];
        const float4 bb = bp[i * 32 + lane];
        __half2 h0 = __floats2half2_rn((xv[i].x - mean) * rstd * gg.x + bb.x,
                                       (xv[i].y - mean) * rstd * gg.y + bb.y);
        __half2 h1 = __floats2half2_rn((xv[i].z - mean) * rstd * gg.z + bb.z,
                                       (xv[i].w - mean) * rstd * gg.w + bb.w);
        uint2 o;
        o.x = *(uint32_t*)&h0;
        o.y = *(uint32_t*)&h1;
        op[i * 32 + lane] = o;
    }
}

// ---------------------------------------------------------------------------
// FP16 tensor-core GEMM: C = A[M,K] @ Wt[N,K]^T + bias
// 128x128 CTA tile, BK=64, 256 threads, 3-stage cp.async, ldmatrix A+B.
// ACT 1: gelu (half out), 2: +residual (fp32 out, optional tile-skip via
//        flags: flag==0 means A-tile is exactly zero), 3: plain (half out)
// ---------------------------------------------------------------------------
template <int ACT, typename OUT_T>
__global__ __launch_bounds__(256, 2)
void hgemm_kernel(const __half* __restrict__ A,
                  const __half* __restrict__ Wt,
                  const float* __restrict__ bias,
                  const float* __restrict__ res,
                  OUT_T* __restrict__ C,
                  int M, int N, int K,
                  const int* __restrict__ flags) {
    extern __shared__ __half smh[];

    const int tid  = threadIdx.x;
    const int lane = tid & 31;
    const int warp = tid >> 5;
    const int wm = warp >> 2;
    const int wn = warp & 3;
    const int bm = blockIdx.y * 128;
    const int bn = blockIdx.x * 128;

    float acc[4][4][4];
    #pragma unroll
    for (int i = 0; i < 4; i++)
        #pragma unroll
        for (int j = 0; j < 4; j++)
            #pragma unroll
            for (int t = 0; t < 4; t++) acc[i][j][t] = 0.f;

    const bool skip = (ACT == 2) && flags && (flags[blockIdx.y] == 0);

    if (!skip) {
        auto load_tile = [&](int kt, int st) {
            const __half* Ag = A  + (size_t)bm * K + kt * 64;
            const __half* Bg = Wt + (size_t)bn * K + kt * 64;
            __half* as = smh + st * STAGE_H;
            __half* bs = as + GEMM_TILE_H;
            #pragma unroll
            for (int i = 0; i < 4; i++) {
                int c = tid + i * 256;
                int r = c >> 3, seg = (c & 7) * 8;
                cp_async16((uint32_t)__cvta_generic_to_shared(as + r * LDH + seg),
                           Ag + (size_t)r * K + seg);
                cp_async16((uint32_t)__cvta_generic_to_shared(bs + r * LDH + seg),
                           Bg + (size_t)r * K + seg);
            }
        };

        const int KT = K / 64;
        load_tile(0, 0);
        cp_commit();
        load_tile(1, 1);
        cp_commit();

        const int a_row  = wm * 64 + (lane & 15);
        const int a_koff = (lane >> 4) * 8;
        const int b_g = lane >> 3;
        const int b_r = lane & 7;

        for (int kt = 0; kt < KT; kt++) {
            if (kt + 1 < KT) cp_wait1(); else cp_wait0();
            __syncthreads();
            if (kt + 2 < KT) { load_tile(kt + 2, (kt + 2) % GEMM_STAGES); cp_commit(); }

            const __half* as = smh + (kt % GEMM_STAGES) * STAGE_H;
            const __half* bs = as + GEMM_TILE_H;
            #pragma unroll
            for (int ks = 0; ks < 4; ks++) {
                uint32_t a[4][4];
                #pragma unroll
                for (int mt = 0; mt < 4; mt++) {
                    uint32_t addr = (uint32_t)__cvta_generic_to_shared(
                        as + (a_row + mt * 16) * LDH + ks * 16 + a_koff);
                    ldsm_x4(a[mt][0], a[mt][1], a[mt][2], a[mt][3], addr);
                }
                uint32_t b[4][2];
                #pragma unroll
                for (int c = 0; c < 2; c++) {
                    int row = wn * 32 + (2 * c + (b_g >> 1)) * 8 + b_r;
                    int col = ks * 16 + (b_g & 1) * 8;
                    uint32_t addr = (uint32_t)__cvta_generic_to_shared(
                        bs + row * LDH + col);
                    ldsm_x4(b[2 * c][0], b[2 * c][1], b[2 * c + 1][0], b[2 * c + 1][1], addr);
                }
                #pragma unroll
                for (int mt = 0; mt < 4; mt++)
                    #pragma unroll
                    for (int nt = 0; nt < 4; nt++)
                        mma_f16(acc[mt][nt], a[mt], b[nt]);
            }
        }
    }

    // Epilogue
    const int e_row = bm + wm * 64 + (lane >> 2);
    const int e_col = bn + wn * 32 + (lane & 3) * 2;
    #pragma unroll
    for (int mt = 0; mt < 4; mt++) {
        #pragma unroll
        for (int nt = 0; nt < 4; nt++) {
            const int col = e_col + nt * 8;
            const float bz0 = bias[col], bz1 = bias[col + 1];
            #pragma unroll
            for (int half_i = 0; half_i < 2; half_i++) {
                const int row = e_row + mt * 16 + half_i * 8;
                float v0 = acc[mt][nt][half_i * 2 + 0] + bz0;
                float v1 = acc[mt][nt][half_i * 2 + 1] + bz1;
                if (ACT == 1) {
                    v0 = gelu_fast(v0);
                    v1 = gelu_fast(v1);
                }
                if (ACT == 2) {
                    const float2 r2 = *(const float2*)(res + (size_t)row * N + col);
                    v0 += r2.x; v1 += r2.y;
                    float2 o; o.x = v0; o.y = v1;
                    *(float2*)((float*)C + (size_t)row * N + col) = o;
                } else {
                    __half2 h = __floats2half2_rn(v0, v1);
                    *(uint32_t*)((__half*)C + (size_t)row * N + col) = *(uint32_t*)&h;
                }
            }
        }
    }
}

// ---------------------------------------------------------------------------
// FP16 tensor-core attention with hard threshold.
//   out_row = (1/Z > 0.5) ? (xn[j*] @ Wv + bv)/Z : 0   (V computed on demand)
// qk layout: [tok][2*CDIM]: Q at 0, K at CDIM. Sets per-M-tile nonzero flags.
// ---------------------------------------------------------------------------
__global__ __launch_bounds__(256, 3)
void attn_mma_kernel(const __half* __restrict__ qk,
                     const __half* __restrict__ xn,
                     const __half* __restrict__ wt,     // full qkv Wt[3C][C]
                     const float* __restrict__ qkv_b,
                     __half* __restrict__ out,
                     int* __restrict__ flags) {
    extern __shared__ __half smh[];
    __half* Qs = smh;                 // [64][LDH]
    __half* Ks = smh + ATTN_Q_H;      // [2 buf][128][LDH]

    __shared__ float part_m[64][4];
    __shared__ float part_z[64][4];
    __shared__ int   part_j[64][4];
    __shared__ float rscale[64];
    __shared__ int   rjmax[64];
    __shared__ int   s_any;

    const int bh = blockIdx.y;
    const int b  = bh >> 4;
    const int h  = bh & 15;
    const int r0 = blockIdx.x * 64;
    const int tid = threadIdx.x, lane = tid & 31, warp = tid >> 5;
    const int wm = warp >> 2, wn = warp & 3;

    if (tid == 0) s_any = 0;

    // load Q tile [64][64]: 512 16B chunks
    #pragma unroll
    for (int i = 0; i < 2; i++) {
        int c = tid + i * 256;
        int r = c >> 3, seg = (c & 7) * 8;
        const __half* src = qk + (size_t)(b * NSEQ + r0 + r) * 2 * CDIM
                            + h * HDIM + seg;
        cp_async16((uint32_t)__cvta_generic_to_shared(Qs + r * LDH + seg), src);
    }

    auto load_k = [&](int c0, int buf) {
        __half* base = Ks + buf * (128 * LDH);
        #pragma unroll
        for (int i = 0; i < 4; i++) {
            int c = tid + i * 256;
            int r = c >> 3, seg = (c & 7) * 8;
            const __half* src = qk + (size_t)(b * NSEQ + c0 + r) * 2 * CDIM
                                + CDIM + h * HDIM + seg;
            cp_async16((uint32_t)__cvta_generic_to_shared(base + r * LDH + seg), src);
        }
    };

    cp_commit();                 // Q group
    load_k(0, 0);
    cp_commit();

    float m_[4], Z_[4];
    int j_[4];
    #pragma unroll
    for (int i = 0; i < 4; i++) { m_[i] = -1e30f; Z_[i] = 0.f; j_[i] = 0; }

    const int b_g = lane >> 3;
    const int b_r = lane & 7;

    for (int kc = 0; kc < 8; kc++) {
        const int buf = kc & 1;
        cp_wait0();
        __syncthreads();
        if (kc < 7) { load_k((kc + 1) * 128, buf ^ 1); cp_commit(); }

        float acc[2][4][4];
        #pragma unroll
        for (int i = 0; i < 2; i++)
            #pragma unroll
            for (int j = 0; j < 4; j++)
                #pragma unroll
                for (int t = 0; t < 4; t++) acc[i][j][t] = 0.f;

        const __half* kb = Ks + buf * (128 * LDH);
        #pragma unroll
        for (int ks = 0; ks < 4; ks++) {
            uint32_t a[2][4];
            #pragma unroll
            for (int mt = 0; mt < 2; mt++) {
                uint32_t addr = (uint32_t)__cvta_generic_to_shared(
                    Qs + (wm * 32 + mt * 16 + (lane & 15)) * LDH
                       + ks * 16 + (lane >> 4) * 8);
                ldsm_x4(a[mt][0], a[mt][1], a[mt][2], a[mt][3], addr);
            }
            uint32_t bfr[4][2];
            #pragma unroll
            for (int c = 0; c < 2; c++) {
                int row = wn * 32 + (2 * c + (b_g >> 1)) * 8 + b_r;
                int col = ks * 16 + (b_g & 1) * 8;
                uint32_t addr = (uint32_t)__cvta_generic_to_shared(
                    kb + row * LDH + col);
                ldsm_x4(bfr[2 * c][0], bfr[2 * c][1], bfr[2 * c + 1][0], bfr[2 * c + 1][1], addr);
            }
            #pragma unroll
            for (int mt = 0; mt < 2; mt++)
                #pragma unroll
                for (int nt = 0; nt < 4; nt++)
                    mma_f16(acc[mt][nt], a[mt], bfr[nt]);
        }

        // online (max, argmax, Z) update on fragments
        #pragma unroll
        for (int mt = 0; mt < 2; mt++) {
            #pragma unroll
            for (int half_i = 0; half_i < 2; half_i++) {
                const int si = mt * 2 + half_i;
                const int bcol = kc * 128 + wn * 32 + (lane & 3) * 2;
                float v[8];
                #pragma unroll
                for (int nt = 0; nt < 4; nt++) {
                    v[nt * 2 + 0] = acc[mt][nt][half_i * 2 + 0] * ATT_SCALE;
                    v[nt * 2 + 1] = acc[mt][nt][half_i * 2 + 1] * ATT_SCALE;
                }
                float cmax = v[0]; int cj = bcol;
                #pragma unroll
                for (int q = 1; q < 8; q++) {
                    int col = bcol + (q >> 1) * 8 + (q & 1);
                    if (v[q] > cmax) { cmax = v[q]; cj = col; }
                }
                if (cmax > m_[si]) {
                    Z_[si] *= __expf(m_[si] - cmax);
                    m_[si] = cmax;
                    j_[si] = cj;
                }
                float e = 0.f;
                #pragma unroll
                for (int q = 0; q < 8; q++) e += __expf(v[q] - m_[si]);
                Z_[si] += e;
            }
        }
    }

    // quad (lane&3) reduce, then cross-warp (wn) reduce via smem
    #pragma unroll
    for (int si = 0; si < 4; si++) {
        float mm = m_[si], zz = Z_[si];
        int jj = j_[si];
        #pragma unroll
        for (int o = 1; o <= 2; o <<= 1) {
            float om = __shfl_xor_sync(0xffffffffu, mm, o);
            float oz = __shfl_xor_sync(0xffffffffu, zz, o);
            int   oj = __shfl_xor_sync(0xffffffffu, jj, o);
            if (om > mm) { zz = zz * __expf(mm - om) + oz; mm = om; jj = oj; }
            else         { zz = zz + oz * __expf(om - mm); }
        }
        if ((lane & 3) == 0) {
            int row = wm * 32 + (si >> 1) * 16 + (si & 1) * 8 + (lane >> 2);
            part_m[row][wn] = mm;
            part_z[row][wn] = zz;
            part_j[row][wn] = jj;
        }
    }
    __syncthreads();

    if (tid < 64) {
        float mm = part_m[tid][0], zz = part_z[tid][0];
        int jj = part_j[tid][0];
        #pragma unroll
        for (int t = 1; t < 4; t++) {
            float om = part_m[tid][t], oz = part_z[tid][t];
            int   oj = part_j[tid][t];
            if (om > mm) { zz = zz * __expf(mm - om) + oz; mm = om; jj = oj; }
            else         { zz = zz + oz * __expf(om - mm); }
        }
        const float amax = 1.0f / zz;
        const float sc = (amax > 0.5f) ? amax : 0.0f;
        rscale[tid] = sc;
        rjmax[tid]  = jj;
        if (sc != 0.0f) s_any = 1;
    }
    __syncthreads();

    if (tid == 0 && s_any) {
        atomicOr(&flags[(b * NSEQ + r0) >> 7], 1);
    }

    // gather: out_row = sc * (xn[j*] @ Wv + bv); zero otherwise
    const int r  = tid >> 2;
    const int d0 = (tid & 3) * 16;
    const float sc = rscale[r];
    const int jj = rjmax[r];
    __half* orow = out + (size_t)(b * NSEQ + r0 + r) * CDIM + h * HDIM;
    if (sc != 0.0f) {
        // on-demand V: rare path (requires a softmax prob > 0.5)
        const __half* xrow = xn + (size_t)(b * NSEQ + jj) * CDIM;
        #pragma unroll 1
        for (int d = d0; d < d0 + 16; d++) {
            const __half* wrow = wt + (size_t)(2 * CDIM + h * HDIM + d) * CDIM;
            float accv = 0.f;
            const __half2* xp = (const __half2*)xrow;
            const __half2* wp = (const __half2*)wrow;
            #pragma unroll 8
            for (int k2 = 0; k2 < CDIM / 2; k2++) {
                float2 xf = __half22float2(xp[k2]);
                float2 wf = __half22float2(wp[k2]);
                accv += xf.x * wf.x + xf.y * wf.y;
            }
            accv += qkv_b[2 * CDIM + h * HDIM + d];
            orow[d] = __float2half(accv * sc);
        }
    } else {
        #pragma unroll
        for (int d = d0; d < d0 + 16; d += 4) {
            uint2 o; o.x = 0u; o.y = 0u;
            *(uint2*)(orow + d) = o;
        }
    }
}

// ---------------------------------------------------------------------------
extern "C" void kernel_launch(void* const* d_in, const int* in_sizes, int n_in,
                              void* d_out, int out_size) {
    (void)in_sizes; (void)n_in; (void)out_size;
    const float* x      = (const float*)d_in[0];
    const float* pos    = (const float*)d_in[1];
    const float* qkv_w  = (const float*)d_in[2];
    const float* qkv_b  = (const float*)d_in[3];
    const float* proj_w = (const float*)d_in[4];
    const float* proj_b = (const float*)d_in[5];
    const float* ln1_g  = (const float*)d_in[6];
    const float* ln1_b  = (const float*)d_in[7];
    const float* ln2_g  = (const float*)d_in[8];
    const float* ln2_b  = (const float*)d_in[9];
    const float* fc1_w  = (const float*)d_in[10];
    const float* fc1_b  = (const float*)d_in[11];
    const float* fc2_w  = (const float*)d_in[12];
    const float* fc2_b  = (const float*)d_in[13];
    float* out = (float*)d_out;

    __half *xn, *qk, *attn, *ff, *wq, *wp, *w1, *w2;
    int* flags;
    cudaGetSymbolAddress((void**)&xn,   g_xn);
    cudaGetSymbolAddress((void**)&qk,   g_qk);
    cudaGetSymbolAddress((void**)&attn, g_attn);
    cudaGetSymbolAddress((void**)&ff,   g_ff);
    cudaGetSymbolAddress((void**)&wq,   g_wq);
    cudaGetSymbolAddress((void**)&wp,   g_wp);
    cudaGetSymbolAddress((void**)&w1,   g_w1);
    cudaGetSymbolAddress((void**)&w2,   g_w2);
    cudaGetSymbolAddress((void**)&flags, g_flags);

    cudaFuncSetAttribute(hgemm_kernel<1, __half>,
                         cudaFuncAttributeMaxDynamicSharedMemorySize, GEMM_SMEM_BYTES);
    cudaFuncSetAttribute(hgemm_kernel<2, float>,
                         cudaFuncAttributeMaxDynamicSharedMemorySize, GEMM_SMEM_BYTES);
    cudaFuncSetAttribute(hgemm_kernel<3, __half>,
                         cudaFuncAttributeMaxDynamicSharedMemorySize, GEMM_SMEM_BYTES);
    cudaFuncSetAttribute(attn_mma_kernel,
                         cudaFuncAttributeMaxDynamicSharedMemorySize, ATTN_SMEM_BYTES);

    // weight prep: fp16 convert + transpose [K,N] -> [N,K] (once per launch)
    prep_w_kernel<<<dim3(3 * CDIM / 64, CDIM / 64, LAYERS), 256>>>(qkv_w,  wq, CDIM, 3 * CDIM);
    prep_w_kernel<<<dim3(CDIM / 64,     CDIM / 64, LAYERS), 256>>>(proj_w, wp, CDIM, CDIM);
    prep_w_kernel<<<dim3(FFD / 64,      CDIM / 64, LAYERS), 256>>>(fc1_w,  w1, CDIM, FFD);
    prep_w_kernel<<<dim3(CDIM / 64,     FFD / 64,  LAYERS), 256>>>(fc2_w,  w2, FFD, CDIM);

    add_pos_kernel<<<(size_t)TOK * CDIM / 4 / 256, 256>>>(x, pos, out);

    for (int l = 0; l < LAYERS; l++) {
        const __half* wql = wq + (size_t)l * CDIM * 3 * CDIM;
        // --- attention block ---
        ln_kernel<<<TOK / 8, 256>>>(out, ln1_g + (size_t)l * CDIM,
                                    ln1_b + (size_t)l * CDIM, xn, flags);
        // Q,K only (Wt rows 0..2C): N = 2048
        hgemm_kernel<3, __half><<<dim3(2 * CDIM / 128, TOK / 128), 256, GEMM_SMEM_BYTES>>>(
            xn, wql, qkv_b + (size_t)l * 3 * CDIM,
            nullptr, qk, TOK, 2 * CDIM, CDIM, nullptr);
        attn_mma_kernel<<<dim3(NSEQ / 64, BSZ * HEADS), 256, ATTN_SMEM_BYTES>>>(
            qk, xn, wql, qkv_b + (size_t)l * 3 * CDIM, attn, flags);
        hgemm_kernel<2, float><<<dim3(CDIM / 128, TOK / 128), 256, GEMM_SMEM_BYTES>>>(
            attn, wp + (size_t)l * CDIM * CDIM, proj_b + (size_t)l * CDIM,
            out, out, TOK, CDIM, CDIM, flags);
        // --- MLP block ---
        ln_kernel<<<TOK / 8, 256>>>(out, ln2_g + (size_t)l * CDIM,
                                    ln2_b + (size_t)l * CDIM, xn, flags);
        hgemm_kernel<1, __half><<<dim3(FFD / 128, TOK / 128), 256, GEMM_SMEM_BYTES>>>(
            xn, w1 + (size_t)l * CDIM * FFD, fc1_b + (size_t)l * FFD,
            nullptr, ff, TOK, FFD, CDIM, nullptr);
        hgemm_kernel<2, float><<<dim3(CDIM / 128, TOK / 128), 256, GEMM_SMEM_BYTES>>>(
            ff, w2 + (size_t)l * FFD * CDIM, fc2_b + (size_t)l * CDIM,
            out, out, TOK, CDIM, FFD, nullptr);
    }
}

// round 11
// speedup vs baseline: 8.9564x; 1.1470x over previous
#include <cuda_runtime.h>
#include <cuda_fp16.h>
#include <math.h>
#include <stdint.h>

#define TOK   4096          // B*N
#define BSZ   4
#define NSEQ  1024
#define CDIM  1024
#define HEADS 16
#define HDIM  64
#define FFD   4096
#define LAYERS 4
#define ATT_SCALE_LOG2E 0.1803368801111244f   // 64^-0.5 * log2(e)

// GEMM smem strides (halves)
#define LDH 72              // 64 halves + 8 pad -> 144 B row stride
#define GEMM_TILE_H (128 * LDH)                 // halves per (A or B) tile
#define STAGE_H (2 * GEMM_TILE_H)               // A + B per stage
#define GEMM_STAGES 3
#define GEMM_SMEM_BYTES (GEMM_STAGES * STAGE_H * 2)   // 110592 B

// attn smem: Q [64][72] + K [2 buf][128][72] halves
#define ATTN_Q_H (64 * LDH)
#define ATTN_K_H (2 * 128 * LDH)
#define ATTN_SMEM_BYTES ((ATTN_Q_H + ATTN_K_H) * 2)

// Scratch (device globals; no allocation allowed)
__device__ __half g_xn  [(size_t)TOK * CDIM];
__device__ __half g_qk  [(size_t)TOK * 2 * CDIM];   // [tok][Q(0..C) K(C..2C)]
__device__ __half g_attn[(size_t)TOK * CDIM];
__device__ __half g_ff  [(size_t)TOK * FFD];
__device__ int    g_flags[TOK / 128];               // per-128-token-tile nonzero flag
__device__ int    g_pbz[LAYERS];                    // proj bias nonzero flag
// fp16, TRANSPOSED weights: Wt[N][K]
__device__ __half g_wq[(size_t)LAYERS * CDIM * 3 * CDIM];
__device__ __half g_wp[(size_t)LAYERS * CDIM * CDIM];
__device__ __half g_w1[(size_t)LAYERS * CDIM * FFD];
__device__ __half g_w2[(size_t)LAYERS * FFD * CDIM];

// ---------------------------------------------------------------------------
__device__ __forceinline__ void cp_async16(uint32_t s, const void* g) {
    asm volatile("cp.async.cg.shared.global [%0], [%1], 16;" :: "r"(s), "l"(g));
}
__device__ __forceinline__ void cp_commit() {
    asm volatile("cp.async.commit_group;");
}
__device__ __forceinline__ void cp_wait0() {
    asm volatile("cp.async.wait_group 0;");
}
__device__ __forceinline__ void cp_wait1() {
    asm volatile("cp.async.wait_group 1;");
}
__device__ __forceinline__ void ldsm_x4(uint32_t& r0, uint32_t& r1, uint32_t& r2,
                                        uint32_t& r3, uint32_t addr) {
    asm volatile("ldmatrix.sync.aligned.m8n8.x4.shared.b16 {%0,%1,%2,%3}, [%4];"
                 : "=r"(r0), "=r"(r1), "=r"(r2), "=r"(r3) : "r"(addr));
}
__device__ __forceinline__ void mma_f16(float* c, const uint32_t* a, const uint32_t* b) {
    asm volatile(
        "mma.sync.aligned.m16n8k16.row.col.f32.f16.f16.f32 "
        "{%0,%1,%2,%3}, {%4,%5,%6,%7}, {%8,%9}, {%0,%1,%2,%3};"
        : "+f"(c[0]), "+f"(c[1]), "+f"(c[2]), "+f"(c[3])
        : "r"(a[0]), "r"(a[1]), "r"(a[2]), "r"(a[3]), "r"(b[0]), "r"(b[1]));
}
__device__ __forceinline__ float tanh_fast(float x) {
    float y;
    asm("tanh.approx.f32 %0, %1;" : "=f"(y) : "f"(x));
    return y;
}
__device__ __forceinline__ float gelu_fast(float v) {
    const float c0 = 0.7978845608028654f, c1 = 0.044715f;
    return 0.5f * v * (1.0f + tanh_fast(c0 * (v + c1 * v * v * v)));
}
__device__ __forceinline__ float ex2(float x) {   // 2^x, HW MUFU
    float y;
    asm("ex2.approx.f32 %0, %1;" : "=f"(y) : "f"(x));
    return y;
}

// ---------------------------------------------------------------------------
// weight prep: fp32 [K,N] -> half [N,K] (transpose + convert), per-layer via z
// 64x64 tiles; coalesced 128B reads AND writes.
// ---------------------------------------------------------------------------
__global__ __launch_bounds__(256)
void prep_w_kernel(const float* __restrict__ src,
                   __half* __restrict__ dst, int K, int N) {
    __shared__ __half t[64][65];
    const size_t lo = (size_t)blockIdx.z * K * N;
    const int n0 = blockIdx.x * 64, k0 = blockIdx.y * 64;
    const int tx = threadIdx.x & 15, ty = threadIdx.x >> 4;   // 16x16

    #pragma unroll
    for (int ii = 0; ii < 4; ii++) {
        const int k = k0 + ty + ii * 16;
        const float4 v = *(const float4*)&src[lo + (size_t)k * N + n0 + tx * 4];
        t[tx * 4 + 0][ty + ii * 16] = __float2half(v.x);
        t[tx * 4 + 1][ty + ii * 16] = __float2half(v.y);
        t[tx * 4 + 2][ty + ii * 16] = __float2half(v.z);
        t[tx * 4 + 3][ty + ii * 16] = __float2half(v.w);
    }
    __syncthreads();

    const int w = threadIdx.x >> 5, l = threadIdx.x & 31;
    #pragma unroll
    for (int r = 0; r < 8; r++) {
        const int n = w * 8 + r;
        __half2 h = __halves2half2(t[n][2 * l], t[n][2 * l + 1]);
        *(uint32_t*)&dst[lo + (size_t)(n0 + n) * K + k0 + 2 * l] = *(uint32_t*)&h;
    }
}

// ---------------------------------------------------------------------------
// per-layer proj-bias nonzero check (one block per layer)
// ---------------------------------------------------------------------------
__global__ void biascheck_kernel(const float* __restrict__ b, int* __restrict__ flag) {
    const float* p = b + (size_t)blockIdx.x * CDIM;
    int nz = 0;
    for (int i = threadIdx.x; i < CDIM; i += 256) nz |= (p[i] != 0.0f);
    nz = __syncthreads_or(nz);
    if (threadIdx.x == 0) flag[blockIdx.x] = nz;
}

// ---------------------------------------------------------------------------
// out = x + pos (pos broadcast over batch), fp32
// ---------------------------------------------------------------------------
__global__ void add_pos_kernel(const float* __restrict__ x,
                               const float* __restrict__ pos,
                               float* __restrict__ out) {
    int i = blockIdx.x * blockDim.x + threadIdx.x;
    const float4 a = ((const float4*)x)[i];
    const float4 p = ((const float4*)pos)[i & ((NSEQ * CDIM / 4) - 1)];
    float4 o;
    o.x = a.x + p.x; o.y = a.y + p.y; o.z = a.z + p.z; o.w = a.w + p.w;
    ((float4*)out)[i] = o;
}

// ---------------------------------------------------------------------------
// LayerNorm: ONE WARP per row (8 rows / 256-thr block). fp32 in -> fp16 out.
// Block 0 also zeroes the attention-sparsity flags (consumed later in layer).
// ---------------------------------------------------------------------------
__global__ __launch_bounds__(256)
void ln_kernel(const float* __restrict__ in,
               const float* __restrict__ g,
               const float* __restrict__ b,
               __half* __restrict__ out,
               int* __restrict__ flags) {
    if (blockIdx.x == 0 && threadIdx.x < TOK / 128) flags[threadIdx.x] = 0;

    const int row  = blockIdx.x * 8 + (threadIdx.x >> 5);
    const int lane = threadIdx.x & 31;
    const float4* rp = (const float4*)(in + (size_t)row * CDIM);

    float4 xv[8];
    float s = 0.f, sq = 0.f;
    #pragma unroll
    for (int i = 0; i < 8; i++) {
        xv[i] = rp[i * 32 + lane];
        s  += xv[i].x + xv[i].y + xv[i].z + xv[i].w;
        sq += xv[i].x * xv[i].x + xv[i].y * xv[i].y
            + xv[i].z * xv[i].z + xv[i].w * xv[i].w;
    }
    #pragma unroll
    for (int o = 16; o > 0; o >>= 1) {
        s  += __shfl_xor_sync(0xffffffffu, s, o);
        sq += __shfl_xor_sync(0xffffffffu, sq, o);
    }
    const float mean = s * (1.0f / CDIM);
    const float var  = sq * (1.0f / CDIM) - mean * mean;
    const float rstd = rsqrtf(var + 1e-5f);

    const float4* gp = (const float4*)g;
    const float4* bp = (const float4*)b;
    uint2* op = (uint2*)(out + (size_t)row * CDIM);
    #pragma unroll
    for (int i = 0; i < 8; i++) {
        const float4 gg = gp[i * 32 + lane];
        const float4 bb = bp[i * 32 + lane];
        __half2 h0 = __floats2half2_rn((xv[i].x - mean) * rstd * gg.x + bb.x,
                                       (xv[i].y - mean) * rstd * gg.y + bb.y);
        __half2 h1 = __floats2half2_rn((xv[i].z - mean) * rstd * gg.z + bb.z,
                                       (xv[i].w - mean) * rstd * gg.w + bb.w);
        uint2 o;
        o.x = *(uint32_t*)&h0;
        o.y = *(uint32_t*)&h1;
        op[i * 32 + lane] = o;
    }
}

// ---------------------------------------------------------------------------
// FP16 tensor-core GEMM: C = A[M,K] @ Wt[N,K]^T + bias
// 128x128 CTA tile, BK=64, 256 threads, 3-stage cp.async pipeline with the
// next-next tile's loads interleaved into the MMA ks-loop (no LSU burst).
// ACT 1: gelu (half out), 2: +residual (fp32 out; tile-skip via flags and
//        full early-exit when bias is known-zero), 3: plain (half out)
// ---------------------------------------------------------------------------
template <int ACT, typename OUT_T>
__global__ __launch_bounds__(256, 2)
void hgemm_kernel(const __half* __restrict__ A,
                  const __half* __restrict__ Wt,
                  const float* __restrict__ bias,
                  const float* __restrict__ res,
                  OUT_T* __restrict__ C,
                  int M, int N, int K,
                  const int* __restrict__ flags,
                  const int* __restrict__ bias_nz) {
    extern __shared__ __half smh[];

    const int tid  = threadIdx.x;
    const int lane = tid & 31;
    const int warp = tid >> 5;
    const int wm = warp >> 2;
    const int wn = warp & 3;
    const int bm = blockIdx.y * 128;
    const int bn = blockIdx.x * 128;

    const bool skip = (ACT == 2) && flags && (flags[blockIdx.y] == 0);
    if (ACT == 2 && skip && bias_nz && bias_nz[0] == 0) return;  // out += 0

    float acc[4][4][4];
    #pragma unroll
    for (int i = 0; i < 4; i++)
        #pragma unroll
        for (int j = 0; j < 4; j++)
            #pragma unroll
            for (int t = 0; t < 4; t++) acc[i][j][t] = 0.f;

    if (!skip) {
        // one 16B A-chunk + one 16B B-chunk per thread per part (4 parts/tile)
        auto load_chunk = [&](int kt, int st, int part) {
            const __half* Ag = A  + (size_t)bm * K + kt * 64;
            const __half* Bg = Wt + (size_t)bn * K + kt * 64;
            __half* as = smh + st * STAGE_H;
            __half* bs = as + GEMM_TILE_H;
            int c = tid + part * 256;
            int r = c >> 3, seg = (c & 7) * 8;
            cp_async16((uint32_t)__cvta_generic_to_shared(as + r * LDH + seg),
                       Ag + (size_t)r * K + seg);
            cp_async16((uint32_t)__cvta_generic_to_shared(bs + r * LDH + seg),
                       Bg + (size_t)r * K + seg);
        };
        auto load_tile = [&](int kt, int st) {
            #pragma unroll
            for (int i = 0; i < 4; i++) load_chunk(kt, st, i);
        };

        const int KT = K / 64;
        load_tile(0, 0);
        cp_commit();
        load_tile(1, 1);
        cp_commit();

        const int a_row  = wm * 64 + (lane & 15);
        const int a_koff = (lane >> 4) * 8;
        const int b_g = lane >> 3;
        const int b_r = lane & 7;

        for (int kt = 0; kt < KT; kt++) {
            if (kt + 1 < KT) cp_wait1(); else cp_wait0();
            __syncthreads();
            const bool pf = (kt + 2 < KT);
            const int pfs = (kt + 2) % GEMM_STAGES;

            const __half* as = smh + (kt % GEMM_STAGES) * STAGE_H;
            const __half* bs = as + GEMM_TILE_H;
            #pragma unroll
            for (int ks = 0; ks < 4; ks++) {
                if (pf) load_chunk(kt + 2, pfs, ks);
                uint32_t a[4][4];
                #pragma unroll
                for (int mt = 0; mt < 4; mt++) {
                    uint32_t addr = (uint32_t)__cvta_generic_to_shared(
                        as + (a_row + mt * 16) * LDH + ks * 16 + a_koff);
                    ldsm_x4(a[mt][0], a[mt][1], a[mt][2], a[mt][3], addr);
                }
                uint32_t b[4][2];
                #pragma unroll
                for (int c = 0; c < 2; c++) {
                    int row = wn * 32 + (2 * c + (b_g >> 1)) * 8 + b_r;
                    int col = ks * 16 + (b_g & 1) * 8;
                    uint32_t addr = (uint32_t)__cvta_generic_to_shared(
                        bs + row * LDH + col);
                    ldsm_x4(b[2 * c][0], b[2 * c][1], b[2 * c + 1][0], b[2 * c + 1][1], addr);
                }
                #pragma unroll
                for (int mt = 0; mt < 4; mt++)
                    #pragma unroll
                    for (int nt = 0; nt < 4; nt++)
                        mma_f16(acc[mt][nt], a[mt], b[nt]);
            }
            if (pf) cp_commit();
        }
    }

    // Epilogue
    const int e_row = bm + wm * 64 + (lane >> 2);
    const int e_col = bn + wn * 32 + (lane & 3) * 2;
    #pragma unroll
    for (int mt = 0; mt < 4; mt++) {
        #pragma unroll
        for (int nt = 0; nt < 4; nt++) {
            const int col = e_col + nt * 8;
            const float bz0 = bias[col], bz1 = bias[col + 1];
            #pragma unroll
            for (int half_i = 0; half_i < 2; half_i++) {
                const int row = e_row + mt * 16 + half_i * 8;
                float v0 = acc[mt][nt][half_i * 2 + 0] + bz0;
                float v1 = acc[mt][nt][half_i * 2 + 1] + bz1;
                if (ACT == 1) {
                    v0 = gelu_fast(v0);
                    v1 = gelu_fast(v1);
                }
                if (ACT == 2) {
                    const float2 r2 = *(const float2*)(res + (size_t)row * N + col);
                    v0 += r2.x; v1 += r2.y;
                    float2 o; o.x = v0; o.y = v1;
                    *(float2*)((float*)C + (size_t)row * N + col) = o;
                } else {
                    __half2 h = __floats2half2_rn(v0, v1);
                    *(uint32_t*)((__half*)C + (size_t)row * N + col) = *(uint32_t*)&h;
                }
            }
        }
    }
}

// ---------------------------------------------------------------------------
// FP16 tensor-core attention with hard threshold (base-2 softmax algebra).
//   out_row = (1/Z > 0.5) ? (xn[j*] @ Wv + bv)/Z : 0   (V computed on demand)
// Scores held as s2 = s*log2(e)*scale; Z = sum 2^(s2-m2) is identical to the
// base-e softmax denominator. qk layout: [tok][2*CDIM]: Q at 0, K at CDIM.
// ---------------------------------------------------------------------------
__global__ __launch_bounds__(256, 3)
void attn_mma_kernel(const __half* __restrict__ qk,
                     const __half* __restrict__ xn,
                     const __half* __restrict__ wt,     // full qkv Wt[3C][C]
                     const float* __restrict__ qkv_b,
                     __half* __restrict__ out,
                     int* __restrict__ flags) {
    extern __shared__ __half smh[];
    __half* Qs = smh;                 // [64][LDH]
    __half* Ks = smh + ATTN_Q_H;      // [2 buf][128][LDH]

    __shared__ float part_m[64][4];
    __shared__ float part_z[64][4];
    __shared__ int   part_j[64][4];
    __shared__ float rscale[64];
    __shared__ int   rjmax[64];
    __shared__ int   s_any;

    const int bh = blockIdx.y;
    const int b  = bh >> 4;
    const int h  = bh & 15;
    const int r0 = blockIdx.x * 64;
    const int tid = threadIdx.x, lane = tid & 31, warp = tid >> 5;
    const int wm = warp >> 2, wn = warp & 3;

    if (tid == 0) s_any = 0;

    // load Q tile [64][64]: 512 16B chunks
    #pragma unroll
    for (int i = 0; i < 2; i++) {
        int c = tid + i * 256;
        int r = c >> 3, seg = (c & 7) * 8;
        const __half* src = qk + (size_t)(b * NSEQ + r0 + r) * 2 * CDIM
                            + h * HDIM + seg;
        cp_async16((uint32_t)__cvta_generic_to_shared(Qs + r * LDH + seg), src);
    }

    auto load_k = [&](int c0, int buf) {
        __half* base = Ks + buf * (128 * LDH);
        #pragma unroll
        for (int i = 0; i < 4; i++) {
            int c = tid + i * 256;
            int r = c >> 3, seg = (c & 7) * 8;
            const __half* src = qk + (size_t)(b * NSEQ + c0 + r) * 2 * CDIM
                                + CDIM + h * HDIM + seg;
            cp_async16((uint32_t)__cvta_generic_to_shared(base + r * LDH + seg), src);
        }
    };

    cp_commit();                 // Q group
    load_k(0, 0);
    cp_commit();

    float m_[4], Z_[4];
    int j_[4];
    #pragma unroll
    for (int i = 0; i < 4; i++) { m_[i] = -1e30f; Z_[i] = 0.f; j_[i] = 0; }

    const int b_g = lane >> 3;
    const int b_r = lane & 7;

    for (int kc = 0; kc < 8; kc++) {
        const int buf = kc & 1;
        cp_wait0();
        __syncthreads();
        if (kc < 7) { load_k((kc + 1) * 128, buf ^ 1); cp_commit(); }

        float acc[2][4][4];
        #pragma unroll
        for (int i = 0; i < 2; i++)
            #pragma unroll
            for (int j = 0; j < 4; j++)
                #pragma unroll
                for (int t = 0; t < 4; t++) acc[i][j][t] = 0.f;

        const __half* kb = Ks + buf * (128 * LDH);
        #pragma unroll
        for (int ks = 0; ks < 4; ks++) {
            uint32_t a[2][4];
            #pragma unroll
            for (int mt = 0; mt < 2; mt++) {
                uint32_t addr = (uint32_t)__cvta_generic_to_shared(
                    Qs + (wm * 32 + mt * 16 + (lane & 15)) * LDH
                       + ks * 16 + (lane >> 4) * 8);
                ldsm_x4(a[mt][0], a[mt][1], a[mt][2], a[mt][3], addr);
            }
            uint32_t bfr[4][2];
            #pragma unroll
            for (int c = 0; c < 2; c++) {
                int row = wn * 32 + (2 * c + (b_g >> 1)) * 8 + b_r;
                int col = ks * 16 + (b_g & 1) * 8;
                uint32_t addr = (uint32_t)__cvta_generic_to_shared(
                    kb + row * LDH + col);
                ldsm_x4(bfr[2 * c][0], bfr[2 * c][1], bfr[2 * c + 1][0], bfr[2 * c + 1][1], addr);
            }
            #pragma unroll
            for (int mt = 0; mt < 2; mt++)
                #pragma unroll
                for (int nt = 0; nt < 4; nt++)
                    mma_f16(acc[mt][nt], a[mt], bfr[nt]);
        }

        // online (max, argmax, Z) update on fragments (base-2 domain)
        #pragma unroll
        for (int mt = 0; mt < 2; mt++) {
            #pragma unroll
            for (int half_i = 0; half_i < 2; half_i++) {
                const int si = mt * 2 + half_i;
                const int bcol = kc * 128 + wn * 32 + (lane & 3) * 2;
                float v[8];
                #pragma unroll
                for (int nt = 0; nt < 4; nt++) {
                    v[nt * 2 + 0] = acc[mt][nt][half_i * 2 + 0] * ATT_SCALE_LOG2E;
                    v[nt * 2 + 1] = acc[mt][nt][half_i * 2 + 1] * ATT_SCALE_LOG2E;
                }
                float cmax = v[0]; int cj = bcol;
                #pragma unroll
                for (int q = 1; q < 8; q++) {
                    int col = bcol + (q >> 1) * 8 + (q & 1);
                    if (v[q] > cmax) { cmax = v[q]; cj = col; }
                }
                if (cmax > m_[si]) {
                    Z_[si] *= ex2(m_[si] - cmax);
                    m_[si] = cmax;
                    j_[si] = cj;
                }
                float e = 0.f;
                #pragma unroll
                for (int q = 0; q < 8; q++) e += ex2(v[q] - m_[si]);
                Z_[si] += e;
            }
        }
    }

    // quad (lane&3) reduce, then cross-warp (wn) reduce via smem
    #pragma unroll
    for (int si = 0; si < 4; si++) {
        float mm = m_[si], zz = Z_[si];
        int jj = j_[si];
        #pragma unroll
        for (int o = 1; o <= 2; o <<= 1) {
            float om = __shfl_xor_sync(0xffffffffu, mm, o);
            float oz = __shfl_xor_sync(0xffffffffu, zz, o);
            int   oj = __shfl_xor_sync(0xffffffffu, jj, o);
            if (om > mm) { zz = zz * ex2(mm - om) + oz; mm = om; jj = oj; }
            else         { zz = zz + oz * ex2(om - mm); }
        }
        if ((lane & 3) == 0) {
            int row = wm * 32 + (si >> 1) * 16 + (si & 1) * 8 + (lane >> 2);
            part_m[row][wn] = mm;
            part_z[row][wn] = zz;
            part_j[row][wn] = jj;
        }
    }
    __syncthreads();

    if (tid < 64) {
        float mm = part_m[tid][0], zz = part_z[tid][0];
        int jj = part_j[tid][0];
        #pragma unroll
        for (int t = 1; t < 4; t++) {
            float om = part_m[tid][t], oz = part_z[tid][t];
            int   oj = part_j[tid][t];
            if (om > mm) { zz = zz * ex2(mm - om) + oz; mm = om; jj = oj; }
            else         { zz = zz + oz * ex2(om - mm); }
        }
        const float amax = 1.0f / zz;
        const float sc = (amax > 0.5f) ? amax : 0.0f;
        rscale[tid] = sc;
        rjmax[tid]  = jj;
        if (sc != 0.0f) s_any = 1;
    }
    __syncthreads();

    if (tid == 0 && s_any) {
        atomicOr(&flags[(b * NSEQ + r0) >> 7], 1);
    }

    // gather: out_row = sc * (xn[j*] @ Wv + bv); zero otherwise
    const int r  = tid >> 2;
    const int d0 = (tid & 3) * 16;
    const float sc = rscale[r];
    const int jj = rjmax[r];
    __half* orow = out + (size_t)(b * NSEQ + r0 + r) * CDIM + h * HDIM;
    if (sc != 0.0f) {
        // on-demand V: rare path (requires a softmax prob > 0.5)
        const __half* xrow = xn + (size_t)(b * NSEQ + jj) * CDIM;
        #pragma unroll 1
        for (int d = d0; d < d0 + 16; d++) {
            const __half* wrow = wt + (size_t)(2 * CDIM + h * HDIM + d) * CDIM;
            float accv = 0.f;
            const __half2* xp = (const __half2*)xrow;
            const __half2* wp = (const __half2*)wrow;
            #pragma unroll 8
            for (int k2 = 0; k2 < CDIM / 2; k2++) {
                float2 xf = __half22float2(xp[k2]);
                float2 wf = __half22float2(wp[k2]);
                accv += xf.x * wf.x + xf.y * wf.y;
            }
            accv += qkv_b[2 * CDIM + h * HDIM + d];
            orow[d] = __float2half(accv * sc);
        }
    } else {
        #pragma unroll
        for (int d = d0; d < d0 + 16; d += 4) {
            uint2 o; o.x = 0u; o.y = 0u;
            *(uint2*)(orow + d) = o;
        }
    }
}

// ---------------------------------------------------------------------------
extern "C" void kernel_launch(void* const* d_in, const int* in_sizes, int n_in,
                              void* d_out, int out_size) {
    (void)in_sizes; (void)n_in; (void)out_size;
    const float* x      = (const float*)d_in[0];
    const float* pos    = (const float*)d_in[1];
    const float* qkv_w  = (const float*)d_in[2];
    const float* qkv_b  = (const float*)d_in[3];
    const float* proj_w = (const float*)d_in[4];
    const float* proj_b = (const float*)d_in[5];
    const float* ln1_g  = (const float*)d_in[6];
    const float* ln1_b  = (const float*)d_in[7];
    const float* ln2_g  = (const float*)d_in[8];
    const float* ln2_b  = (const float*)d_in[9];
    const float* fc1_w  = (const float*)d_in[10];
    const float* fc1_b  = (const float*)d_in[11];
    const float* fc2_w  = (const float*)d_in[12];
    const float* fc2_b  = (const float*)d_in[13];
    float* out = (float*)d_out;

    __half *xn, *qk, *attn, *ff, *wq, *wp, *w1, *w2;
    int *flags, *pbz;
    cudaGetSymbolAddress((void**)&xn,   g_xn);
    cudaGetSymbolAddress((void**)&qk,   g_qk);
    cudaGetSymbolAddress((void**)&attn, g_attn);
    cudaGetSymbolAddress((void**)&ff,   g_ff);
    cudaGetSymbolAddress((void**)&wq,   g_wq);
    cudaGetSymbolAddress((void**)&wp,   g_wp);
    cudaGetSymbolAddress((void**)&w1,   g_w1);
    cudaGetSymbolAddress((void**)&w2,   g_w2);
    cudaGetSymbolAddress((void**)&flags, g_flags);
    cudaGetSymbolAddress((void**)&pbz,  g_pbz);

    cudaFuncSetAttribute(hgemm_kernel<1, __half>,
                         cudaFuncAttributeMaxDynamicSharedMemorySize, GEMM_SMEM_BYTES);
    cudaFuncSetAttribute(hgemm_kernel<2, float>,
                         cudaFuncAttributeMaxDynamicSharedMemorySize, GEMM_SMEM_BYTES);
    cudaFuncSetAttribute(hgemm_kernel<3, __half>,
                         cudaFuncAttributeMaxDynamicSharedMemorySize, GEMM_SMEM_BYTES);
    cudaFuncSetAttribute(attn_mma_kernel,
                         cudaFuncAttributeMaxDynamicSharedMemorySize, ATTN_SMEM_BYTES);

    // weight prep: fp16 convert + transpose [K,N] -> [N,K] (once per launch)
    prep_w_kernel<<<dim3(3 * CDIM / 64, CDIM / 64, LAYERS), 256>>>(qkv_w,  wq, CDIM, 3 * CDIM);
    prep_w_kernel<<<dim3(CDIM / 64,     CDIM / 64, LAYERS), 256>>>(proj_w, wp, CDIM, CDIM);
    prep_w_kernel<<<dim3(FFD / 64,      CDIM / 64, LAYERS), 256>>>(fc1_w,  w1, CDIM, FFD);
    prep_w_kernel<<<dim3(CDIM / 64,     FFD / 64,  LAYERS), 256>>>(fc2_w,  w2, FFD, CDIM);
    biascheck_kernel<<<LAYERS, 256>>>(proj_b, pbz);

    add_pos_kernel<<<(size_t)TOK * CDIM / 4 / 256, 256>>>(x, pos, out);

    for (int l = 0; l < LAYERS; l++) {
        const __half* wql = wq + (size_t)l * CDIM * 3 * CDIM;
        // --- attention block ---
        ln_kernel<<<TOK / 8, 256>>>(out, ln1_g + (size_t)l * CDIM,
                                    ln1_b + (size_t)l * CDIM, xn, flags);
        // Q,K only (Wt rows 0..2C): N = 2048
        hgemm_kernel<3, __half><<<dim3(2 * CDIM / 128, TOK / 128), 256, GEMM_SMEM_BYTES>>>(
            xn, wql, qkv_b + (size_t)l * 3 * CDIM,
            nullptr, qk, TOK, 2 * CDIM, CDIM, nullptr, nullptr);
        attn_mma_kernel<<<dim3(NSEQ / 64, BSZ * HEADS), 256, ATTN_SMEM_BYTES>>>(
            qk, xn, wql, qkv_b + (size_t)l * 3 * CDIM, attn, flags);
        hgemm_kernel<2, float><<<dim3(CDIM / 128, TOK / 128), 256, GEMM_SMEM_BYTES>>>(
            attn, wp + (size_t)l * CDIM * CDIM, proj_b + (size_t)l * CDIM,
            out, out, TOK, CDIM, CDIM, flags, pbz + l);
        // --- MLP block ---
        ln_kernel<<<TOK / 8, 256>>>(out, ln2_g + (size_t)l * CDIM,
                                    ln2_b + (size_t)l * CDIM, xn, flags);
        hgemm_kernel<1, __half><<<dim3(FFD / 128, TOK / 128), 256, GEMM_SMEM_BYTES>>>(
            xn, w1 + (size_t)l * CDIM * FFD, fc1_b + (size_t)l * FFD,
            nullptr, ff, TOK, FFD, CDIM, nullptr, nullptr);
        hgemm_kernel<2, float><<<dim3(CDIM / 128, TOK / 128), 256, GEMM_SMEM_BYTES>>>(
            ff, w2 + (size_t)l * FFD * CDIM, fc2_b + (size_t)l * CDIM,
            out, out, TOK, CDIM, FFD, nullptr, nullptr);
    }
}

// round 12
// speedup vs baseline: 9.0416x; 1.0095x over previous
#include <cuda_runtime.h>
#include <cuda_fp16.h>
#include <math.h>
#include <stdint.h>

#define TOK   4096          // B*N
#define BSZ   4
#define NSEQ  1024
#define CDIM  1024
#define HEADS 16
#define HDIM  64
#define FFD   4096
#define LAYERS 4
#define ATT_SCALE_LOG2E 0.1803368801111244f   // 64^-0.5 * log2(e)
#define NFLAGS (TOK / 128 + 1)                // [0..31] tile flags, [32] anyWinner

// GEMM smem strides (halves)
#define LDH 72              // 64 halves + 8 pad -> 144 B row stride
#define GEMM_TILE_H (128 * LDH)                 // halves per (A or B) tile
#define STAGE_H (2 * GEMM_TILE_H)               // A + B per stage
#define GEMM_STAGES 3
#define GEMM_SMEM_BYTES (GEMM_STAGES * STAGE_H * 2)   // 110592 B

// attn smem: Q [64][72] + K [2 buf][128][72] halves
#define ATTN_Q_H (64 * LDH)
#define ATTN_K_H (2 * 128 * LDH)
#define ATTN_SMEM_BYTES ((ATTN_Q_H + ATTN_K_H) * 2)

// Scratch (device globals; no allocation allowed)
__device__ __half g_xn  [(size_t)TOK * CDIM];
__device__ __half g_qk  [(size_t)TOK * 2 * CDIM];   // [tok][Q(0..C) K(C..2C)]
__device__ __half g_attn[(size_t)TOK * CDIM];
__device__ __half g_ff  [(size_t)TOK * FFD];
__device__ int    g_flags[NFLAGS];
__device__ int    g_pbz[LAYERS];                    // proj bias nonzero
__device__ int    g_lneq[LAYERS];                   // ln1 params == ln2 params
// fp16, TRANSPOSED weights: Wt[N][K]
__device__ __half g_wq[(size_t)LAYERS * CDIM * 3 * CDIM];
__device__ __half g_wp[(size_t)LAYERS * CDIM * CDIM];
__device__ __half g_w1[(size_t)LAYERS * CDIM * FFD];
__device__ __half g_w2[(size_t)LAYERS * FFD * CDIM];

// ---------------------------------------------------------------------------
__device__ __forceinline__ void cp_async16(uint32_t s, const void* g) {
    asm volatile("cp.async.cg.shared.global [%0], [%1], 16;" :: "r"(s), "l"(g));
}
__device__ __forceinline__ void cp_commit() {
    asm volatile("cp.async.commit_group;");
}
__device__ __forceinline__ void cp_wait0() {
    asm volatile("cp.async.wait_group 0;");
}
__device__ __forceinline__ void cp_wait1() {
    asm volatile("cp.async.wait_group 1;");
}
__device__ __forceinline__ void ldsm_x4(uint32_t& r0, uint32_t& r1, uint32_t& r2,
                                        uint32_t& r3, uint32_t addr) {
    asm volatile("ldmatrix.sync.aligned.m8n8.x4.shared.b16 {%0,%1,%2,%3}, [%4];"
                 : "=r"(r0), "=r"(r1), "=r"(r2), "=r"(r3) : "r"(addr));
}
__device__ __forceinline__ void mma_f16(float* c, const uint32_t* a, const uint32_t* b) {
    asm volatile(
        "mma.sync.aligned.m16n8k16.row.col.f32.f16.f16.f32 "
        "{%0,%1,%2,%3}, {%4,%5,%6,%7}, {%8,%9}, {%0,%1,%2,%3};"
        : "+f"(c[0]), "+f"(c[1]), "+f"(c[2]), "+f"(c[3])
        : "r"(a[0]), "r"(a[1]), "r"(a[2]), "r"(a[3]), "r"(b[0]), "r"(b[1]));
}
__device__ __forceinline__ float tanh_fast(float x) {
    float y;
    asm("tanh.approx.f32 %0, %1;" : "=f"(y) : "f"(x));
    return y;
}
__device__ __forceinline__ float gelu_fast(float v) {
    const float c0 = 0.7978845608028654f, c1 = 0.044715f;
    return 0.5f * v * (1.0f + tanh_fast(c0 * (v + c1 * v * v * v)));
}
__device__ __forceinline__ float ex2(float x) {   // 2^x, HW MUFU
    float y;
    asm("ex2.approx.f32 %0, %1;" : "=f"(y) : "f"(x));
    return y;
}

// ---------------------------------------------------------------------------
// weight prep: fp32 [K,N] -> half [N,K] (transpose + convert), per-layer via z
// 64x64 tiles; coalesced 128B reads AND writes.
// ---------------------------------------------------------------------------
__global__ __launch_bounds__(256)
void prep_w_kernel(const float* __restrict__ src,
                   __half* __restrict__ dst, int K, int N) {
    __shared__ __half t[64][65];
    const size_t lo = (size_t)blockIdx.z * K * N;
    const int n0 = blockIdx.x * 64, k0 = blockIdx.y * 64;
    const int tx = threadIdx.x & 15, ty = threadIdx.x >> 4;   // 16x16

    #pragma unroll
    for (int ii = 0; ii < 4; ii++) {
        const int k = k0 + ty + ii * 16;
        const float4 v = *(const float4*)&src[lo + (size_t)k * N + n0 + tx * 4];
        t[tx * 4 + 0][ty + ii * 16] = __float2half(v.x);
        t[tx * 4 + 1][ty + ii * 16] = __float2half(v.y);
        t[tx * 4 + 2][ty + ii * 16] = __float2half(v.z);
        t[tx * 4 + 3][ty + ii * 16] = __float2half(v.w);
    }
    __syncthreads();

    const int w = threadIdx.x >> 5, l = threadIdx.x & 31;
    #pragma unroll
    for (int r = 0; r < 8; r++) {
        const int n = w * 8 + r;
        __half2 h = __halves2half2(t[n][2 * l], t[n][2 * l + 1]);
        *(uint32_t*)&dst[lo + (size_t)(n0 + n) * K + k0 + 2 * l] = *(uint32_t*)&h;
    }
}

// ---------------------------------------------------------------------------
// small per-layer checks: proj bias nonzero? ln1 params == ln2 params?
// ---------------------------------------------------------------------------
__global__ void smallprep_kernel(const float* __restrict__ proj_b,
                                 const float* __restrict__ l1g,
                                 const float* __restrict__ l1b,
                                 const float* __restrict__ l2g,
                                 const float* __restrict__ l2b,
                                 int* __restrict__ pbz,
                                 int* __restrict__ lneq) {
    const int l = blockIdx.x;
    const size_t o = (size_t)l * CDIM;
    int nz = 0, neq = 0;
    for (int i = threadIdx.x; i < CDIM; i += 256) {
        nz  |= (proj_b[o + i] != 0.0f);
        neq |= (l1g[o + i] != l2g[o + i]) | (l1b[o + i] != l2b[o + i]);
    }
    nz  = __syncthreads_or(nz);
    neq = __syncthreads_or(neq);
    if (threadIdx.x == 0) { pbz[l] = nz; lneq[l] = !neq; }
}

// ---------------------------------------------------------------------------
// out = x + pos (pos broadcast over batch), fp32
// ---------------------------------------------------------------------------
__global__ void add_pos_kernel(const float* __restrict__ x,
                               const float* __restrict__ pos,
                               float* __restrict__ out) {
    int i = blockIdx.x * blockDim.x + threadIdx.x;
    const float4 a = ((const float4*)x)[i];
    const float4 p = ((const float4*)pos)[i & ((NSEQ * CDIM / 4) - 1)];
    float4 o;
    o.x = a.x + p.x; o.y = a.y + p.y; o.z = a.z + p.z; o.w = a.w + p.w;
    ((float4*)out)[i] = o;
}

// ---------------------------------------------------------------------------
// LayerNorm: ONE WARP per row (8 rows / 256-thr block). fp32 in -> fp16 out.
// If `flags` given (ln1), block 0 zeroes all flags (incl. anyWinner).
// If `anyw`/`lneq` given (ln2), early-exit when attention was an identity and
// ln params match ln1 (xn already holds the correct values).
// ---------------------------------------------------------------------------
__global__ __launch_bounds__(256)
void ln_kernel(const float* __restrict__ in,
               const float* __restrict__ g,
               const float* __restrict__ b,
               __half* __restrict__ out,
               int* __restrict__ flags,
               const int* __restrict__ anyw,
               const int* __restrict__ lneq) {
    if (anyw && lneq && lneq[0] != 0 && anyw[0] == 0) return;
    if (flags && blockIdx.x == 0 && threadIdx.x < NFLAGS) flags[threadIdx.x] = 0;

    const int row  = blockIdx.x * 8 + (threadIdx.x >> 5);
    const int lane = threadIdx.x & 31;
    const float4* rp = (const float4*)(in + (size_t)row * CDIM);

    float4 xv[8];
    float s = 0.f, sq = 0.f;
    #pragma unroll
    for (int i = 0; i < 8; i++) {
        xv[i] = rp[i * 32 + lane];
        s  += xv[i].x + xv[i].y + xv[i].z + xv[i].w;
        sq += xv[i].x * xv[i].x + xv[i].y * xv[i].y
            + xv[i].z * xv[i].z + xv[i].w * xv[i].w;
    }
    #pragma unroll
    for (int o = 16; o > 0; o >>= 1) {
        s  += __shfl_xor_sync(0xffffffffu, s, o);
        sq += __shfl_xor_sync(0xffffffffu, sq, o);
    }
    const float mean = s * (1.0f / CDIM);
    const float var  = sq * (1.0f / CDIM) - mean * mean;
    const float rstd = rsqrtf(var + 1e-5f);

    const float4* gp = (const float4*)g;
    const float4* bp = (const float4*)b;
    uint2* op = (uint2*)(out + (size_t)row * CDIM);
    #pragma unroll
    for (int i = 0; i < 8; i++) {
        const float4 gg = gp[i * 32 + lane];
        const float4 bb = bp[i * 32 + lane];
        __half2 h0 = __floats2half2_rn((xv[i].x - mean) * rstd * gg.x + bb.x,
                                       (xv[i].y - mean) * rstd * gg.y + bb.y);
        __half2 h1 = __floats2half2_rn((xv[i].z - mean) * rstd * gg.z + bb.z,
                                       (xv[i].w - mean) * rstd * gg.w + bb.w);
        uint2 o;
        o.x = *(uint32_t*)&h0;
        o.y = *(uint32_t*)&h1;
        op[i * 32 + lane] = o;
    }
}

// ---------------------------------------------------------------------------
// FP16 tensor-core GEMM: C = A[M,K] @ Wt[N,K]^T + bias
// 128x128 CTA tile, BK=64, 256 threads, 3-stage cp.async pipeline with the
// next-next tile's loads interleaved into the MMA ks-loop (no LSU burst).
// ACT 1: gelu (half out), 2: +residual (fp32 out; tile-skip via flags and
//        full early-exit when bias is known-zero), 3: plain (half out)
// ---------------------------------------------------------------------------
template <int ACT, typename OUT_T>
__global__ __launch_bounds__(256, 2)
void hgemm_kernel(const __half* __restrict__ A,
                  const __half* __restrict__ Wt,
                  const float* __restrict__ bias,
                  const float* __restrict__ res,
                  OUT_T* __restrict__ C,
                  int M, int N, int K,
                  const int* __restrict__ flags,
                  const int* __restrict__ bias_nz) {
    extern __shared__ __half smh[];

    const int tid  = threadIdx.x;
    const int lane = tid & 31;
    const int warp = tid >> 5;
    const int wm = warp >> 2;
    const int wn = warp & 3;
    const int bm = blockIdx.y * 128;
    const int bn = blockIdx.x * 128;

    const bool skip = (ACT == 2) && flags && (flags[blockIdx.y] == 0);
    if (ACT == 2 && skip && bias_nz && bias_nz[0] == 0) return;  // out += 0

    float acc[4][4][4];
    #pragma unroll
    for (int i = 0; i < 4; i++)
        #pragma unroll
        for (int j = 0; j < 4; j++)
            #pragma unroll
            for (int t = 0; t < 4; t++) acc[i][j][t] = 0.f;

    if (!skip) {
        // one 16B A-chunk + one 16B B-chunk per thread per part (4 parts/tile)
        auto load_chunk = [&](int kt, int st, int part) {
            const __half* Ag = A  + (size_t)bm * K + kt * 64;
            const __half* Bg = Wt + (size_t)bn * K + kt * 64;
            __half* as = smh + st * STAGE_H;
            __half* bs = as + GEMM_TILE_H;
            int c = tid + part * 256;
            int r = c >> 3, seg = (c & 7) * 8;
            cp_async16((uint32_t)__cvta_generic_to_shared(as + r * LDH + seg),
                       Ag + (size_t)r * K + seg);
            cp_async16((uint32_t)__cvta_generic_to_shared(bs + r * LDH + seg),
                       Bg + (size_t)r * K + seg);
        };
        auto load_tile = [&](int kt, int st) {
            #pragma unroll
            for (int i = 0; i < 4; i++) load_chunk(kt, st, i);
        };

        const int KT = K / 64;
        load_tile(0, 0);
        cp_commit();
        load_tile(1, 1);
        cp_commit();

        const int a_row  = wm * 64 + (lane & 15);
        const int a_koff = (lane >> 4) * 8;
        const int b_g = lane >> 3;
        const int b_r = lane & 7;

        for (int kt = 0; kt < KT; kt++) {
            if (kt + 1 < KT) cp_wait1(); else cp_wait0();
            __syncthreads();
            const bool pf = (kt + 2 < KT);
            const int pfs = (kt + 2) % GEMM_STAGES;

            const __half* as = smh + (kt % GEMM_STAGES) * STAGE_H;
            const __half* bs = as + GEMM_TILE_H;
            #pragma unroll
            for (int ks = 0; ks < 4; ks++) {
                if (pf) load_chunk(kt + 2, pfs, ks);
                uint32_t a[4][4];
                #pragma unroll
                for (int mt = 0; mt < 4; mt++) {
                    uint32_t addr = (uint32_t)__cvta_generic_to_shared(
                        as + (a_row + mt * 16) * LDH + ks * 16 + a_koff);
                    ldsm_x4(a[mt][0], a[mt][1], a[mt][2], a[mt][3], addr);
                }
                uint32_t b[4][2];
                #pragma unroll
                for (int c = 0; c < 2; c++) {
                    int row = wn * 32 + (2 * c + (b_g >> 1)) * 8 + b_r;
                    int col = ks * 16 + (b_g & 1) * 8;
                    uint32_t addr = (uint32_t)__cvta_generic_to_shared(
                        bs + row * LDH + col);
                    ldsm_x4(b[2 * c][0], b[2 * c][1], b[2 * c + 1][0], b[2 * c + 1][1], addr);
                }
                #pragma unroll
                for (int mt = 0; mt < 4; mt++)
                    #pragma unroll
                    for (int nt = 0; nt < 4; nt++)
                        mma_f16(acc[mt][nt], a[mt], b[nt]);
            }
            if (pf) cp_commit();
        }
    }

    // Epilogue
    const int e_row = bm + wm * 64 + (lane >> 2);
    const int e_col = bn + wn * 32 + (lane & 3) * 2;
    #pragma unroll
    for (int mt = 0; mt < 4; mt++) {
        #pragma unroll
        for (int nt = 0; nt < 4; nt++) {
            const int col = e_col + nt * 8;
            const float bz0 = bias[col], bz1 = bias[col + 1];
            #pragma unroll
            for (int half_i = 0; half_i < 2; half_i++) {
                const int row = e_row + mt * 16 + half_i * 8;
                float v0 = acc[mt][nt][half_i * 2 + 0] + bz0;
                float v1 = acc[mt][nt][half_i * 2 + 1] + bz1;
                if (ACT == 1) {
                    v0 = gelu_fast(v0);
                    v1 = gelu_fast(v1);
                }
                if (ACT == 2) {
                    const float2 r2 = *(const float2*)(res + (size_t)row * N + col);
                    v0 += r2.x; v1 += r2.y;
                    float2 o; o.x = v0; o.y = v1;
                    *(float2*)((float*)C + (size_t)row * N + col) = o;
                } else {
                    __half2 h = __floats2half2_rn(v0, v1);
                    *(uint32_t*)((__half*)C + (size_t)row * N + col) = *(uint32_t*)&h;
                }
            }
        }
    }
}

// ---------------------------------------------------------------------------
// FP16 tensor-core attention with hard threshold (base-2 softmax algebra).
//   out_row = (1/Z > 0.5) ? (xn[j*] @ Wv + bv)/Z : 0   (V computed on demand)
// fmaxf-tree chunk max; argmax index recovered only when the running max
// improves. Sets per-tile flags and the per-layer anyWinner flag.
// ---------------------------------------------------------------------------
__global__ __launch_bounds__(256, 3)
void attn_mma_kernel(const __half* __restrict__ qk,
                     const __half* __restrict__ xn,
                     const __half* __restrict__ wt,     // full qkv Wt[3C][C]
                     const float* __restrict__ qkv_b,
                     __half* __restrict__ out,
                     int* __restrict__ flags) {
    extern __shared__ __half smh[];
    __half* Qs = smh;                 // [64][LDH]
    __half* Ks = smh + ATTN_Q_H;      // [2 buf][128][LDH]

    __shared__ float part_m[64][4];
    __shared__ float part_z[64][4];
    __shared__ int   part_j[64][4];
    __shared__ float rscale[64];
    __shared__ int   rjmax[64];
    __shared__ int   s_any;

    const int bh = blockIdx.y;
    const int b  = bh >> 4;
    const int h  = bh & 15;
    const int r0 = blockIdx.x * 64;
    const int tid = threadIdx.x, lane = tid & 31, warp = tid >> 5;
    const int wm = warp >> 2, wn = warp & 3;

    if (tid == 0) s_any = 0;

    // load Q tile [64][64]: 512 16B chunks
    #pragma unroll
    for (int i = 0; i < 2; i++) {
        int c = tid + i * 256;
        int r = c >> 3, seg = (c & 7) * 8;
        const __half* src = qk + (size_t)(b * NSEQ + r0 + r) * 2 * CDIM
                            + h * HDIM + seg;
        cp_async16((uint32_t)__cvta_generic_to_shared(Qs + r * LDH + seg), src);
    }

    auto load_k = [&](int c0, int buf) {
        __half* base = Ks + buf * (128 * LDH);
        #pragma unroll
        for (int i = 0; i < 4; i++) {
            int c = tid + i * 256;
            int r = c >> 3, seg = (c & 7) * 8;
            const __half* src = qk + (size_t)(b * NSEQ + c0 + r) * 2 * CDIM
                                + CDIM + h * HDIM + seg;
            cp_async16((uint32_t)__cvta_generic_to_shared(base + r * LDH + seg), src);
        }
    };

    cp_commit();                 // Q group
    load_k(0, 0);
    cp_commit();

    float m_[4], Z_[4];
    int j_[4];
    #pragma unroll
    for (int i = 0; i < 4; i++) { m_[i] = -1e30f; Z_[i] = 0.f; j_[i] = 0; }

    const int b_g = lane >> 3;
    const int b_r = lane & 7;

    for (int kc = 0; kc < 8; kc++) {
        const int buf = kc & 1;
        cp_wait0();
        __syncthreads();
        if (kc < 7) { load_k((kc + 1) * 128, buf ^ 1); cp_commit(); }

        float acc[2][4][4];
        #pragma unroll
        for (int i = 0; i < 2; i++)
            #pragma unroll
            for (int j = 0; j < 4; j++)
                #pragma unroll
                for (int t = 0; t < 4; t++) acc[i][j][t] = 0.f;

        const __half* kb = Ks + buf * (128 * LDH);
        #pragma unroll
        for (int ks = 0; ks < 4; ks++) {
            uint32_t a[2][4];
            #pragma unroll
            for (int mt = 0; mt < 2; mt++) {
                uint32_t addr = (uint32_t)__cvta_generic_to_shared(
                    Qs + (wm * 32 + mt * 16 + (lane & 15)) * LDH
                       + ks * 16 + (lane >> 4) * 8);
                ldsm_x4(a[mt][0], a[mt][1], a[mt][2], a[mt][3], addr);
            }
            uint32_t bfr[4][2];
            #pragma unroll
            for (int c = 0; c < 2; c++) {
                int row = wn * 32 + (2 * c + (b_g >> 1)) * 8 + b_r;
                int col = ks * 16 + (b_g & 1) * 8;
                uint32_t addr = (uint32_t)__cvta_generic_to_shared(
                    kb + row * LDH + col);
                ldsm_x4(bfr[2 * c][0], bfr[2 * c][1], bfr[2 * c + 1][0], bfr[2 * c + 1][1], addr);
            }
            #pragma unroll
            for (int mt = 0; mt < 2; mt++)
                #pragma unroll
                for (int nt = 0; nt < 4; nt++)
                    mma_f16(acc[mt][nt], a[mt], bfr[nt]);
        }

        // online (max, argmax, Z) update on fragments (base-2 domain)
        #pragma unroll
        for (int mt = 0; mt < 2; mt++) {
            #pragma unroll
            for (int half_i = 0; half_i < 2; half_i++) {
                const int si = mt * 2 + half_i;
                const int bcol = kc * 128 + wn * 32 + (lane & 3) * 2;
                float v[8];
                #pragma unroll
                for (int nt = 0; nt < 4; nt++) {
                    v[nt * 2 + 0] = acc[mt][nt][half_i * 2 + 0] * ATT_SCALE_LOG2E;
                    v[nt * 2 + 1] = acc[mt][nt][half_i * 2 + 1] * ATT_SCALE_LOG2E;
                }
                // chunk max via fmax tree (no index tracking)
                float m01 = fmaxf(v[0], v[1]), m23 = fmaxf(v[2], v[3]);
                float m45 = fmaxf(v[4], v[5]), m67 = fmaxf(v[6], v[7]);
                float cmax = fmaxf(fmaxf(m01, m23), fmaxf(m45, m67));
                if (cmax > m_[si]) {
                    // recover index (rare after the first chunks)
                    int cj = bcol;
                    #pragma unroll
                    for (int q = 1; q < 8; q++)
                        if (v[q] == cmax) cj = bcol + (q >> 1) * 8 + (q & 1);
                    Z_[si] *= ex2(m_[si] - cmax);
                    m_[si] = cmax;
                    j_[si] = cj;
                }
                float e = 0.f;
                #pragma unroll
                for (int q = 0; q < 8; q++) e += ex2(v[q] - m_[si]);
                Z_[si] += e;
            }
        }
    }

    // quad (lane&3) reduce, then cross-warp (wn) reduce via smem
    #pragma unroll
    for (int si = 0; si < 4; si++) {
        float mm = m_[si], zz = Z_[si];
        int jj = j_[si];
        #pragma unroll
        for (int o = 1; o <= 2; o <<= 1) {
            float om = __shfl_xor_sync(0xffffffffu, mm, o);
            float oz = __shfl_xor_sync(0xffffffffu, zz, o);
            int   oj = __shfl_xor_sync(0xffffffffu, jj, o);
            if (om > mm) { zz = zz * ex2(mm - om) + oz; mm = om; jj = oj; }
            else         { zz = zz + oz * ex2(om - mm); }
        }
        if ((lane & 3) == 0) {
            int row = wm * 32 + (si >> 1) * 16 + (si & 1) * 8 + (lane >> 2);
            part_m[row][wn] = mm;
            part_z[row][wn] = zz;
            part_j[row][wn] = jj;
        }
    }
    __syncthreads();

    if (tid < 64) {
        float mm = part_m[tid][0], zz = part_z[tid][0];
        int jj = part_j[tid][0];
        #pragma unroll
        for (int t = 1; t < 4; t++) {
            float om = part_m[tid][t], oz = part_z[tid][t];
            int   oj = part_j[tid][t];
            if (om > mm) { zz = zz * ex2(mm - om) + oz; mm = om; jj = oj; }
            else         { zz = zz + oz * ex2(om - mm); }
        }
        const float amax = 1.0f / zz;
        const float sc = (amax > 0.5f) ? amax : 0.0f;
        rscale[tid] = sc;
        rjmax[tid]  = jj;
        if (sc != 0.0f) s_any = 1;
    }
    __syncthreads();

    if (tid == 0 && s_any) {
        atomicOr(&flags[(b * NSEQ + r0) >> 7], 1);
        atomicOr(&flags[NFLAGS - 1], 1);          // per-layer anyWinner
    }

    // gather: out_row = sc * (xn[j*] @ Wv + bv); zero otherwise
    const int r  = tid >> 2;
    const int d0 = (tid & 3) * 16;
    const float sc = rscale[r];
    const int jj = rjmax[r];
    __half* orow = out + (size_t)(b * NSEQ + r0 + r) * CDIM + h * HDIM;
    if (sc != 0.0f) {
        // on-demand V: rare path (requires a softmax prob > 0.5)
        const __half* xrow = xn + (size_t)(b * NSEQ + jj) * CDIM;
        #pragma unroll 1
        for (int d = d0; d < d0 + 16; d++) {
            const __half* wrow = wt + (size_t)(2 * CDIM + h * HDIM + d) * CDIM;
            float accv = 0.f;
            const __half2* xp = (const __half2*)xrow;
            const __half2* wp = (const __half2*)wrow;
            #pragma unroll 8
            for (int k2 = 0; k2 < CDIM / 2; k2++) {
                float2 xf = __half22float2(xp[k2]);
                float2 wf = __half22float2(wp[k2]);
                accv += xf.x * wf.x + xf.y * wf.y;
            }
            accv += qkv_b[2 * CDIM + h * HDIM + d];
            orow[d] = __float2half(accv * sc);
        }
    } else {
        uint4 z; z.x = 0u; z.y = 0u; z.z = 0u; z.w = 0u;
        *(uint4*)(orow + d0) = z;
        *(uint4*)(orow + d0 + 8) = z;
    }
}

// ---------------------------------------------------------------------------
extern "C" void kernel_launch(void* const* d_in, const int* in_sizes, int n_in,
                              void* d_out, int out_size) {
    (void)in_sizes; (void)n_in; (void)out_size;
    const float* x      = (const float*)d_in[0];
    const float* pos    = (const float*)d_in[1];
    const float* qkv_w  = (const float*)d_in[2];
    const float* qkv_b  = (const float*)d_in[3];
    const float* proj_w = (const float*)d_in[4];
    const float* proj_b = (const float*)d_in[5];
    const float* ln1_g  = (const float*)d_in[6];
    const float* ln1_b  = (const float*)d_in[7];
    const float* ln2_g  = (const float*)d_in[8];
    const float* ln2_b  = (const float*)d_in[9];
    const float* fc1_w  = (const float*)d_in[10];
    const float* fc1_b  = (const float*)d_in[11];
    const float* fc2_w  = (const float*)d_in[12];
    const float* fc2_b  = (const float*)d_in[13];
    float* out = (float*)d_out;

    __half *xn, *qk, *attn, *ff, *wq, *wp, *w1, *w2;
    int *flags, *pbz, *lneq;
    cudaGetSymbolAddress((void**)&xn,   g_xn);
    cudaGetSymbolAddress((void**)&qk,   g_qk);
    cudaGetSymbolAddress((void**)&attn, g_attn);
    cudaGetSymbolAddress((void**)&ff,   g_ff);
    cudaGetSymbolAddress((void**)&wq,   g_wq);
    cudaGetSymbolAddress((void**)&wp,   g_wp);
    cudaGetSymbolAddress((void**)&w1,   g_w1);
    cudaGetSymbolAddress((void**)&w2,   g_w2);
    cudaGetSymbolAddress((void**)&flags, g_flags);
    cudaGetSymbolAddress((void**)&pbz,  g_pbz);
    cudaGetSymbolAddress((void**)&lneq, g_lneq);

    cudaFuncSetAttribute(hgemm_kernel<1, __half>,
                         cudaFuncAttributeMaxDynamicSharedMemorySize, GEMM_SMEM_BYTES);
    cudaFuncSetAttribute(hgemm_kernel<2, float>,
                         cudaFuncAttributeMaxDynamicSharedMemorySize, GEMM_SMEM_BYTES);
    cudaFuncSetAttribute(hgemm_kernel<3, __half>,
                         cudaFuncAttributeMaxDynamicSharedMemorySize, GEMM_SMEM_BYTES);
    cudaFuncSetAttribute(attn_mma_kernel,
                         cudaFuncAttributeMaxDynamicSharedMemorySize, ATTN_SMEM_BYTES);

    // weight prep: fp16 convert + transpose [K,N] -> [N,K] (once per launch)
    prep_w_kernel<<<dim3(3 * CDIM / 64, CDIM / 64, LAYERS), 256>>>(qkv_w,  wq, CDIM, 3 * CDIM);
    prep_w_kernel<<<dim3(CDIM / 64,     CDIM / 64, LAYERS), 256>>>(proj_w, wp, CDIM, CDIM);
    prep_w_kernel<<<dim3(FFD / 64,      CDIM / 64, LAYERS), 256>>>(fc1_w,  w1, CDIM, FFD);
    prep_w_kernel<<<dim3(CDIM / 64,     FFD / 64,  LAYERS), 256>>>(fc2_w,  w2, FFD, CDIM);
    smallprep_kernel<<<LAYERS, 256>>>(proj_b, ln1_g, ln1_b, ln2_g, ln2_b, pbz, lneq);

    add_pos_kernel<<<(size_t)TOK * CDIM / 4 / 256, 256>>>(x, pos, out);

    for (int l = 0; l < LAYERS; l++) {
        const __half* wql = wq + (size_t)l * CDIM * 3 * CDIM;
        // --- attention block ---
        ln_kernel<<<TOK / 8, 256>>>(out, ln1_g + (size_t)l * CDIM,
                                    ln1_b + (size_t)l * CDIM, xn, flags,
                                    nullptr, nullptr);
        // Q,K only (Wt rows 0..2C): N = 2048
        hgemm_kernel<3, __half><<<dim3(2 * CDIM / 128, TOK / 128), 256, GEMM_SMEM_BYTES>>>(
            xn, wql, qkv_b + (size_t)l * 3 * CDIM,
            nullptr, qk, TOK, 2 * CDIM, CDIM, nullptr, nullptr);
        attn_mma_kernel<<<dim3(NSEQ / 64, BSZ * HEADS), 256, ATTN_SMEM_BYTES>>>(
            qk, xn, wql, qkv_b + (size_t)l * 3 * CDIM, attn, flags);
        hgemm_kernel<2, float><<<dim3(CDIM / 128, TOK / 128), 256, GEMM_SMEM_BYTES>>>(
            attn, wp + (size_t)l * CDIM * CDIM, proj_b + (size_t)l * CDIM,
            out, out, TOK, CDIM, CDIM, flags, pbz + l);
        // --- MLP block ---
        ln_kernel<<<TOK / 8, 256>>>(out, ln2_g + (size_t)l * CDIM,
                                    ln2_b + (size_t)l * CDIM, xn, nullptr,
                                    flags + NFLAGS - 1, lneq + l);
        hgemm_kernel<1, __half><<<dim3(FFD / 128, TOK / 128), 256, GEMM_SMEM_BYTES>>>(
            xn, w1 + (size_t)l * CDIM * FFD, fc1_b + (size_t)l * FFD,
            nullptr, ff, TOK, FFD, CDIM, nullptr, nullptr);
        hgemm_kernel<2, float><<<dim3(CDIM / 128, TOK / 128), 256, GEMM_SMEM_BYTES>>>(
            ff, w2 + (size_t)l * FFD * CDIM, fc2_b + (size_t)l * CDIM,
            out, out, TOK, CDIM, FFD, nullptr, nullptr);
    }
}